// round 7
// baseline (speedup 1.0000x reference)
#include <cuda_runtime.h>
#include <cuda_bf16.h>
#include <math.h>
#include <stdint.h>

// GAT forward, B=4 N=2048 F=128 H=8 D=64 C=32.
// Softmax trick: exp(lrelu(f1_i+f2_j))/exp(f1_i) = (f1_i+f2_j>0) ? exp(f2_j)
//   : exp(-0.8 f1_i)*exp(0.2 f2_j); exp(f1_i) cancels in softmax.
// R7: k3 software-pipelined — A(weights) double-buffered in smem, B tile
// prefetched in registers one tile ahead; weight ALU overlaps HMMA.

#define BB 4
#define NN 2048
#define FF 128
#define DD 64
#define HH 8
#define CC 32
#define HD (HH*DD)

__device__ __align__(16) float  g_Wh[BB*HH*NN*DD];   // [b,h,n,d] fp32 16MB
__device__ __align__(16) float2 g_F1R[BB*HH*NN];     // (f1, exp(-0.8 f1))
__device__ __align__(16) float4 g_F2C[BB*HH*NN];     // (f2, exp(f2), exp(0.2 f2), 0)
__device__ __align__(16) float  g_h[BB*NN*HD];       // [b,n,h*64+d] 16MB
__device__ __align__(16) float  g_Wh2[BB*NN*CC];     // [b,n,c]
__device__ __align__(16) float2 g_G1R[BB*NN];
__device__ __align__(16) float4 g_G2C[BB*NN];
__device__ unsigned g_adjbT[BB*64*NN];               // bitmask, TRANSPOSED [b][word][row]
__device__ __align__(16) __nv_bfloat16 g_WhT_hi[BB*HH*DD*NN];  // WhT bf16 hi [bh][d][j]
__device__ __align__(16) __nv_bfloat16 g_WhT_lo[BB*HH*DD*NN];  // WhT bf16 lo
__device__ __align__(16) __nv_bfloat16 g_Wh2T_hi[BB*CC*NN];    // Wh2T bf16 hi [b][c][j]
__device__ __align__(16) __nv_bfloat16 g_Wh2T_lo[BB*CC*NN];    // Wh2T bf16 lo

typedef unsigned long long u64;

__device__ __forceinline__ void fma2(u64& d, u64 a, u64 b) {
    asm("fma.rn.f32x2 %0, %1, %2, %0;" : "+l"(d) : "l"(a), "l"(b));
}
__device__ __forceinline__ u64 dup2(float x) {
    u64 r; asm("mov.b64 %0, {%1, %1};" : "=l"(r) : "f"(x)); return r;
}
__device__ __forceinline__ float2 unp(u64 v) {
    float2 r; asm("mov.b64 {%0, %1}, %2;" : "=f"(r.x), "=f"(r.y) : "l"(v)); return r;
}
__device__ __forceinline__ uint32_t smem_u32(const void* p) {
    uint32_t a;
    asm("{ .reg .u64 tmp; cvta.to.shared.u64 tmp, %1; cvt.u32.u64 %0, tmp; }"
        : "=r"(a) : "l"(p));
    return a;
}
__device__ __forceinline__ void ldsm_x4(uint32_t* r, uint32_t addr) {
    asm volatile("ldmatrix.sync.aligned.m8n8.x4.shared.b16 {%0,%1,%2,%3}, [%4];"
        : "=r"(r[0]), "=r"(r[1]), "=r"(r[2]), "=r"(r[3]) : "r"(addr));
}
__device__ __forceinline__ void ldsm_x2(uint32_t* r, uint32_t addr) {
    asm volatile("ldmatrix.sync.aligned.m8n8.x2.shared.b16 {%0,%1}, [%2];"
        : "=r"(r[0]), "=r"(r[1]) : "r"(addr));
}
__device__ __forceinline__ void mma16816(float* c, const uint32_t* a, const uint32_t* b) {
    asm volatile(
        "mma.sync.aligned.m16n8k16.row.col.f32.bf16.bf16.f32 "
        "{%0,%1,%2,%3}, {%4,%5,%6,%7}, {%8,%9}, {%0,%1,%2,%3};"
        : "+f"(c[0]), "+f"(c[1]), "+f"(c[2]), "+f"(c[3])
        : "r"(a[0]), "r"(a[1]), "r"(a[2]), "r"(a[3]), "r"(b[0]), "r"(b[1]));
}

// ---------------- K0: adjacency -> transposed bitmask ----------------
__global__ __launch_bounds__(256) void k0_mask(const int* __restrict__ adj) {
    int gw = (blockIdx.x * 256 + threadIdx.x) >> 5;  // 0..8191 = b*2048+row
    int lane = threadIdx.x & 31;
    int b = gw >> 11, row = gw & 2047;
    const int* ar = adj + (size_t)gw * NN;
    #pragma unroll 4
    for (int w = 0; w < 64; w++) {
        unsigned m = __ballot_sync(0xffffffffu, ar[w*32 + lane] > 0);
        if (lane == 0) g_adjbT[((b<<6) + w)*NN + row] = m;
    }
}

// ---------------- K1: Wh[b,h,n,d] = x[b,n,:] @ W[h,:,d] ----------------
__global__ __launch_bounds__(256) void k1_gemm_wh(const float* __restrict__ x,
                                                  const float* __restrict__ W) {
    __shared__ __align__(16) float Xs[64*33];
    __shared__ __align__(16) float Ws[32*128];
    int t = threadIdx.x;
    int tr = t >> 4, tc = t & 15;
    int gr0 = blockIdx.y * 64;
    int gc0 = blockIdx.x * 128;
    u64 acc[4][4];
    #pragma unroll
    for (int i=0;i<4;i++){ acc[i][0]=0; acc[i][1]=0; acc[i][2]=0; acc[i][3]=0; }

    for (int kt = 0; kt < 4; kt++) {
        int k0 = kt*32;
        for (int idx = t; idx < 2048; idx += 256) {
            int row = idx >> 5, kk = idx & 31;
            Xs[row*33 + kk] = x[(gr0+row)*FF + k0 + kk];
        }
        for (int idx = t; idx < 4096; idx += 256) {
            int kk = idx >> 7, c = idx & 127;
            int gc = gc0 + c;
            Ws[idx] = W[(gc>>6)*(FF*DD) + (k0+kk)*DD + (gc&63)];
        }
        __syncthreads();
        #pragma unroll
        for (int kk = 0; kk < 32; kk++) {
            u64 ad[4];
            #pragma unroll
            for (int i=0;i<4;i++) ad[i] = dup2(Xs[(tr*4+i)*33 + kk]);
            const ulonglong2* bp = reinterpret_cast<const ulonglong2*>(&Ws[kk*128 + tc*8]);
            ulonglong2 b01 = bp[0], b23 = bp[1];
            #pragma unroll
            for (int i=0;i<4;i++) {
                fma2(acc[i][0], ad[i], b01.x);
                fma2(acc[i][1], ad[i], b01.y);
                fma2(acc[i][2], ad[i], b23.x);
                fma2(acc[i][3], ad[i], b23.y);
            }
        }
        __syncthreads();
    }
    #pragma unroll
    for (int i=0;i<4;i++) {
        int gr = gr0 + tr*4 + i;
        int b = gr >> 11, n = gr & 2047;
        #pragma unroll
        for (int j=0;j<4;j++) {
            float2 v = unp(acc[i][j]);
            int gc = gc0 + tc*8 + j*2;
            int h = gc >> 6, d = gc & 63;
            float* o = &g_Wh[(((b<<3)|h)*NN + n)*DD + d];
            o[0] = v.x; o[1] = v.y;
        }
    }
}

// ---------------- K2: f1,f2 + exp precompute ----------------
__global__ __launch_bounds__(256) void k2_f(const float* __restrict__ a1,
                                            const float* __restrict__ a2) {
    int tid = blockIdx.x*256 + threadIdx.x;      // (b*8+h)*2048+n
    int h = (tid >> 11) & 7;
    const float4* wr = reinterpret_cast<const float4*>(&g_Wh[(size_t)tid*DD]);
    const float4* p1 = reinterpret_cast<const float4*>(&a1[h*DD]);
    const float4* p2 = reinterpret_cast<const float4*>(&a2[h*DD]);
    float f1=0.f, f2=0.f;
    #pragma unroll
    for (int i=0;i<16;i++) {
        float4 w = wr[i], v1 = p1[i], v2 = p2[i];
        f1 += w.x*v1.x + w.y*v1.y + w.z*v1.z + w.w*v1.w;
        f2 += w.x*v2.x + w.y*v2.y + w.z*v2.z + w.w*v2.w;
    }
    g_F1R[tid] = make_float2(f1, expf(-0.8f*f1));
    g_F2C[tid] = make_float4(f2, expf(f2), expf(0.2f*f2), 0.f);
}

// ---------------- K2T: Wh fp32 [bh][n][d] -> WhT bf16 hi/lo [bh][d][n] ----------------
__global__ __launch_bounds__(256) void k2t_transpose() {
    __shared__ float ts[64][129];
    int t = threadIdx.x;
    int nblk = blockIdx.x, bh = blockIdx.y;
    const float* src = g_Wh + ((size_t)bh*NN + nblk*128)*DD;
    #pragma unroll
    for (int q = 0; q < 8; q++) {
        int idx = t + q*256;                 // 0..2047 float4s = 128n x 16c4
        int n = idx >> 4, c4 = idx & 15;
        float4 v = *reinterpret_cast<const float4*>(src + n*DD + c4*4);
        ts[c4*4+0][n] = v.x; ts[c4*4+1][n] = v.y;
        ts[c4*4+2][n] = v.z; ts[c4*4+3][n] = v.w;
    }
    __syncthreads();
    #pragma unroll
    for (int q = 0; q < 4; q++) {
        int task = t + q*256;                // 0..1023 = 64d x 16 chunks(8n)
        int d = task >> 4, nc = task & 15;
        uint32_t hiw[4], low[4];
        #pragma unroll
        for (int p = 0; p < 4; p++) {
            float a = ts[d][nc*8 + 2*p], c = ts[d][nc*8 + 2*p + 1];
            __nv_bfloat162 hp = __floats2bfloat162_rn(a, c);
            float2 hf = __bfloat1622float2(hp);
            __nv_bfloat162 lp = __floats2bfloat162_rn(a - hf.x, c - hf.y);
            hiw[p] = *reinterpret_cast<uint32_t*>(&hp);
            low[p] = *reinterpret_cast<uint32_t*>(&lp);
        }
        size_t off = ((size_t)bh*DD + d)*NN + nblk*128 + nc*8;
        *reinterpret_cast<uint4*>(g_WhT_hi + off) = *reinterpret_cast<uint4*>(hiw);
        *reinterpret_cast<uint4*>(g_WhT_lo + off) = *reinterpret_cast<uint4*>(low);
    }
}

// ---------------- K3: h = elu(softmax(mask(e)) @ Wh), HMMA pipelined ----------------
// smem layout (bytes):
//  A buf0: hi @0, lo @18432 | A buf1: hi @36864, lo @55296   (128x72 bf16 each)
//  B: hi @73728, lo @82944  (64x72 bf16 each)
//  zp @92160 (256 floats)   total 93184
#define K3_SMEM 93184

// weight phase for tile jt -> A[abuf]; returns partial z
__device__ __forceinline__ float k3_weights(char* smem, int abuf, int jt,
        int b, int bh, int i0, int i, int jh, float negf1, float rmul) {
    float zadd = 0.f;
    unsigned bw = g_adjbT[((b<<6) + jt*2 + jh)*NN + i0 + i];
    const float4* f2p = reinterpret_cast<const float4*>(&g_F2C[bh*NN + jt*64 + jh*32]);
    char* Ah = smem + abuf*36864;
    char* Al = Ah + 18432;
    #pragma unroll
    for (int oct = 0; oct < 4; oct++) {
        float w[8];
        #pragma unroll
        for (int e = 0; e < 8; e++) {
            float4 fc = __ldg(&f2p[oct*8 + e]);
            float w1 = (fc.x > negf1) ? fc.y : rmul*fc.z;
            w[e] = ((bw >> (oct*8 + e)) & 1u) ? w1 : 0.f;
            zadd += w[e];
        }
        uint32_t hiw[4], low[4];
        #pragma unroll
        for (int p = 0; p < 4; p++) {
            __nv_bfloat162 hp = __floats2bfloat162_rn(w[2*p], w[2*p+1]);
            float2 hf = __bfloat1622float2(hp);
            __nv_bfloat162 lp = __floats2bfloat162_rn(w[2*p]-hf.x, w[2*p+1]-hf.y);
            hiw[p] = *reinterpret_cast<uint32_t*>(&hp);
            low[p] = *reinterpret_cast<uint32_t*>(&lp);
        }
        uint32_t off = (uint32_t)i*144u + (uint32_t)(jh*64 + oct*16);
        *reinterpret_cast<uint4*>(Ah + off) = *reinterpret_cast<uint4*>(hiw);
        *reinterpret_cast<uint4*>(Al + off) = *reinterpret_cast<uint4*>(low);
    }
    return zadd;
}

__global__ __launch_bounds__(256) void k3_attn1_mma() {
    extern __shared__ __align__(16) char smem[];
    float* zp = reinterpret_cast<float*>(smem + 92160);
    uint32_t sb = smem_u32(smem);

    int t = threadIdx.x;
    int warp = t >> 5, lane = t & 31;
    int i0 = blockIdx.x * 128;
    int h = blockIdx.y, b = blockIdx.z;
    int bh = (b<<3) + h;

    int i = t & 127, jh = t >> 7;
    float2 f1r = g_F1R[bh*NN + i0 + i];
    float negf1 = -f1r.x, rmul = f1r.y;
    float zacc = 0.f;
    const __nv_bfloat16* bhsrc = g_WhT_hi + (size_t)bh*DD*NN;
    const __nv_bfloat16* blsrc = g_WhT_lo + (size_t)bh*DD*NN;

    float acc[8][4];
    #pragma unroll
    for (int n=0;n<8;n++){ acc[n][0]=0.f; acc[n][1]=0.f; acc[n][2]=0.f; acc[n][3]=0.f; }

    int m0 = warp * 16;
    uint32_t aRow = (uint32_t)(m0 + (lane & 15)) * 144u + ((lane & 16) ? 16u : 0u);
    uint32_t bRow = (uint32_t)(lane & 7) * 144u + (uint32_t)(lane & 8) * 2u;

    // B prefetch role: thread handles d = t>>2, chunk c = t&3 (16 j each)
    int dB = t >> 2, cB = t & 3;
    const __nv_bfloat16* pBh = bhsrc + (size_t)dB*NN + cB*16;
    const __nv_bfloat16* pBl = blsrc + (size_t)dB*NN + cB*16;
    uint32_t bOff = (uint32_t)dB*144u + (uint32_t)cB*32u;

    // ---- prologue: weights(0) -> A buf0; prefetch B(0) into regs ----
    zacc += k3_weights(smem, 0, 0, b, bh, i0, i, jh, negf1, rmul);
    uint4 bh0 = *reinterpret_cast<const uint4*>(pBh);
    uint4 bh1 = *reinterpret_cast<const uint4*>(pBh + 8);
    uint4 bl0 = *reinterpret_cast<const uint4*>(pBl);
    uint4 bl1 = *reinterpret_cast<const uint4*>(pBl + 8);

    for (int jt = 0; jt < 32; jt++) {
        int buf = jt & 1;
        if (jt) __syncthreads();       // MMA(jt-1) done reading B and A[buf]
        // store prefetched B(jt)
        *reinterpret_cast<uint4*>(smem + 73728 + bOff)      = bh0;
        *reinterpret_cast<uint4*>(smem + 73728 + bOff + 16) = bh1;
        *reinterpret_cast<uint4*>(smem + 82944 + bOff)      = bl0;
        *reinterpret_cast<uint4*>(smem + 82944 + bOff + 16) = bl1;
        // prefetch B(jt+1) (clamped; redundant on last iter)
        int jn = (jt < 31) ? jt + 1 : 31;
        bh0 = *reinterpret_cast<const uint4*>(pBh + jn*64);
        bh1 = *reinterpret_cast<const uint4*>(pBh + jn*64 + 8);
        bl0 = *reinterpret_cast<const uint4*>(pBl + jn*64);
        bl1 = *reinterpret_cast<const uint4*>(pBl + jn*64 + 8);
        // weights(jt+1) -> A[buf^1], overlaps MMA(jt) tensor work
        if (jt < 31)
            zacc += k3_weights(smem, buf^1, jt+1, b, bh, i0, i, jh, negf1, rmul);
        __syncthreads();               // B(jt) + A[buf] visible
        // ---- MMA(jt): A[buf] x B ----
        uint32_t aBaseH = sb + (uint32_t)buf*36864u;
        uint32_t aBaseL = aBaseH + 18432u;
        #pragma unroll
        for (int k = 0; k < 4; k++) {
            uint32_t kb = (uint32_t)k * 32u;
            uint32_t ah[4], al[4];
            ldsm_x4(ah, aBaseH + aRow + kb);
            ldsm_x4(al, aBaseL + aRow + kb);
            #pragma unroll
            for (int n = 0; n < 8; n++) {
                uint32_t bfh[2], bfl[2];
                uint32_t boff = (uint32_t)n * (8u*144u) + bRow + kb;
                ldsm_x2(bfh, sb + 73728u + boff);
                ldsm_x2(bfl, sb + 82944u + boff);
                mma16816(acc[n], ah, bfh);
                mma16816(acc[n], ah, bfl);
                mma16816(acc[n], al, bfh);
            }
        }
    }
    zp[jh*128 + i] = zacc;
    __syncthreads();
    // ---- epilogue: softmax normalize + ELU + store ----
    int r0 = m0 + (lane >> 2);
    int r1 = r0 + 8;
    float z0 = zp[r0] + zp[128 + r0];   if (z0 < 1e-30f) z0 = 1.f;
    float z1 = zp[r1] + zp[128 + r1];   if (z1 < 1e-30f) z1 = 1.f;
    float invz0 = 1.f / z0, invz1 = 1.f / z1;
    float* d0 = &g_h[(size_t)(b*NN + i0 + r0)*HD + h*DD + (lane & 3)*2];
    float* d1 = &g_h[(size_t)(b*NN + i0 + r1)*HD + h*DD + (lane & 3)*2];
    #pragma unroll
    for (int n = 0; n < 8; n++) {
        float v0 = acc[n][0] * invz0, v1 = acc[n][1] * invz0;
        float v2 = acc[n][2] * invz1, v3 = acc[n][3] * invz1;
        float2 o0 = make_float2(v0 > 0.f ? v0 : expm1f(v0),
                                 v1 > 0.f ? v1 : expm1f(v1));
        float2 o1 = make_float2(v2 > 0.f ? v2 : expm1f(v2),
                                 v3 > 0.f ? v3 : expm1f(v3));
        *reinterpret_cast<float2*>(d0 + n*8) = o0;
        *reinterpret_cast<float2*>(d1 + n*8) = o1;
    }
}

// ---------------- K4: Wh2 = h[8192,512] @ Wo[512,32] ----------------
__global__ __launch_bounds__(256) void k4_gemm_out(const float* __restrict__ Wo) {
    __shared__ __align__(16) float hs[32*132];
    __shared__ __align__(16) float Wos[128*32];
    int t = threadIdx.x;
    int r = t >> 3, cg = t & 7;
    int gr0 = blockIdx.x * 32;
    u64 acc[2] = {0,0};
    for (int kt = 0; kt < 4; kt++) {
        int k0 = kt*128;
        __syncthreads();
        #pragma unroll
        for (int q=0;q<4;q++) {
            int idx = t + q*256;
            int row = idx >> 5, kq = idx & 31;
            *reinterpret_cast<float4*>(&hs[row*132 + kq*4]) =
                *reinterpret_cast<const float4*>(&g_h[(size_t)(gr0+row)*HD + k0 + kq*4]);
            *reinterpret_cast<float4*>(&Wos[idx*4]) =
                *reinterpret_cast<const float4*>(&Wo[k0*32 + idx*4]);
        }
        __syncthreads();
        #pragma unroll 8
        for (int kk = 0; kk < 128; kk++) {
            u64 a = dup2(hs[r*132 + kk]);
            const ulonglong2* bp = reinterpret_cast<const ulonglong2*>(&Wos[kk*32 + cg*4]);
            ulonglong2 bv = bp[0];
            fma2(acc[0], a, bv.x);
            fma2(acc[1], a, bv.y);
        }
    }
    float2 v0 = unp(acc[0]), v1 = unp(acc[1]);
    float4 o = make_float4(v0.x, v0.y, v1.x, v1.y);
    *reinterpret_cast<float4*>(&g_Wh2[(gr0 + r)*CC + cg*4]) = o;
}

// ---------------- K4b: g1,g2 + exp precompute ----------------
__global__ __launch_bounds__(256) void k4b_g(const float* __restrict__ ao1,
                                             const float* __restrict__ ao2) {
    int tid = blockIdx.x*256 + threadIdx.x;  // 0..8191
    const float4* wr = reinterpret_cast<const float4*>(&g_Wh2[tid*CC]);
    const float4* p1 = reinterpret_cast<const float4*>(ao1);
    const float4* p2 = reinterpret_cast<const float4*>(ao2);
    float g1=0.f, g2=0.f;
    #pragma unroll
    for (int i=0;i<8;i++) {
        float4 w = wr[i], v1=p1[i], v2=p2[i];
        g1 += w.x*v1.x + w.y*v1.y + w.z*v1.z + w.w*v1.w;
        g2 += w.x*v2.x + w.y*v2.y + w.z*v2.z + w.w*v2.w;
    }
    g_G1R[tid] = make_float2(g1, expf(-0.8f*g1));
    g_G2C[tid] = make_float4(g2, expf(g2), expf(0.2f*g2), 0.f);
}

// ---------------- K4T: Wh2 fp32 [b][n][c] -> Wh2T bf16 hi/lo [b][c][n] ----------------
__global__ __launch_bounds__(256) void k4t_transpose() {
    __shared__ float ts[32][132];
    int t = threadIdx.x;
    int nblk = blockIdx.x, b = blockIdx.y;
    const float* src = g_Wh2 + ((size_t)(b*NN) + nblk*128)*CC;
    #pragma unroll
    for (int q = 0; q < 4; q++) {
        int idx = t + q*256;                 // 0..1023 float4s = 128n x 8c4
        int n = idx >> 3, c4 = idx & 7;
        float4 v = *reinterpret_cast<const float4*>(src + n*CC + c4*4);
        ts[c4*4+0][n] = v.x; ts[c4*4+1][n] = v.y;
        ts[c4*4+2][n] = v.z; ts[c4*4+3][n] = v.w;
    }
    __syncthreads();
    int c = t >> 3, nc = t & 7;              // 32c x 8 chunks(16n)
    uint32_t hiw[8], low[8];
    #pragma unroll
    for (int p = 0; p < 8; p++) {
        float a = ts[c][nc*16 + 2*p], d = ts[c][nc*16 + 2*p + 1];
        __nv_bfloat162 hp = __floats2bfloat162_rn(a, d);
        float2 hf = __bfloat1622float2(hp);
        __nv_bfloat162 lp = __floats2bfloat162_rn(a - hf.x, d - hf.y);
        hiw[p] = *reinterpret_cast<uint32_t*>(&hp);
        low[p] = *reinterpret_cast<uint32_t*>(&lp);
    }
    size_t off = ((size_t)(b*CC) + c)*NN + nblk*128 + nc*16;
    *reinterpret_cast<uint4*>(g_Wh2T_hi + off)     = *reinterpret_cast<uint4*>(&hiw[0]);
    *reinterpret_cast<uint4*>(g_Wh2T_hi + off + 8) = *reinterpret_cast<uint4*>(&hiw[4]);
    *reinterpret_cast<uint4*>(g_Wh2T_lo + off)     = *reinterpret_cast<uint4*>(&low[0]);
    *reinterpret_cast<uint4*>(g_Wh2T_lo + off + 8) = *reinterpret_cast<uint4*>(&low[4]);
}

// ---------------- K5: out = softmax(mask(e2)) @ Wh2, HMMA ----------------
__global__ __launch_bounds__(256) void k5_attn2_mma(float* __restrict__ out) {
    __shared__ __align__(16) char Ahp[64*144];   // w hi  [64][72 bf16]
    __shared__ __align__(16) char Alp[64*144];   // w lo
    __shared__ __align__(16) char Bhp[32*144];   // Wh2T hi [32][72 bf16]
    __shared__ __align__(16) char Blp[32*144];   // Wh2T lo
    __shared__ float zp[4][64];
    uint32_t sbA_h = smem_u32(Ahp), sbA_l = smem_u32(Alp);
    uint32_t sbB_h = smem_u32(Bhp), sbB_l = smem_u32(Blp);

    int t = threadIdx.x;
    int warp = t >> 5, lane = t & 31;
    int i0 = blockIdx.x * 64;
    int b = blockIdx.y;

    int i = t & 63, jq = t >> 6;             // weight-phase role
    float2 g1r = g_G1R[b*NN + i0 + i];
    float negg = -g1r.x, rmul = g1r.y;
    float zacc = 0.f;
    const __nv_bfloat16* bhsrc = g_Wh2T_hi + (size_t)(b*CC)*NN;
    const __nv_bfloat16* blsrc = g_Wh2T_lo + (size_t)(b*CC)*NN;

    int mt = warp >> 1, nh = warp & 1;
    float acc[2][4];
    acc[0][0]=0.f; acc[0][1]=0.f; acc[0][2]=0.f; acc[0][3]=0.f;
    acc[1][0]=0.f; acc[1][1]=0.f; acc[1][2]=0.f; acc[1][3]=0.f;

    uint32_t aRow = (uint32_t)(mt*16 + (lane & 15)) * 144u + ((lane & 16) ? 16u : 0u);
    uint32_t bRow = (uint32_t)(lane & 7) * 144u + (uint32_t)(lane & 8) * 2u;

    for (int jt = 0; jt < 32; jt++) {
        if (jt) __syncthreads();
        int j0 = jt * 64;
        unsigned bwf = g_adjbT[((b<<6) + jt*2 + (jq>>1))*NN + i0 + i];
        unsigned bw = (bwf >> ((jq & 1)*16)) & 0xFFFFu;
        const float4* g2p = &g_G2C[b*NN + j0 + jq*16];
        float w[16];
        #pragma unroll
        for (int e = 0; e < 16; e++) {
            float4 fc = __ldg(&g2p[e]);
            float w1 = (fc.x > negg) ? fc.y : rmul*fc.z;
            w[e] = ((bw >> e) & 1u) ? w1 : 0.f;
            zacc += w[e];
        }
        uint32_t hiw[8], low[8];
        #pragma unroll
        for (int p = 0; p < 8; p++) {
            __nv_bfloat162 hp = __floats2bfloat162_rn(w[2*p], w[2*p+1]);
            float2 hf = __bfloat1622float2(hp);
            __nv_bfloat162 lp = __floats2bfloat162_rn(w[2*p]-hf.x, w[2*p+1]-hf.y);
            hiw[p] = *reinterpret_cast<uint32_t*>(&hp);
            low[p] = *reinterpret_cast<uint32_t*>(&lp);
        }
        uint32_t off = (uint32_t)i*144u + (uint32_t)jq*32u;
        *reinterpret_cast<uint4*>(Ahp + off)      = *reinterpret_cast<uint4*>(&hiw[0]);
        *reinterpret_cast<uint4*>(Ahp + off + 16) = *reinterpret_cast<uint4*>(&hiw[4]);
        *reinterpret_cast<uint4*>(Alp + off)      = *reinterpret_cast<uint4*>(&low[0]);
        *reinterpret_cast<uint4*>(Alp + off + 16) = *reinterpret_cast<uint4*>(&low[4]);
        {
            int c = t >> 3, ch = t & 7;      // 32 c x 8 chunks of 8 j (16B)
            uint4 vh = *reinterpret_cast<const uint4*>(bhsrc + (size_t)c*NN + j0 + ch*8);
            uint4 vl = *reinterpret_cast<const uint4*>(blsrc + (size_t)c*NN + j0 + ch*8);
            uint32_t boff = (uint32_t)c*144u + (uint32_t)ch*16u;
            *reinterpret_cast<uint4*>(Bhp + boff) = vh;
            *reinterpret_cast<uint4*>(Blp + boff) = vl;
        }
        __syncthreads();
        #pragma unroll
        for (int k = 0; k < 4; k++) {
            uint32_t kb = (uint32_t)k * 32u;
            uint32_t ah[4], al[4];
            ldsm_x4(ah, sbA_h + aRow + kb);
            ldsm_x4(al, sbA_l + aRow + kb);
            #pragma unroll
            for (int n = 0; n < 2; n++) {
                uint32_t bfh[2], bfl[2];
                uint32_t boff = (uint32_t)(nh*2 + n) * (8u*144u) + bRow + kb;
                ldsm_x2(bfh, sbB_h + boff);
                ldsm_x2(bfl, sbB_l + boff);
                mma16816(acc[n], ah, bfh);
                mma16816(acc[n], ah, bfl);
                mma16816(acc[n], al, bfh);
            }
        }
    }
    zp[jq][i] = zacc;
    __syncthreads();
    int r0 = mt*16 + (lane >> 2);
    int r1 = r0 + 8;
    float z0 = zp[0][r0] + zp[1][r0] + zp[2][r0] + zp[3][r0];
    float z1 = zp[0][r1] + zp[1][r1] + zp[2][r1] + zp[3][r1];
    if (z0 < 1e-30f) z0 = 1.f;
    if (z1 < 1e-30f) z1 = 1.f;
    float invz0 = 1.f / z0, invz1 = 1.f / z1;
    #pragma unroll
    for (int n = 0; n < 2; n++) {
        int c0 = nh*16 + n*8 + (lane & 3)*2;
        float2 o0 = make_float2(acc[n][0]*invz0, acc[n][1]*invz0);
        float2 o1 = make_float2(acc[n][2]*invz1, acc[n][3]*invz1);
        *reinterpret_cast<float2*>(&out[(size_t)(b*NN + i0 + r0)*CC + c0]) = o0;
        *reinterpret_cast<float2*>(&out[(size_t)(b*NN + i0 + r1)*CC + c0]) = o1;
    }
}

extern "C" void kernel_launch(void* const* d_in, const int* in_sizes, int n_in,
                              void* d_out, int out_size) {
    const float* x   = (const float*)d_in[0];
    const int*   adj = (const int*)  d_in[1];
    const float* W   = (const float*)d_in[2];
    const float* a1  = (const float*)d_in[3];
    const float* a2  = (const float*)d_in[4];
    const float* Wo  = (const float*)d_in[5];
    const float* ao1 = (const float*)d_in[6];
    const float* ao2 = (const float*)d_in[7];
    float* out = (float*)d_out;

    cudaFuncSetAttribute(k3_attn1_mma,
                         cudaFuncAttributeMaxDynamicSharedMemorySize, K3_SMEM);

    k0_mask<<<1024, 256>>>(adj);                      // adj -> transposed bitmask
    k1_gemm_wh<<<dim3(4,128), 256>>>(x, W);           // Wh
    k2_f<<<256, 256>>>(a1, a2);                       // f1,f2 + exps
    k2t_transpose<<<dim3(16, 32), 256>>>();           // WhT bf16 hi/lo
    k3_attn1_mma<<<dim3(16, 8, 4), 256, K3_SMEM>>>(); // layer-1 attn (HMMA, pipelined)
    k4_gemm_out<<<256, 256>>>(Wo);                    // Wh2 = h @ Wo
    k4b_g<<<32, 256>>>(ao1, ao2);                     // g1,g2 + exps
    k4t_transpose<<<dim3(16, 4), 256>>>();            // Wh2T bf16 hi/lo
    k5_attn2_mma<<<dim3(32, 4), 256>>>(out);          // layer-2 attn (HMMA)
}

// round 8
// speedup vs baseline: 1.2603x; 1.2603x over previous
#include <cuda_runtime.h>
#include <cuda_bf16.h>
#include <math.h>
#include <stdint.h>

// GAT forward, B=4 N=2048 F=128 H=8 D=64 C=32.
// Softmax trick: exp(lrelu(f1_i+f2_j))/exp(f1_i) = (f1_i+f2_j>0) ? exp(f2_j)
//   : exp(-0.8 f1_i)*exp(0.2 f2_j); exp(f1_i) cancels in softmax.
// R8: k3 reverted to R6 (pipelining regressed); k1 + k4 converted to the same
// HMMA split-precision bf16 template (3 products); k2 fused into k2t; k3
// epilogue emits h as bf16 hi/lo for k4.

#define BB 4
#define NN 2048
#define FF 128
#define DD 64
#define HH 8
#define CC 32
#define HD (HH*DD)

__device__ __align__(16) float  g_Wh[BB*HH*NN*DD];   // [b,h,n,d] fp32 16MB
__device__ __align__(16) float2 g_F1R[BB*HH*NN];     // (f1, exp(-0.8 f1))
__device__ __align__(16) float4 g_F2C[BB*HH*NN];     // (f2, exp(f2), exp(0.2 f2), 0)
__device__ __align__(16) float  g_Wh2[BB*NN*CC];     // [b,n,c]
__device__ __align__(16) float2 g_G1R[BB*NN];
__device__ __align__(16) float4 g_G2C[BB*NN];
__device__ unsigned g_adjbT[BB*64*NN];               // bitmask, TRANSPOSED [b][word][row]
__device__ __align__(16) __nv_bfloat16 g_WhT_hi[BB*HH*DD*NN];  // WhT bf16 hi [bh][d][j]
__device__ __align__(16) __nv_bfloat16 g_WhT_lo[BB*HH*DD*NN];  // WhT bf16 lo
__device__ __align__(16) __nv_bfloat16 g_Wh2T_hi[BB*CC*NN];    // Wh2T bf16 hi [b][c][j]
__device__ __align__(16) __nv_bfloat16 g_Wh2T_lo[BB*CC*NN];    // Wh2T bf16 lo
__device__ __align__(16) __nv_bfloat16 g_x_hi[BB*NN*FF];       // x bf16 hi [bn][f]
__device__ __align__(16) __nv_bfloat16 g_x_lo[BB*NN*FF];
__device__ __align__(16) __nv_bfloat16 g_WT_hi[HH*DD*FF];      // WcatT [c][f] hi
__device__ __align__(16) __nv_bfloat16 g_WT_lo[HH*DD*FF];
__device__ __align__(16) __nv_bfloat16 g_h_hi[BB*NN*HD];       // h bf16 hi [bn][hd]
__device__ __align__(16) __nv_bfloat16 g_h_lo[BB*NN*HD];
__device__ __align__(16) __nv_bfloat16 g_WoT_hi[CC*HD];        // WoT [c][k] hi
__device__ __align__(16) __nv_bfloat16 g_WoT_lo[CC*HD];

__device__ __forceinline__ uint32_t smem_u32(const void* p) {
    uint32_t a;
    asm("{ .reg .u64 tmp; cvta.to.shared.u64 tmp, %1; cvt.u32.u64 %0, tmp; }"
        : "=r"(a) : "l"(p));
    return a;
}
__device__ __forceinline__ void ldsm_x4(uint32_t* r, uint32_t addr) {
    asm volatile("ldmatrix.sync.aligned.m8n8.x4.shared.b16 {%0,%1,%2,%3}, [%4];"
        : "=r"(r[0]), "=r"(r[1]), "=r"(r[2]), "=r"(r[3]) : "r"(addr));
}
__device__ __forceinline__ void ldsm_x2(uint32_t* r, uint32_t addr) {
    asm volatile("ldmatrix.sync.aligned.m8n8.x2.shared.b16 {%0,%1}, [%2];"
        : "=r"(r[0]), "=r"(r[1]) : "r"(addr));
}
__device__ __forceinline__ void mma16816(float* c, const uint32_t* a, const uint32_t* b) {
    asm volatile(
        "mma.sync.aligned.m16n8k16.row.col.f32.bf16.bf16.f32 "
        "{%0,%1,%2,%3}, {%4,%5,%6,%7}, {%8,%9}, {%0,%1,%2,%3};"
        : "+f"(c[0]), "+f"(c[1]), "+f"(c[2]), "+f"(c[3])
        : "r"(a[0]), "r"(a[1]), "r"(a[2]), "r"(a[3]), "r"(b[0]), "r"(b[1]));
}
// split a float pair into bf16 hi / lo packed words
__device__ __forceinline__ void split2(float a, float b, uint32_t& hi, uint32_t& lo) {
    __nv_bfloat162 hp = __floats2bfloat162_rn(a, b);
    float2 hf = __bfloat1622float2(hp);
    __nv_bfloat162 lp = __floats2bfloat162_rn(a - hf.x, b - hf.y);
    hi = *reinterpret_cast<uint32_t*>(&hp);
    lo = *reinterpret_cast<uint32_t*>(&lp);
}

// ---------------- KXS: x fp32 -> bf16 hi/lo ----------------
__global__ __launch_bounds__(256) void kxs_split(const float* __restrict__ x) {
    int idx = blockIdx.x*256 + threadIdx.x;      // 0..262143 (x float4s)
    float4 v = reinterpret_cast<const float4*>(x)[idx];
    uint32_t h0, l0, h1, l1;
    split2(v.x, v.y, h0, l0);
    split2(v.z, v.w, h1, l1);
    *reinterpret_cast<uint2*>(g_x_hi + (size_t)idx*4) = make_uint2(h0, h1);
    *reinterpret_cast<uint2*>(g_x_lo + (size_t)idx*4) = make_uint2(l0, l1);
}

// ---------------- KWS: W[h][f][d] -> WcatT[c][f] bf16 hi/lo ----------------
__global__ __launch_bounds__(256) void kws_split(const float* __restrict__ W) {
    int idx = blockIdx.x*256 + threadIdx.x;      // 0..16383 = c*32 + kg
    int c = idx >> 5, kg = idx & 31;             // 4 f's per thread
    int h = c >> 6, d = c & 63;
    float v[4];
    #pragma unroll
    for (int q = 0; q < 4; q++)
        v[q] = W[h*(FF*DD) + (kg*4 + q)*DD + d];
    uint32_t h0, l0, h1, l1;
    split2(v[0], v[1], h0, l0);
    split2(v[2], v[3], h1, l1);
    *reinterpret_cast<uint2*>(g_WT_hi + (size_t)c*FF + kg*4) = make_uint2(h0, h1);
    *reinterpret_cast<uint2*>(g_WT_lo + (size_t)c*FF + kg*4) = make_uint2(l0, l1);
}

// ---------------- K4W: Wo[k][c] -> WoT[c][k] bf16 hi/lo ----------------
__global__ __launch_bounds__(256) void k4w_split(const float* __restrict__ Wo) {
    int idx = blockIdx.x*256 + threadIdx.x;      // 0..4095 = c*128 + kg
    int c = idx >> 7, kg = idx & 127;            // 4 k's per thread
    float v[4];
    #pragma unroll
    for (int q = 0; q < 4; q++)
        v[q] = Wo[(kg*4 + q)*CC + c];
    uint32_t h0, l0, h1, l1;
    split2(v[0], v[1], h0, l0);
    split2(v[2], v[3], h1, l1);
    *reinterpret_cast<uint2*>(g_WoT_hi + (size_t)c*HD + kg*4) = make_uint2(h0, h1);
    *reinterpret_cast<uint2*>(g_WoT_lo + (size_t)c*HD + kg*4) = make_uint2(l0, l1);
}

// ---------------- K0: adjacency -> transposed bitmask ----------------
__global__ __launch_bounds__(256) void k0_mask(const int* __restrict__ adj) {
    int gw = (blockIdx.x * 256 + threadIdx.x) >> 5;  // 0..8191 = b*2048+row
    int lane = threadIdx.x & 31;
    int b = gw >> 11, row = gw & 2047;
    const int* ar = adj + (size_t)gw * NN;
    #pragma unroll 4
    for (int w = 0; w < 64; w++) {
        unsigned m = __ballot_sync(0xffffffffu, ar[w*32 + lane] > 0);
        if (lane == 0) g_adjbT[((b<<6) + w)*NN + row] = m;
    }
}

// ---------------- K1: Wh = x @ Wcat, HMMA split bf16 ----------------
// CTA 128m x 64n, 256 thr, K=128 in 2 tiles of 64. Same smem layout as k3:
// Ah @0, Al @18432 (128x72 bf16, 144B pitch); Bh @36864, Bl @46080 (64x72).
#define K1_SMEM 55296
__global__ __launch_bounds__(256) void k1_hmma() {
    extern __shared__ __align__(16) char smem[];
    uint32_t sb = smem_u32(smem);
    int t = threadIdx.x;
    int warp = t >> 5, lane = t & 31;
    int n0 = blockIdx.x * 64;       // output col block (8)
    int m0 = blockIdx.y * 128;      // output row block (64)

    float acc[8][4];
    #pragma unroll
    for (int n=0;n<8;n++){ acc[n][0]=0.f; acc[n][1]=0.f; acc[n][2]=0.f; acc[n][3]=0.f; }

    uint32_t aRow = (uint32_t)(warp*16 + (lane & 15)) * 144u + ((lane & 16) ? 16u : 0u);
    uint32_t bRow = (uint32_t)(lane & 7) * 144u + (uint32_t)(lane & 8) * 2u;

    int rA = t >> 1, hA = t & 1;    // A: 128 rows x 2 halves (32 k)
    int rB = t >> 2, cB = t & 3;    // B: 64 rows x 4 chunks (16 k)

    #pragma unroll
    for (int kt = 0; kt < 2; kt++) {
        if (kt) __syncthreads();
        int k0 = kt * 64;
        {   // A tile: x hi/lo
            const __nv_bfloat16* ph = g_x_hi + (size_t)(m0 + rA)*FF + k0 + hA*32;
            const __nv_bfloat16* pl = g_x_lo + (size_t)(m0 + rA)*FF + k0 + hA*32;
            uint32_t off = (uint32_t)rA*144u + (uint32_t)hA*64u;
            #pragma unroll
            for (int q = 0; q < 4; q++) {
                *reinterpret_cast<uint4*>(smem + off + q*16) =
                    *reinterpret_cast<const uint4*>(ph + q*8);
                *reinterpret_cast<uint4*>(smem + 18432 + off + q*16) =
                    *reinterpret_cast<const uint4*>(pl + q*8);
            }
        }
        {   // B tile: WcatT hi/lo
            const __nv_bfloat16* ph = g_WT_hi + (size_t)(n0 + rB)*FF + k0 + cB*16;
            const __nv_bfloat16* pl = g_WT_lo + (size_t)(n0 + rB)*FF + k0 + cB*16;
            uint32_t off = (uint32_t)rB*144u + (uint32_t)cB*32u;
            #pragma unroll
            for (int q = 0; q < 2; q++) {
                *reinterpret_cast<uint4*>(smem + 36864 + off + q*16) =
                    *reinterpret_cast<const uint4*>(ph + q*8);
                *reinterpret_cast<uint4*>(smem + 46080 + off + q*16) =
                    *reinterpret_cast<const uint4*>(pl + q*8);
            }
        }
        __syncthreads();
        #pragma unroll
        for (int k = 0; k < 4; k++) {
            uint32_t kb = (uint32_t)k * 32u;
            uint32_t ah[4], al[4];
            ldsm_x4(ah, sb + 0     + aRow + kb);
            ldsm_x4(al, sb + 18432 + aRow + kb);
            #pragma unroll
            for (int n = 0; n < 8; n++) {
                uint32_t bfh[2], bfl[2];
                uint32_t boff = (uint32_t)n * (8u*144u) + bRow + kb;
                ldsm_x2(bfh, sb + 36864u + boff);
                ldsm_x2(bfl, sb + 46080u + boff);
                mma16816(acc[n], ah, bfh);
                mma16816(acc[n], ah, bfl);
                mma16816(acc[n], al, bfh);
            }
        }
    }
    // epilogue: write fp32 Wh [bh][node][d]
    int r0 = warp*16 + (lane >> 2);
    int r1 = r0 + 8;
    int gr0 = m0 + r0, gr1 = m0 + r1;
    int b0 = gr0 >> 11, nd0 = gr0 & 2047;
    int b1 = gr1 >> 11, nd1 = gr1 & 2047;
    #pragma unroll
    for (int n = 0; n < 8; n++) {
        int gc = n0 + n*8 + (lane & 3)*2;
        int h = gc >> 6, d = gc & 63;
        *reinterpret_cast<float2*>(&g_Wh[(size_t)((b0*8+h)*NN + nd0)*DD + d]) =
            make_float2(acc[n][0], acc[n][1]);
        *reinterpret_cast<float2*>(&g_Wh[(size_t)((b1*8+h)*NN + nd1)*DD + d]) =
            make_float2(acc[n][2], acc[n][3]);
    }
}

// ---------------- K2T: transpose Wh -> WhT bf16 hi/lo, + f1/f2 fused ----------------
__global__ __launch_bounds__(256) void k2t_transpose(const float* __restrict__ a1,
                                                     const float* __restrict__ a2) {
    __shared__ float ts[64][129];
    __shared__ float a1s[64], a2s[64];
    int t = threadIdx.x;
    int nblk = blockIdx.x, bh = blockIdx.y;
    int h = bh & 7;
    if (t < 64) { a1s[t] = a1[h*DD + t]; a2s[t] = a2[h*DD + t]; }
    const float* src = g_Wh + ((size_t)bh*NN + nblk*128)*DD;
    #pragma unroll
    for (int q = 0; q < 8; q++) {
        int idx = t + q*256;                 // 0..2047 float4s = 128n x 16c4
        int n = idx >> 4, c4 = idx & 15;
        float4 v = *reinterpret_cast<const float4*>(src + n*DD + c4*4);
        ts[c4*4+0][n] = v.x; ts[c4*4+1][n] = v.y;
        ts[c4*4+2][n] = v.z; ts[c4*4+3][n] = v.w;
    }
    __syncthreads();
    // fused f1/f2 (was k2): threads 0..127, one n each
    if (t < 128) {
        float f1 = 0.f, f2 = 0.f;
        #pragma unroll
        for (int d = 0; d < 64; d++) {
            float wv = ts[d][t];
            f1 += wv * a1s[d];
            f2 += wv * a2s[d];
        }
        int tid = bh*NN + nblk*128 + t;
        g_F1R[tid] = make_float2(f1, expf(-0.8f*f1));
        g_F2C[tid] = make_float4(f2, expf(f2), expf(0.2f*f2), 0.f);
    }
    #pragma unroll
    for (int q = 0; q < 4; q++) {
        int task = t + q*256;                // 0..1023 = 64d x 16 chunks(8n)
        int d = task >> 4, nc = task & 15;
        uint32_t hiw[4], low[4];
        #pragma unroll
        for (int p = 0; p < 4; p++)
            split2(ts[d][nc*8 + 2*p], ts[d][nc*8 + 2*p + 1], hiw[p], low[p]);
        size_t off = ((size_t)bh*DD + d)*NN + nblk*128 + nc*8;
        *reinterpret_cast<uint4*>(g_WhT_hi + off) = *reinterpret_cast<uint4*>(hiw);
        *reinterpret_cast<uint4*>(g_WhT_lo + off) = *reinterpret_cast<uint4*>(low);
    }
}

// ---------------- K3: h = elu(softmax(mask(e)) @ Wh), HMMA (R6 structure) ----------------
// smem: Ah[128][72] @0, Al @18432, Bh[64][72] @36864, Bl @46080, zp @55296.
#define K3_SMEM 56320
__global__ __launch_bounds__(256) void k3_attn1_mma() {
    extern __shared__ __align__(16) char smem[];
    char* Ahp = smem;
    char* Alp = smem + 18432;
    char* Bhp = smem + 36864;
    char* Blp = smem + 46080;
    float* zp = reinterpret_cast<float*>(smem + 55296);
    uint32_t sb = smem_u32(smem);

    int t = threadIdx.x;
    int warp = t >> 5, lane = t & 31;
    int i0 = blockIdx.x * 128;
    int h = blockIdx.y, b = blockIdx.z;
    int bh = (b<<3) + h;

    int i = t & 127, jh = t >> 7;
    float2 f1r = g_F1R[bh*NN + i0 + i];
    float negf1 = -f1r.x, rmul = f1r.y;
    float zacc = 0.f;
    const __nv_bfloat16* bhsrc = g_WhT_hi + (size_t)bh*DD*NN;
    const __nv_bfloat16* blsrc = g_WhT_lo + (size_t)bh*DD*NN;

    float acc[8][4];
    #pragma unroll
    for (int n=0;n<8;n++){ acc[n][0]=0.f; acc[n][1]=0.f; acc[n][2]=0.f; acc[n][3]=0.f; }

    int m0 = warp * 16;
    uint32_t aRow = (uint32_t)(m0 + (lane & 15)) * 144u + ((lane & 16) ? 16u : 0u);
    uint32_t bRow = (uint32_t)(lane & 7) * 144u + (uint32_t)(lane & 8) * 2u;

    for (int jt = 0; jt < 32; jt++) {
        if (jt) __syncthreads();
        int j0 = jt * 64;
        unsigned bw = g_adjbT[((b<<6) + jt*2 + jh)*NN + i0 + i];
        const float4* f2p = &g_F2C[bh*NN + j0 + jh*32];
        #pragma unroll
        for (int oct = 0; oct < 4; oct++) {
            float w[8];
            #pragma unroll
            for (int e = 0; e < 8; e++) {
                float4 fc = __ldg(&f2p[oct*8 + e]);
                float w1 = (fc.x > negf1) ? fc.y : rmul*fc.z;
                w[e] = ((bw >> (oct*8 + e)) & 1u) ? w1 : 0.f;
                zacc += w[e];
            }
            uint32_t hiw[4], low[4];
            #pragma unroll
            for (int p = 0; p < 4; p++)
                split2(w[2*p], w[2*p+1], hiw[p], low[p]);
            uint32_t off = (uint32_t)i*144u + (uint32_t)(jh*64 + oct*16);
            *reinterpret_cast<uint4*>(Ahp + off) = *reinterpret_cast<uint4*>(hiw);
            *reinterpret_cast<uint4*>(Alp + off) = *reinterpret_cast<uint4*>(low);
        }
        {
            int d = t >> 2, c = t & 3;
            const uint4* sh = reinterpret_cast<const uint4*>(bhsrc + (size_t)d*NN + j0 + c*16);
            const uint4* sl = reinterpret_cast<const uint4*>(blsrc + (size_t)d*NN + j0 + c*16);
            uint4 vh0 = sh[0], vh1 = sh[1];
            uint4 vl0 = sl[0], vl1 = sl[1];
            uint32_t off = (uint32_t)d*144u + (uint32_t)c*32u;
            *reinterpret_cast<uint4*>(Bhp + off)      = vh0;
            *reinterpret_cast<uint4*>(Bhp + off + 16) = vh1;
            *reinterpret_cast<uint4*>(Blp + off)      = vl0;
            *reinterpret_cast<uint4*>(Blp + off + 16) = vl1;
        }
        __syncthreads();
        #pragma unroll
        for (int k = 0; k < 4; k++) {
            uint32_t kb = (uint32_t)k * 32u;
            uint32_t ah[4], al[4];
            ldsm_x4(ah, sb + 0     + aRow + kb);
            ldsm_x4(al, sb + 18432 + aRow + kb);
            #pragma unroll
            for (int n = 0; n < 8; n++) {
                uint32_t bfh[2], bfl[2];
                uint32_t boff = (uint32_t)n * (8u*144u) + bRow + kb;
                ldsm_x2(bfh, sb + 36864u + boff);
                ldsm_x2(bfl, sb + 46080u + boff);
                mma16816(acc[n], ah, bfh);
                mma16816(acc[n], ah, bfl);
                mma16816(acc[n], al, bfh);
            }
        }
    }
    zp[jh*128 + i] = zacc;
    __syncthreads();
    // epilogue: normalize + ELU, write h as bf16 hi/lo
    int r0 = m0 + (lane >> 2);
    int r1 = r0 + 8;
    float z0 = zp[r0] + zp[128 + r0];   if (z0 < 1e-30f) z0 = 1.f;
    float z1 = zp[r1] + zp[128 + r1];   if (z1 < 1e-30f) z1 = 1.f;
    float invz0 = 1.f / z0, invz1 = 1.f / z1;
    size_t base0 = (size_t)(b*NN + i0 + r0)*HD + h*DD + (lane & 3)*2;
    size_t base1 = (size_t)(b*NN + i0 + r1)*HD + h*DD + (lane & 3)*2;
    #pragma unroll
    for (int n = 0; n < 8; n++) {
        float v0 = acc[n][0] * invz0, v1 = acc[n][1] * invz0;
        float v2 = acc[n][2] * invz1, v3 = acc[n][3] * invz1;
        v0 = v0 > 0.f ? v0 : expm1f(v0);
        v1 = v1 > 0.f ? v1 : expm1f(v1);
        v2 = v2 > 0.f ? v2 : expm1f(v2);
        v3 = v3 > 0.f ? v3 : expm1f(v3);
        uint32_t h0, l0, h1, l1;
        split2(v0, v1, h0, l0);
        split2(v2, v3, h1, l1);
        *reinterpret_cast<uint32_t*>(g_h_hi + base0 + n*8) = h0;
        *reinterpret_cast<uint32_t*>(g_h_lo + base0 + n*8) = l0;
        *reinterpret_cast<uint32_t*>(g_h_hi + base1 + n*8) = h1;
        *reinterpret_cast<uint32_t*>(g_h_lo + base1 + n*8) = l1;
    }
}

// ---------------- K4: Wh2 = h @ Wo, HMMA split bf16 ----------------
// CTA 64m x 32n (k5 mma config), K=512 in 8 tiles of 64.
__global__ __launch_bounds__(256) void k4_hmma() {
    __shared__ __align__(16) char Ahp[64*144];
    __shared__ __align__(16) char Alp[64*144];
    __shared__ __align__(16) char Bhp[32*144];
    __shared__ __align__(16) char Blp[32*144];
    uint32_t sbA_h = smem_u32(Ahp), sbA_l = smem_u32(Alp);
    uint32_t sbB_h = smem_u32(Bhp), sbB_l = smem_u32(Blp);

    int t = threadIdx.x;
    int warp = t >> 5, lane = t & 31;
    int m0 = blockIdx.x * 64;
    int mt = warp >> 1, nh = warp & 1;

    float acc[2][4];
    acc[0][0]=0.f; acc[0][1]=0.f; acc[0][2]=0.f; acc[0][3]=0.f;
    acc[1][0]=0.f; acc[1][1]=0.f; acc[1][2]=0.f; acc[1][3]=0.f;

    uint32_t aRow = (uint32_t)(mt*16 + (lane & 15)) * 144u + ((lane & 16) ? 16u : 0u);
    uint32_t bRow = (uint32_t)(lane & 7) * 144u + (uint32_t)(lane & 8) * 2u;

    int rA = t >> 2, cA = t & 3;     // A: 64 rows x 4 chunks (16 k)
    int rB = t >> 3, cB = t & 7;     // B: 32 rows x 8 chunks (8 k)

    #pragma unroll
    for (int kt = 0; kt < 8; kt++) {
        if (kt) __syncthreads();
        int k0 = kt * 64;
        {
            const __nv_bfloat16* ph = g_h_hi + (size_t)(m0 + rA)*HD + k0 + cA*16;
            const __nv_bfloat16* pl = g_h_lo + (size_t)(m0 + rA)*HD + k0 + cA*16;
            uint32_t off = (uint32_t)rA*144u + (uint32_t)cA*32u;
            #pragma unroll
            for (int q = 0; q < 2; q++) {
                *reinterpret_cast<uint4*>(Ahp + off + q*16) =
                    *reinterpret_cast<const uint4*>(ph + q*8);
                *reinterpret_cast<uint4*>(Alp + off + q*16) =
                    *reinterpret_cast<const uint4*>(pl + q*8);
            }
        }
        {
            const __nv_bfloat16* ph = g_WoT_hi + (size_t)rB*HD + k0 + cB*8;
            const __nv_bfloat16* pl = g_WoT_lo + (size_t)rB*HD + k0 + cB*8;
            uint32_t off = (uint32_t)rB*144u + (uint32_t)cB*16u;
            *reinterpret_cast<uint4*>(Bhp + off) = *reinterpret_cast<const uint4*>(ph);
            *reinterpret_cast<uint4*>(Blp + off) = *reinterpret_cast<const uint4*>(pl);
        }
        __syncthreads();
        #pragma unroll
        for (int k = 0; k < 4; k++) {
            uint32_t kb = (uint32_t)k * 32u;
            uint32_t ah[4], al[4];
            ldsm_x4(ah, sbA_h + aRow + kb);
            ldsm_x4(al, sbA_l + aRow + kb);
            #pragma unroll
            for (int n = 0; n < 2; n++) {
                uint32_t bfh[2], bfl[2];
                uint32_t boff = (uint32_t)(nh*2 + n) * (8u*144u) + bRow + kb;
                ldsm_x2(bfh, sbB_h + boff);
                ldsm_x2(bfl, sbB_l + boff);
                mma16816(acc[n], ah, bfh);
                mma16816(acc[n], ah, bfl);
                mma16816(acc[n], al, bfh);
            }
        }
    }
    int r0 = mt*16 + (lane >> 2);
    int r1 = r0 + 8;
    #pragma unroll
    for (int n = 0; n < 2; n++) {
        int c0 = nh*16 + n*8 + (lane & 3)*2;
        *reinterpret_cast<float2*>(&g_Wh2[(size_t)(m0 + r0)*CC + c0]) =
            make_float2(acc[n][0], acc[n][1]);
        *reinterpret_cast<float2*>(&g_Wh2[(size_t)(m0 + r1)*CC + c0]) =
            make_float2(acc[n][2], acc[n][3]);
    }
}

// ---------------- K4b: g1,g2 + exp precompute ----------------
__global__ __launch_bounds__(256) void k4b_g(const float* __restrict__ ao1,
                                             const float* __restrict__ ao2) {
    int tid = blockIdx.x*256 + threadIdx.x;  // 0..8191
    const float4* wr = reinterpret_cast<const float4*>(&g_Wh2[tid*CC]);
    const float4* p1 = reinterpret_cast<const float4*>(ao1);
    const float4* p2 = reinterpret_cast<const float4*>(ao2);
    float g1=0.f, g2=0.f;
    #pragma unroll
    for (int i=0;i<8;i++) {
        float4 w = wr[i], v1=p1[i], v2=p2[i];
        g1 += w.x*v1.x + w.y*v1.y + w.z*v1.z + w.w*v1.w;
        g2 += w.x*v2.x + w.y*v2.y + w.z*v2.z + w.w*v2.w;
    }
    g_G1R[tid] = make_float2(g1, expf(-0.8f*g1));
    g_G2C[tid] = make_float4(g2, expf(g2), expf(0.2f*g2), 0.f);
}

// ---------------- K4T: Wh2 fp32 [b][n][c] -> Wh2T bf16 hi/lo [b][c][n] ----------------
__global__ __launch_bounds__(256) void k4t_transpose() {
    __shared__ float ts[32][132];
    int t = threadIdx.x;
    int nblk = blockIdx.x, b = blockIdx.y;
    const float* src = g_Wh2 + ((size_t)(b*NN) + nblk*128)*CC;
    #pragma unroll
    for (int q = 0; q < 4; q++) {
        int idx = t + q*256;                 // 0..1023 float4s = 128n x 8c4
        int n = idx >> 3, c4 = idx & 7;
        float4 v = *reinterpret_cast<const float4*>(src + n*CC + c4*4);
        ts[c4*4+0][n] = v.x; ts[c4*4+1][n] = v.y;
        ts[c4*4+2][n] = v.z; ts[c4*4+3][n] = v.w;
    }
    __syncthreads();
    int c = t >> 3, nc = t & 7;              // 32c x 8 chunks(16n)
    uint32_t hiw[8], low[8];
    #pragma unroll
    for (int p = 0; p < 8; p++)
        split2(ts[c][nc*16 + 2*p], ts[c][nc*16 + 2*p + 1], hiw[p], low[p]);
    size_t off = ((size_t)(b*CC) + c)*NN + nblk*128 + nc*16;
    *reinterpret_cast<uint4*>(g_Wh2T_hi + off)     = *reinterpret_cast<uint4*>(&hiw[0]);
    *reinterpret_cast<uint4*>(g_Wh2T_hi + off + 8) = *reinterpret_cast<uint4*>(&hiw[4]);
    *reinterpret_cast<uint4*>(g_Wh2T_lo + off)     = *reinterpret_cast<uint4*>(&low[0]);
    *reinterpret_cast<uint4*>(g_Wh2T_lo + off + 8) = *reinterpret_cast<uint4*>(&low[4]);
}

// ---------------- K5: out = softmax(mask(e2)) @ Wh2, HMMA ----------------
__global__ __launch_bounds__(256) void k5_attn2_mma(float* __restrict__ out) {
    __shared__ __align__(16) char Ahp[64*144];
    __shared__ __align__(16) char Alp[64*144];
    __shared__ __align__(16) char Bhp[32*144];
    __shared__ __align__(16) char Blp[32*144];
    __shared__ float zp[4][64];
    uint32_t sbA_h = smem_u32(Ahp), sbA_l = smem_u32(Alp);
    uint32_t sbB_h = smem_u32(Bhp), sbB_l = smem_u32(Blp);

    int t = threadIdx.x;
    int warp = t >> 5, lane = t & 31;
    int i0 = blockIdx.x * 64;
    int b = blockIdx.y;

    int i = t & 63, jq = t >> 6;
    float2 g1r = g_G1R[b*NN + i0 + i];
    float negg = -g1r.x, rmul = g1r.y;
    float zacc = 0.f;
    const __nv_bfloat16* bhsrc = g_Wh2T_hi + (size_t)(b*CC)*NN;
    const __nv_bfloat16* blsrc = g_Wh2T_lo + (size_t)(b*CC)*NN;

    int mt = warp >> 1, nh = warp & 1;
    float acc[2][4];
    acc[0][0]=0.f; acc[0][1]=0.f; acc[0][2]=0.f; acc[0][3]=0.f;
    acc[1][0]=0.f; acc[1][1]=0.f; acc[1][2]=0.f; acc[1][3]=0.f;

    uint32_t aRow = (uint32_t)(mt*16 + (lane & 15)) * 144u + ((lane & 16) ? 16u : 0u);
    uint32_t bRow = (uint32_t)(lane & 7) * 144u + (uint32_t)(lane & 8) * 2u;

    for (int jt = 0; jt < 32; jt++) {
        if (jt) __syncthreads();
        int j0 = jt * 64;
        unsigned bwf = g_adjbT[((b<<6) + jt*2 + (jq>>1))*NN + i0 + i];
        unsigned bw = (bwf >> ((jq & 1)*16)) & 0xFFFFu;
        const float4* g2p = &g_G2C[b*NN + j0 + jq*16];
        float w[16];
        #pragma unroll
        for (int e = 0; e < 16; e++) {
            float4 fc = __ldg(&g2p[e]);
            float w1 = (fc.x > negg) ? fc.y : rmul*fc.z;
            w[e] = ((bw >> e) & 1u) ? w1 : 0.f;
            zacc += w[e];
        }
        uint32_t hiw[8], low[8];
        #pragma unroll
        for (int p = 0; p < 8; p++)
            split2(w[2*p], w[2*p+1], hiw[p], low[p]);
        uint32_t off = (uint32_t)i*144u + (uint32_t)jq*32u;
        *reinterpret_cast<uint4*>(Ahp + off)      = *reinterpret_cast<uint4*>(&hiw[0]);
        *reinterpret_cast<uint4*>(Ahp + off + 16) = *reinterpret_cast<uint4*>(&hiw[4]);
        *reinterpret_cast<uint4*>(Alp + off)      = *reinterpret_cast<uint4*>(&low[0]);
        *reinterpret_cast<uint4*>(Alp + off + 16) = *reinterpret_cast<uint4*>(&low[4]);
        {
            int c = t >> 3, ch = t & 7;
            uint4 vh = *reinterpret_cast<const uint4*>(bhsrc + (size_t)c*NN + j0 + ch*8);
            uint4 vl = *reinterpret_cast<const uint4*>(blsrc + (size_t)c*NN + j0 + ch*8);
            uint32_t boff = (uint32_t)c*144u + (uint32_t)ch*16u;
            *reinterpret_cast<uint4*>(Bhp + boff) = vh;
            *reinterpret_cast<uint4*>(Blp + boff) = vl;
        }
        __syncthreads();
        #pragma unroll
        for (int k = 0; k < 4; k++) {
            uint32_t kb = (uint32_t)k * 32u;
            uint32_t ah[4], al[4];
            ldsm_x4(ah, sbA_h + aRow + kb);
            ldsm_x4(al, sbA_l + aRow + kb);
            #pragma unroll
            for (int n = 0; n < 2; n++) {
                uint32_t bfh[2], bfl[2];
                uint32_t boff = (uint32_t)(nh*2 + n) * (8u*144u) + bRow + kb;
                ldsm_x2(bfh, sbB_h + boff);
                ldsm_x2(bfl, sbB_l + boff);
                mma16816(acc[n], ah, bfh);
                mma16816(acc[n], ah, bfl);
                mma16816(acc[n], al, bfh);
            }
        }
    }
    zp[jq][i] = zacc;
    __syncthreads();
    int r0 = mt*16 + (lane >> 2);
    int r1 = r0 + 8;
    float z0 = zp[0][r0] + zp[1][r0] + zp[2][r0] + zp[3][r0];
    float z1 = zp[0][r1] + zp[1][r1] + zp[2][r1] + zp[3][r1];
    if (z0 < 1e-30f) z0 = 1.f;
    if (z1 < 1e-30f) z1 = 1.f;
    float invz0 = 1.f / z0, invz1 = 1.f / z1;
    #pragma unroll
    for (int n = 0; n < 2; n++) {
        int c0 = nh*16 + n*8 + (lane & 3)*2;
        float2 o0 = make_float2(acc[n][0]*invz0, acc[n][1]*invz0);
        float2 o1 = make_float2(acc[n][2]*invz1, acc[n][3]*invz1);
        *reinterpret_cast<float2*>(&out[(size_t)(b*NN + i0 + r0)*CC + c0]) = o0;
        *reinterpret_cast<float2*>(&out[(size_t)(b*NN + i0 + r1)*CC + c0]) = o1;
    }
}

extern "C" void kernel_launch(void* const* d_in, const int* in_sizes, int n_in,
                              void* d_out, int out_size) {
    const float* x   = (const float*)d_in[0];
    const int*   adj = (const int*)  d_in[1];
    const float* W   = (const float*)d_in[2];
    const float* a1  = (const float*)d_in[3];
    const float* a2  = (const float*)d_in[4];
    const float* Wo  = (const float*)d_in[5];
    const float* ao1 = (const float*)d_in[6];
    const float* ao2 = (const float*)d_in[7];
    float* out = (float*)d_out;

    cudaFuncSetAttribute(k3_attn1_mma,
                         cudaFuncAttributeMaxDynamicSharedMemorySize, K3_SMEM);
    cudaFuncSetAttribute(k1_hmma,
                         cudaFuncAttributeMaxDynamicSharedMemorySize, K1_SMEM);

    kxs_split<<<1024, 256>>>(x);                      // x -> bf16 hi/lo
    kws_split<<<64, 256>>>(W);                        // W -> WcatT hi/lo
    k4w_split<<<16, 256>>>(Wo);                       // Wo -> WoT hi/lo
    k0_mask<<<1024, 256>>>(adj);                      // adj -> transposed bitmask
    k1_hmma<<<dim3(8, 64), 256, K1_SMEM>>>();         // Wh (HMMA)
    k2t_transpose<<<dim3(16, 32), 256>>>(a1, a2);     // WhT hi/lo + f1/f2
    k3_attn1_mma<<<dim3(16, 8, 4), 256, K3_SMEM>>>(); // layer-1 attn (HMMA)
    k4_hmma<<<128, 256>>>();                          // Wh2 = h @ Wo (HMMA)
    k4b_g<<<32, 256>>>(ao1, ao2);                     // g1,g2 + exps
    k4t_transpose<<<dim3(16, 4), 256>>>();            // Wh2T hi/lo
    k5_attn2_mma<<<dim3(32, 4), 256>>>(out);          // layer-2 attn (HMMA)
}

// round 9
// speedup vs baseline: 1.3384x; 1.0619x over previous
#include <cuda_runtime.h>
#include <cuda_bf16.h>
#include <math.h>
#include <stdint.h>

// GAT forward, B=4 N=2048 F=128 H=8 D=64 C=32.
// Softmax trick: exp(lrelu(f1_i+f2_j))/exp(f1_i) = (f1_i+f2_j>0) ? exp(f2_j)
//   : exp(-0.8 f1_i)*exp(0.2 f2_j); exp(f1_i) cancels in softmax.
// R9: k3 B tiles via cp.async double-buffer (L2 latency off critical path);
// merged hi/lo B fragments via single ldmatrix.x4 in all HMMA kernels.

#define BB 4
#define NN 2048
#define FF 128
#define DD 64
#define HH 8
#define CC 32
#define HD (HH*DD)

__device__ __align__(16) float  g_Wh[BB*HH*NN*DD];   // [b,h,n,d] fp32 16MB
__device__ __align__(16) float2 g_F1R[BB*HH*NN];     // (f1, exp(-0.8 f1))
__device__ __align__(16) float4 g_F2C[BB*HH*NN];     // (f2, exp(f2), exp(0.2 f2), 0)
__device__ __align__(16) float  g_Wh2[BB*NN*CC];     // [b,n,c]
__device__ __align__(16) float2 g_G1R[BB*NN];
__device__ __align__(16) float4 g_G2C[BB*NN];
__device__ unsigned g_adjbT[BB*64*NN];               // bitmask, TRANSPOSED [b][word][row]
__device__ __align__(16) __nv_bfloat16 g_WhT_hi[BB*HH*DD*NN];  // WhT bf16 hi [bh][d][j]
__device__ __align__(16) __nv_bfloat16 g_WhT_lo[BB*HH*DD*NN];  // WhT bf16 lo
__device__ __align__(16) __nv_bfloat16 g_Wh2T_hi[BB*CC*NN];    // Wh2T bf16 hi [b][c][j]
__device__ __align__(16) __nv_bfloat16 g_Wh2T_lo[BB*CC*NN];    // Wh2T bf16 lo
__device__ __align__(16) __nv_bfloat16 g_x_hi[BB*NN*FF];       // x bf16 hi [bn][f]
__device__ __align__(16) __nv_bfloat16 g_x_lo[BB*NN*FF];
__device__ __align__(16) __nv_bfloat16 g_WT_hi[HH*DD*FF];      // WcatT [c][f] hi
__device__ __align__(16) __nv_bfloat16 g_WT_lo[HH*DD*FF];
__device__ __align__(16) __nv_bfloat16 g_h_hi[BB*NN*HD];       // h bf16 hi [bn][hd]
__device__ __align__(16) __nv_bfloat16 g_h_lo[BB*NN*HD];
__device__ __align__(16) __nv_bfloat16 g_WoT_hi[CC*HD];        // WoT [c][k] hi
__device__ __align__(16) __nv_bfloat16 g_WoT_lo[CC*HD];

__device__ __forceinline__ uint32_t smem_u32(const void* p) {
    uint32_t a;
    asm("{ .reg .u64 tmp; cvta.to.shared.u64 tmp, %1; cvt.u32.u64 %0, tmp; }"
        : "=r"(a) : "l"(p));
    return a;
}
__device__ __forceinline__ void ldsm_x4(uint32_t* r, uint32_t addr) {
    asm volatile("ldmatrix.sync.aligned.m8n8.x4.shared.b16 {%0,%1,%2,%3}, [%4];"
        : "=r"(r[0]), "=r"(r[1]), "=r"(r[2]), "=r"(r[3]) : "r"(addr));
}
__device__ __forceinline__ void mma16816(float* c, const uint32_t* a, const uint32_t* b) {
    asm volatile(
        "mma.sync.aligned.m16n8k16.row.col.f32.bf16.bf16.f32 "
        "{%0,%1,%2,%3}, {%4,%5,%6,%7}, {%8,%9}, {%0,%1,%2,%3};"
        : "+f"(c[0]), "+f"(c[1]), "+f"(c[2]), "+f"(c[3])
        : "r"(a[0]), "r"(a[1]), "r"(a[2]), "r"(a[3]), "r"(b[0]), "r"(b[1]));
}
#define CP_ASYNC16(dst, src) \
    asm volatile("cp.async.cg.shared.global [%0], [%1], 16;" :: "r"(dst), "l"(src))
#define CP_COMMIT() asm volatile("cp.async.commit_group;" ::: "memory")
#define CP_WAIT(n)  asm volatile("cp.async.wait_group %0;" :: "n"(n) : "memory")

// split a float pair into bf16 hi / lo packed words
__device__ __forceinline__ void split2(float a, float b, uint32_t& hi, uint32_t& lo) {
    __nv_bfloat162 hp = __floats2bfloat162_rn(a, b);
    float2 hf = __bfloat1622float2(hp);
    __nv_bfloat162 lp = __floats2bfloat162_rn(a - hf.x, b - hf.y);
    hi = *reinterpret_cast<uint32_t*>(&hp);
    lo = *reinterpret_cast<uint32_t*>(&lp);
}

// ---------------- KXS: x fp32 -> bf16 hi/lo ----------------
__global__ __launch_bounds__(256) void kxs_split(const float* __restrict__ x) {
    int idx = blockIdx.x*256 + threadIdx.x;      // 0..262143 (x float4s)
    float4 v = reinterpret_cast<const float4*>(x)[idx];
    uint32_t h0, l0, h1, l1;
    split2(v.x, v.y, h0, l0);
    split2(v.z, v.w, h1, l1);
    *reinterpret_cast<uint2*>(g_x_hi + (size_t)idx*4) = make_uint2(h0, h1);
    *reinterpret_cast<uint2*>(g_x_lo + (size_t)idx*4) = make_uint2(l0, l1);
}

// ---------------- KWS: W[h][f][d] -> WcatT[c][f] bf16 hi/lo ----------------
__global__ __launch_bounds__(256) void kws_split(const float* __restrict__ W) {
    int idx = blockIdx.x*256 + threadIdx.x;      // 0..16383 = c*32 + kg
    int c = idx >> 5, kg = idx & 31;
    int h = c >> 6, d = c & 63;
    float v[4];
    #pragma unroll
    for (int q = 0; q < 4; q++)
        v[q] = W[h*(FF*DD) + (kg*4 + q)*DD + d];
    uint32_t h0, l0, h1, l1;
    split2(v[0], v[1], h0, l0);
    split2(v[2], v[3], h1, l1);
    *reinterpret_cast<uint2*>(g_WT_hi + (size_t)c*FF + kg*4) = make_uint2(h0, h1);
    *reinterpret_cast<uint2*>(g_WT_lo + (size_t)c*FF + kg*4) = make_uint2(l0, l1);
}

// ---------------- K4W: Wo[k][c] -> WoT[c][k] bf16 hi/lo ----------------
__global__ __launch_bounds__(256) void k4w_split(const float* __restrict__ Wo) {
    int idx = blockIdx.x*256 + threadIdx.x;      // 0..4095 = c*128 + kg
    int c = idx >> 7, kg = idx & 127;
    float v[4];
    #pragma unroll
    for (int q = 0; q < 4; q++)
        v[q] = Wo[(kg*4 + q)*CC + c];
    uint32_t h0, l0, h1, l1;
    split2(v[0], v[1], h0, l0);
    split2(v[2], v[3], h1, l1);
    *reinterpret_cast<uint2*>(g_WoT_hi + (size_t)c*HD + kg*4) = make_uint2(h0, h1);
    *reinterpret_cast<uint2*>(g_WoT_lo + (size_t)c*HD + kg*4) = make_uint2(l0, l1);
}

// ---------------- K0: adjacency -> transposed bitmask ----------------
__global__ __launch_bounds__(256) void k0_mask(const int* __restrict__ adj) {
    int gw = (blockIdx.x * 256 + threadIdx.x) >> 5;  // 0..8191 = b*2048+row
    int lane = threadIdx.x & 31;
    int b = gw >> 11, row = gw & 2047;
    const int* ar = adj + (size_t)gw * NN;
    #pragma unroll 4
    for (int w = 0; w < 64; w++) {
        unsigned m = __ballot_sync(0xffffffffu, ar[w*32 + lane] > 0);
        if (lane == 0) g_adjbT[((b<<6) + w)*NN + row] = m;
    }
}

// ---------------- K1: Wh = x @ Wcat, HMMA split bf16 ----------------
// smem: Ah @0, Al @18432 (128x72 bf16, 144B pitch); Bh @36864, Bl @46080.
#define K1_SMEM 55296
__global__ __launch_bounds__(256) void k1_hmma() {
    extern __shared__ __align__(16) char smem[];
    uint32_t sb = smem_u32(smem);
    int t = threadIdx.x;
    int warp = t >> 5, lane = t & 31;
    int n0 = blockIdx.x * 64;
    int m0 = blockIdx.y * 128;

    float acc[8][4];
    #pragma unroll
    for (int n=0;n<8;n++){ acc[n][0]=0.f; acc[n][1]=0.f; acc[n][2]=0.f; acc[n][3]=0.f; }

    uint32_t aRow = (uint32_t)(warp*16 + (lane & 15)) * 144u + ((lane & 16) ? 16u : 0u);
    uint32_t bAddr = sb + 36864u + ((lane & 16) ? 9216u : 0u)
                   + (uint32_t)(lane & 7) * 144u + (uint32_t)(lane & 8) * 2u;

    int rA = t >> 1, hA = t & 1;
    int rB = t >> 2, cB = t & 3;

    #pragma unroll
    for (int kt = 0; kt < 2; kt++) {
        if (kt) __syncthreads();
        int k0 = kt * 64;
        {
            const __nv_bfloat16* ph = g_x_hi + (size_t)(m0 + rA)*FF + k0 + hA*32;
            const __nv_bfloat16* pl = g_x_lo + (size_t)(m0 + rA)*FF + k0 + hA*32;
            uint32_t off = (uint32_t)rA*144u + (uint32_t)hA*64u;
            #pragma unroll
            for (int q = 0; q < 4; q++) {
                *reinterpret_cast<uint4*>(smem + off + q*16) =
                    *reinterpret_cast<const uint4*>(ph + q*8);
                *reinterpret_cast<uint4*>(smem + 18432 + off + q*16) =
                    *reinterpret_cast<const uint4*>(pl + q*8);
            }
        }
        {
            const __nv_bfloat16* ph = g_WT_hi + (size_t)(n0 + rB)*FF + k0 + cB*16;
            const __nv_bfloat16* pl = g_WT_lo + (size_t)(n0 + rB)*FF + k0 + cB*16;
            uint32_t off = (uint32_t)rB*144u + (uint32_t)cB*32u;
            #pragma unroll
            for (int q = 0; q < 2; q++) {
                *reinterpret_cast<uint4*>(smem + 36864 + off + q*16) =
                    *reinterpret_cast<const uint4*>(ph + q*8);
                *reinterpret_cast<uint4*>(smem + 46080 + off + q*16) =
                    *reinterpret_cast<const uint4*>(pl + q*8);
            }
        }
        __syncthreads();
        #pragma unroll
        for (int k = 0; k < 4; k++) {
            uint32_t kb = (uint32_t)k * 32u;
            uint32_t ah[4], al[4];
            ldsm_x4(ah, sb + 0     + aRow + kb);
            ldsm_x4(al, sb + 18432 + aRow + kb);
            #pragma unroll
            for (int n = 0; n < 8; n++) {
                uint32_t bf[4];
                ldsm_x4(bf, bAddr + (uint32_t)n*(8u*144u) + kb);
                mma16816(acc[n], ah, bf);
                mma16816(acc[n], ah, bf + 2);
                mma16816(acc[n], al, bf);
            }
        }
    }
    int r0 = warp*16 + (lane >> 2);
    int r1 = r0 + 8;
    int gr0 = m0 + r0, gr1 = m0 + r1;
    int b0 = gr0 >> 11, nd0 = gr0 & 2047;
    int b1 = gr1 >> 11, nd1 = gr1 & 2047;
    #pragma unroll
    for (int n = 0; n < 8; n++) {
        int gc = n0 + n*8 + (lane & 3)*2;
        int h = gc >> 6, d = gc & 63;
        *reinterpret_cast<float2*>(&g_Wh[(size_t)((b0*8+h)*NN + nd0)*DD + d]) =
            make_float2(acc[n][0], acc[n][1]);
        *reinterpret_cast<float2*>(&g_Wh[(size_t)((b1*8+h)*NN + nd1)*DD + d]) =
            make_float2(acc[n][2], acc[n][3]);
    }
}

// ---------------- K2T: transpose Wh -> WhT bf16 hi/lo, + f1/f2 fused ----------------
__global__ __launch_bounds__(256) void k2t_transpose(const float* __restrict__ a1,
                                                     const float* __restrict__ a2) {
    __shared__ float ts[64][129];
    __shared__ float a1s[64], a2s[64];
    int t = threadIdx.x;
    int nblk = blockIdx.x, bh = blockIdx.y;
    int h = bh & 7;
    if (t < 64) { a1s[t] = a1[h*DD + t]; a2s[t] = a2[h*DD + t]; }
    const float* src = g_Wh + ((size_t)bh*NN + nblk*128)*DD;
    #pragma unroll
    for (int q = 0; q < 8; q++) {
        int idx = t + q*256;
        int n = idx >> 4, c4 = idx & 15;
        float4 v = *reinterpret_cast<const float4*>(src + n*DD + c4*4);
        ts[c4*4+0][n] = v.x; ts[c4*4+1][n] = v.y;
        ts[c4*4+2][n] = v.z; ts[c4*4+3][n] = v.w;
    }
    __syncthreads();
    if (t < 128) {
        float f1 = 0.f, f2 = 0.f;
        #pragma unroll
        for (int d = 0; d < 64; d++) {
            float wv = ts[d][t];
            f1 += wv * a1s[d];
            f2 += wv * a2s[d];
        }
        int tid = bh*NN + nblk*128 + t;
        g_F1R[tid] = make_float2(f1, expf(-0.8f*f1));
        g_F2C[tid] = make_float4(f2, expf(f2), expf(0.2f*f2), 0.f);
    }
    #pragma unroll
    for (int q = 0; q < 4; q++) {
        int task = t + q*256;
        int d = task >> 4, nc = task & 15;
        uint32_t hiw[4], low[4];
        #pragma unroll
        for (int p = 0; p < 4; p++)
            split2(ts[d][nc*8 + 2*p], ts[d][nc*8 + 2*p + 1], hiw[p], low[p]);
        size_t off = ((size_t)bh*DD + d)*NN + nblk*128 + nc*8;
        *reinterpret_cast<uint4*>(g_WhT_hi + off) = *reinterpret_cast<uint4*>(hiw);
        *reinterpret_cast<uint4*>(g_WhT_lo + off) = *reinterpret_cast<uint4*>(low);
    }
}

// ---------------- K3: h = elu(softmax(mask(e)) @ Wh), HMMA + cp.async ----------------
// smem: Ah @0, Al @18432; B buf0 hi @36864 lo @46080; buf1 hi @55296 lo @64512;
// zp @73728. Total 74752.
#define K3_SMEM 74752
__global__ __launch_bounds__(256) void k3_attn1_mma() {
    extern __shared__ __align__(16) char smem[];
    char* Ahp = smem;
    char* Alp = smem + 18432;
    float* zp = reinterpret_cast<float*>(smem + 73728);
    uint32_t sb = smem_u32(smem);

    int t = threadIdx.x;
    int warp = t >> 5, lane = t & 31;
    int i0 = blockIdx.x * 128;
    int h = blockIdx.y, b = blockIdx.z;
    int bh = (b<<3) + h;

    int i = t & 127, jh = t >> 7;
    float2 f1r = g_F1R[bh*NN + i0 + i];
    float negf1 = -f1r.x, rmul = f1r.y;
    float zacc = 0.f;
    const __nv_bfloat16* bhsrc = g_WhT_hi + (size_t)bh*DD*NN;
    const __nv_bfloat16* blsrc = g_WhT_lo + (size_t)bh*DD*NN;

    float acc[8][4];
    #pragma unroll
    for (int n=0;n<8;n++){ acc[n][0]=0.f; acc[n][1]=0.f; acc[n][2]=0.f; acc[n][3]=0.f; }

    int m0 = warp * 16;
    uint32_t aRow = (uint32_t)(m0 + (lane & 15)) * 144u + ((lane & 16) ? 16u : 0u);
    uint32_t bFrag = ((lane & 16) ? 9216u : 0u)
                   + (uint32_t)(lane & 7) * 144u + (uint32_t)(lane & 8) * 2u;

    // B copy role: d = t>>2 (0..63), chunk c = t&3 (16 j = 32B)
    int dB = t >> 2, cB = t & 3;
    const __nv_bfloat16* pBh = bhsrc + (size_t)dB*NN + cB*16;
    const __nv_bfloat16* pBl = blsrc + (size_t)dB*NN + cB*16;
    uint32_t bStOff = (uint32_t)dB*144u + (uint32_t)cB*32u;

    // prologue: async-load B(0) into buf0
    {
        uint32_t d0 = sb + 36864u + bStOff;
        CP_ASYNC16(d0,          pBh);
        CP_ASYNC16(d0 + 16,     pBh + 8);
        CP_ASYNC16(d0 + 9216u,      pBl);
        CP_ASYNC16(d0 + 9216u + 16, pBl + 8);
        CP_COMMIT();
    }

    for (int jt = 0; jt < 32; jt++) {
        int buf = jt & 1;
        if (jt) __syncthreads();       // MMA(jt-1) done: A and B[buf^1] free
        // async-prefetch B(jt+1) into buf^1
        if (jt < 31) {
            uint32_t dN = sb + 36864u + (uint32_t)(buf^1)*18432u + bStOff;
            const __nv_bfloat16* sh = pBh + (jt+1)*64;
            const __nv_bfloat16* sl = pBl + (jt+1)*64;
            CP_ASYNC16(dN,          sh);
            CP_ASYNC16(dN + 16,     sh + 8);
            CP_ASYNC16(dN + 9216u,      sl);
            CP_ASYNC16(dN + 9216u + 16, sl + 8);
            CP_COMMIT();
        }
        // weight phase -> A (overlaps outstanding cp.async)
        int j0 = jt * 64;
        unsigned bw = g_adjbT[((b<<6) + jt*2 + jh)*NN + i0 + i];
        const float4* f2p = &g_F2C[bh*NN + j0 + jh*32];
        #pragma unroll
        for (int oct = 0; oct < 4; oct++) {
            float w[8];
            #pragma unroll
            for (int e = 0; e < 8; e++) {
                float4 fc = __ldg(&f2p[oct*8 + e]);
                float w1 = (fc.x > negf1) ? fc.y : rmul*fc.z;
                w[e] = ((bw >> (oct*8 + e)) & 1u) ? w1 : 0.f;
                zacc += w[e];
            }
            uint32_t hiw[4], low[4];
            #pragma unroll
            for (int p = 0; p < 4; p++)
                split2(w[2*p], w[2*p+1], hiw[p], low[p]);
            uint32_t off = (uint32_t)i*144u + (uint32_t)(jh*64 + oct*16);
            *reinterpret_cast<uint4*>(Ahp + off) = *reinterpret_cast<uint4*>(hiw);
            *reinterpret_cast<uint4*>(Alp + off) = *reinterpret_cast<uint4*>(low);
        }
        if (jt < 31) { CP_WAIT(1); } else { CP_WAIT(0); }
        __syncthreads();               // A + B(jt) visible
        // ---- MMA(jt) on B[buf] ----
        uint32_t bBase = sb + 36864u + (uint32_t)buf*18432u + bFrag;
        #pragma unroll
        for (int k = 0; k < 4; k++) {
            uint32_t kb = (uint32_t)k * 32u;
            uint32_t ah[4], al[4];
            ldsm_x4(ah, sb + 0     + aRow + kb);
            ldsm_x4(al, sb + 18432 + aRow + kb);
            #pragma unroll
            for (int n = 0; n < 8; n++) {
                uint32_t bf[4];
                ldsm_x4(bf, bBase + (uint32_t)n*(8u*144u) + kb);
                mma16816(acc[n], ah, bf);
                mma16816(acc[n], ah, bf + 2);
                mma16816(acc[n], al, bf);
            }
        }
    }
    zp[jh*128 + i] = zacc;
    __syncthreads();
    // epilogue: normalize + ELU, write h as bf16 hi/lo
    int r0 = m0 + (lane >> 2);
    int r1 = r0 + 8;
    float z0 = zp[r0] + zp[128 + r0];   if (z0 < 1e-30f) z0 = 1.f;
    float z1 = zp[r1] + zp[128 + r1];   if (z1 < 1e-30f) z1 = 1.f;
    float invz0 = 1.f / z0, invz1 = 1.f / z1;
    size_t base0 = (size_t)(b*NN + i0 + r0)*HD + h*DD + (lane & 3)*2;
    size_t base1 = (size_t)(b*NN + i0 + r1)*HD + h*DD + (lane & 3)*2;
    #pragma unroll
    for (int n = 0; n < 8; n++) {
        float v0 = acc[n][0] * invz0, v1 = acc[n][1] * invz0;
        float v2 = acc[n][2] * invz1, v3 = acc[n][3] * invz1;
        v0 = v0 > 0.f ? v0 : expm1f(v0);
        v1 = v1 > 0.f ? v1 : expm1f(v1);
        v2 = v2 > 0.f ? v2 : expm1f(v2);
        v3 = v3 > 0.f ? v3 : expm1f(v3);
        uint32_t h0, l0, h1, l1;
        split2(v0, v1, h0, l0);
        split2(v2, v3, h1, l1);
        *reinterpret_cast<uint32_t*>(g_h_hi + base0 + n*8) = h0;
        *reinterpret_cast<uint32_t*>(g_h_lo + base0 + n*8) = l0;
        *reinterpret_cast<uint32_t*>(g_h_hi + base1 + n*8) = h1;
        *reinterpret_cast<uint32_t*>(g_h_lo + base1 + n*8) = l1;
    }
}

// ---------------- K4: Wh2 = h @ Wo, HMMA split bf16 ----------------
__global__ __launch_bounds__(256) void k4_hmma() {
    __shared__ __align__(16) char Ahp[64*144];
    __shared__ __align__(16) char Alp[64*144];
    __shared__ __align__(16) char Bs[2*32*144];   // hi @0, lo @4608
    uint32_t sbA_h = smem_u32(Ahp), sbA_l = smem_u32(Alp);
    uint32_t sbB = smem_u32(Bs);

    int t = threadIdx.x;
    int warp = t >> 5, lane = t & 31;
    int m0 = blockIdx.x * 64;
    int mt = warp >> 1, nh = warp & 1;

    float acc[2][4];
    acc[0][0]=0.f; acc[0][1]=0.f; acc[0][2]=0.f; acc[0][3]=0.f;
    acc[1][0]=0.f; acc[1][1]=0.f; acc[1][2]=0.f; acc[1][3]=0.f;

    uint32_t aRow = (uint32_t)(mt*16 + (lane & 15)) * 144u + ((lane & 16) ? 16u : 0u);
    uint32_t bAddr = sbB + ((lane & 16) ? 4608u : 0u)
                   + (uint32_t)(lane & 7) * 144u + (uint32_t)(lane & 8) * 2u;

    int rA = t >> 2, cA = t & 3;
    int rB = t >> 3, cB = t & 7;

    #pragma unroll
    for (int kt = 0; kt < 8; kt++) {
        if (kt) __syncthreads();
        int k0 = kt * 64;
        {
            const __nv_bfloat16* ph = g_h_hi + (size_t)(m0 + rA)*HD + k0 + cA*16;
            const __nv_bfloat16* pl = g_h_lo + (size_t)(m0 + rA)*HD + k0 + cA*16;
            uint32_t off = (uint32_t)rA*144u + (uint32_t)cA*32u;
            #pragma unroll
            for (int q = 0; q < 2; q++) {
                *reinterpret_cast<uint4*>(Ahp + off + q*16) =
                    *reinterpret_cast<const uint4*>(ph + q*8);
                *reinterpret_cast<uint4*>(Alp + off + q*16) =
                    *reinterpret_cast<const uint4*>(pl + q*8);
            }
        }
        {
            const __nv_bfloat16* ph = g_WoT_hi + (size_t)rB*HD + k0 + cB*8;
            const __nv_bfloat16* pl = g_WoT_lo + (size_t)rB*HD + k0 + cB*8;
            uint32_t off = (uint32_t)rB*144u + (uint32_t)cB*16u;
            *reinterpret_cast<uint4*>(Bs + off)         = *reinterpret_cast<const uint4*>(ph);
            *reinterpret_cast<uint4*>(Bs + 4608 + off)  = *reinterpret_cast<const uint4*>(pl);
        }
        __syncthreads();
        #pragma unroll
        for (int k = 0; k < 4; k++) {
            uint32_t kb = (uint32_t)k * 32u;
            uint32_t ah[4], al[4];
            ldsm_x4(ah, sbA_h + aRow + kb);
            ldsm_x4(al, sbA_l + aRow + kb);
            #pragma unroll
            for (int n = 0; n < 2; n++) {
                uint32_t bf[4];
                ldsm_x4(bf, bAddr + (uint32_t)(nh*2 + n)*(8u*144u) + kb);
                mma16816(acc[n], ah, bf);
                mma16816(acc[n], ah, bf + 2);
                mma16816(acc[n], al, bf);
            }
        }
    }
    int r0 = mt*16 + (lane >> 2);
    int r1 = r0 + 8;
    #pragma unroll
    for (int n = 0; n < 2; n++) {
        int c0 = nh*16 + n*8 + (lane & 3)*2;
        *reinterpret_cast<float2*>(&g_Wh2[(size_t)(m0 + r0)*CC + c0]) =
            make_float2(acc[n][0], acc[n][1]);
        *reinterpret_cast<float2*>(&g_Wh2[(size_t)(m0 + r1)*CC + c0]) =
            make_float2(acc[n][2], acc[n][3]);
    }
}

// ---------------- K4b: g1,g2 + exp precompute ----------------
__global__ __launch_bounds__(256) void k4b_g(const float* __restrict__ ao1,
                                             const float* __restrict__ ao2) {
    int tid = blockIdx.x*256 + threadIdx.x;  // 0..8191
    const float4* wr = reinterpret_cast<const float4*>(&g_Wh2[tid*CC]);
    const float4* p1 = reinterpret_cast<const float4*>(ao1);
    const float4* p2 = reinterpret_cast<const float4*>(ao2);
    float g1=0.f, g2=0.f;
    #pragma unroll
    for (int i=0;i<8;i++) {
        float4 w = wr[i], v1=p1[i], v2=p2[i];
        g1 += w.x*v1.x + w.y*v1.y + w.z*v1.z + w.w*v1.w;
        g2 += w.x*v2.x + w.y*v2.y + w.z*v2.z + w.w*v2.w;
    }
    g_G1R[tid] = make_float2(g1, expf(-0.8f*g1));
    g_G2C[tid] = make_float4(g2, expf(g2), expf(0.2f*g2), 0.f);
}

// ---------------- K4T: Wh2 fp32 [b][n][c] -> Wh2T bf16 hi/lo [b][c][n] ----------------
__global__ __launch_bounds__(256) void k4t_transpose() {
    __shared__ float ts[32][132];
    int t = threadIdx.x;
    int nblk = blockIdx.x, b = blockIdx.y;
    const float* src = g_Wh2 + ((size_t)(b*NN) + nblk*128)*CC;
    #pragma unroll
    for (int q = 0; q < 4; q++) {
        int idx = t + q*256;
        int n = idx >> 3, c4 = idx & 7;
        float4 v = *reinterpret_cast<const float4*>(src + n*CC + c4*4);
        ts[c4*4+0][n] = v.x; ts[c4*4+1][n] = v.y;
        ts[c4*4+2][n] = v.z; ts[c4*4+3][n] = v.w;
    }
    __syncthreads();
    int c = t >> 3, nc = t & 7;
    uint32_t hiw[8], low[8];
    #pragma unroll
    for (int p = 0; p < 8; p++)
        split2(ts[c][nc*16 + 2*p], ts[c][nc*16 + 2*p + 1], hiw[p], low[p]);
    size_t off = ((size_t)(b*CC) + c)*NN + nblk*128 + nc*16;
    *reinterpret_cast<uint4*>(g_Wh2T_hi + off)     = *reinterpret_cast<uint4*>(&hiw[0]);
    *reinterpret_cast<uint4*>(g_Wh2T_hi + off + 8) = *reinterpret_cast<uint4*>(&hiw[4]);
    *reinterpret_cast<uint4*>(g_Wh2T_lo + off)     = *reinterpret_cast<uint4*>(&low[0]);
    *reinterpret_cast<uint4*>(g_Wh2T_lo + off + 8) = *reinterpret_cast<uint4*>(&low[4]);
}

// ---------------- K5: out = softmax(mask(e2)) @ Wh2, HMMA ----------------
__global__ __launch_bounds__(256) void k5_attn2_mma(float* __restrict__ out) {
    __shared__ __align__(16) char Ahp[64*144];
    __shared__ __align__(16) char Alp[64*144];
    __shared__ __align__(16) char Bs[2*32*144];   // hi @0, lo @4608
    __shared__ float zp[4][64];
    uint32_t sbA_h = smem_u32(Ahp), sbA_l = smem_u32(Alp);
    uint32_t sbB = smem_u32(Bs);

    int t = threadIdx.x;
    int warp = t >> 5, lane = t & 31;
    int i0 = blockIdx.x * 64;
    int b = blockIdx.y;

    int i = t & 63, jq = t >> 6;
    float2 g1r = g_G1R[b*NN + i0 + i];
    float negg = -g1r.x, rmul = g1r.y;
    float zacc = 0.f;
    const __nv_bfloat16* bhsrc = g_Wh2T_hi + (size_t)(b*CC)*NN;
    const __nv_bfloat16* blsrc = g_Wh2T_lo + (size_t)(b*CC)*NN;

    int mt = warp >> 1, nh = warp & 1;
    float acc[2][4];
    acc[0][0]=0.f; acc[0][1]=0.f; acc[0][2]=0.f; acc[0][3]=0.f;
    acc[1][0]=0.f; acc[1][1]=0.f; acc[1][2]=0.f; acc[1][3]=0.f;

    uint32_t aRow = (uint32_t)(mt*16 + (lane & 15)) * 144u + ((lane & 16) ? 16u : 0u);
    uint32_t bAddr = sbB + ((lane & 16) ? 4608u : 0u)
                   + (uint32_t)(lane & 7) * 144u + (uint32_t)(lane & 8) * 2u;

    for (int jt = 0; jt < 32; jt++) {
        if (jt) __syncthreads();
        int j0 = jt * 64;
        unsigned bwf = g_adjbT[((b<<6) + jt*2 + (jq>>1))*NN + i0 + i];
        unsigned bw = (bwf >> ((jq & 1)*16)) & 0xFFFFu;
        const float4* g2p = &g_G2C[b*NN + j0 + jq*16];
        float w[16];
        #pragma unroll
        for (int e = 0; e < 16; e++) {
            float4 fc = __ldg(&g2p[e]);
            float w1 = (fc.x > negg) ? fc.y : rmul*fc.z;
            w[e] = ((bw >> e) & 1u) ? w1 : 0.f;
            zacc += w[e];
        }
        uint32_t hiw[8], low[8];
        #pragma unroll
        for (int p = 0; p < 8; p++)
            split2(w[2*p], w[2*p+1], hiw[p], low[p]);
        uint32_t off = (uint32_t)i*144u + (uint32_t)jq*32u;
        *reinterpret_cast<uint4*>(Ahp + off)      = *reinterpret_cast<uint4*>(&hiw[0]);
        *reinterpret_cast<uint4*>(Ahp + off + 16) = *reinterpret_cast<uint4*>(&hiw[4]);
        *reinterpret_cast<uint4*>(Alp + off)      = *reinterpret_cast<uint4*>(&low[0]);
        *reinterpret_cast<uint4*>(Alp + off + 16) = *reinterpret_cast<uint4*>(&low[4]);
        {
            int c = t >> 3, ch = t & 7;
            uint4 vh = *reinterpret_cast<const uint4*>(bhsrc + (size_t)c*NN + j0 + ch*8);
            uint4 vl = *reinterpret_cast<const uint4*>(blsrc + (size_t)c*NN + j0 + ch*8);
            uint32_t boff = (uint32_t)c*144u + (uint32_t)ch*16u;
            *reinterpret_cast<uint4*>(Bs + boff)        = vh;
            *reinterpret_cast<uint4*>(Bs + 4608 + boff) = vl;
        }
        __syncthreads();
        #pragma unroll
        for (int k = 0; k < 4; k++) {
            uint32_t kb = (uint32_t)k * 32u;
            uint32_t ah[4], al[4];
            ldsm_x4(ah, sbA_h + aRow + kb);
            ldsm_x4(al, sbA_l + aRow + kb);
            #pragma unroll
            for (int n = 0; n < 2; n++) {
                uint32_t bf[4];
                ldsm_x4(bf, bAddr + (uint32_t)(nh*2 + n)*(8u*144u) + kb);
                mma16816(acc[n], ah, bf);
                mma16816(acc[n], ah, bf + 2);
                mma16816(acc[n], al, bf);
            }
        }
    }
    zp[jq][i] = zacc;
    __syncthreads();
    int r0 = mt*16 + (lane >> 2);
    int r1 = r0 + 8;
    float z0 = zp[0][r0] + zp[1][r0] + zp[2][r0] + zp[3][r0];
    float z1 = zp[0][r1] + zp[1][r1] + zp[2][r1] + zp[3][r1];
    if (z0 < 1e-30f) z0 = 1.f;
    if (z1 < 1e-30f) z1 = 1.f;
    float invz0 = 1.f / z0, invz1 = 1.f / z1;
    #pragma unroll
    for (int n = 0; n < 2; n++) {
        int c0 = nh*16 + n*8 + (lane & 3)*2;
        float2 o0 = make_float2(acc[n][0]*invz0, acc[n][1]*invz0);
        float2 o1 = make_float2(acc[n][2]*invz1, acc[n][3]*invz1);
        *reinterpret_cast<float2*>(&out[(size_t)(b*NN + i0 + r0)*CC + c0]) = o0;
        *reinterpret_cast<float2*>(&out[(size_t)(b*NN + i0 + r1)*CC + c0]) = o1;
    }
}

extern "C" void kernel_launch(void* const* d_in, const int* in_sizes, int n_in,
                              void* d_out, int out_size) {
    const float* x   = (const float*)d_in[0];
    const int*   adj = (const int*)  d_in[1];
    const float* W   = (const float*)d_in[2];
    const float* a1  = (const float*)d_in[3];
    const float* a2  = (const float*)d_in[4];
    const float* Wo  = (const float*)d_in[5];
    const float* ao1 = (const float*)d_in[6];
    const float* ao2 = (const float*)d_in[7];
    float* out = (float*)d_out;

    cudaFuncSetAttribute(k3_attn1_mma,
                         cudaFuncAttributeMaxDynamicSharedMemorySize, K3_SMEM);
    cudaFuncSetAttribute(k1_hmma,
                         cudaFuncAttributeMaxDynamicSharedMemorySize, K1_SMEM);

    kxs_split<<<1024, 256>>>(x);                      // x -> bf16 hi/lo
    kws_split<<<64, 256>>>(W);                        // W -> WcatT hi/lo
    k4w_split<<<16, 256>>>(Wo);                       // Wo -> WoT hi/lo
    k0_mask<<<1024, 256>>>(adj);                      // adj -> transposed bitmask
    k1_hmma<<<dim3(8, 64), 256, K1_SMEM>>>();         // Wh (HMMA)
    k2t_transpose<<<dim3(16, 32), 256>>>(a1, a2);     // WhT hi/lo + f1/f2
    k3_attn1_mma<<<dim3(16, 8, 4), 256, K3_SMEM>>>(); // layer-1 attn (HMMA+cp.async)
    k4_hmma<<<128, 256>>>();                          // Wh2 = h @ Wo (HMMA)
    k4b_g<<<32, 256>>>(ao1, ao2);                     // g1,g2 + exps
    k4t_transpose<<<dim3(16, 4), 256>>>();            // Wh2T hi/lo
    k5_attn2_mma<<<dim3(32, 4), 256>>>(out);          // layer-2 attn (HMMA)
}

// round 10
// speedup vs baseline: 1.5635x; 1.1682x over previous
#include <cuda_runtime.h>
#include <cuda_bf16.h>
#include <math.h>
#include <stdint.h>

// GAT forward, B=4 N=2048 F=128 H=8 D=64 C=32.
// Softmax trick: exp(lrelu(f1_i+f2_j))/exp(f1_i) = (f1_i+f2_j>0) ? exp(f2_j)
//   : exp(-0.8 f1_i)*exp(0.2 f2_j); exp(f1_i) cancels in softmax.
// R10: k3/k5 weight-phase f2c/g2c broadcast LDGs replaced with smem staging
// (double-buffered, LDS.128 broadcast reads); k0 deeper unroll.

#define BB 4
#define NN 2048
#define FF 128
#define DD 64
#define HH 8
#define CC 32
#define HD (HH*DD)

__device__ __align__(16) float  g_Wh[BB*HH*NN*DD];   // [b,h,n,d] fp32 16MB
__device__ __align__(16) float2 g_F1R[BB*HH*NN];     // (f1, exp(-0.8 f1))
__device__ __align__(16) float4 g_F2C[BB*HH*NN];     // (f2, exp(f2), exp(0.2 f2), 0)
__device__ __align__(16) float  g_Wh2[BB*NN*CC];     // [b,n,c]
__device__ __align__(16) float2 g_G1R[BB*NN];
__device__ __align__(16) float4 g_G2C[BB*NN];
__device__ unsigned g_adjbT[BB*64*NN];               // bitmask, TRANSPOSED [b][word][row]
__device__ __align__(16) __nv_bfloat16 g_WhT_hi[BB*HH*DD*NN];  // WhT bf16 hi [bh][d][j]
__device__ __align__(16) __nv_bfloat16 g_WhT_lo[BB*HH*DD*NN];  // WhT bf16 lo
__device__ __align__(16) __nv_bfloat16 g_Wh2T_hi[BB*CC*NN];    // Wh2T bf16 hi [b][c][j]
__device__ __align__(16) __nv_bfloat16 g_Wh2T_lo[BB*CC*NN];    // Wh2T bf16 lo
__device__ __align__(16) __nv_bfloat16 g_x_hi[BB*NN*FF];       // x bf16 hi [bn][f]
__device__ __align__(16) __nv_bfloat16 g_x_lo[BB*NN*FF];
__device__ __align__(16) __nv_bfloat16 g_WT_hi[HH*DD*FF];      // WcatT [c][f] hi
__device__ __align__(16) __nv_bfloat16 g_WT_lo[HH*DD*FF];
__device__ __align__(16) __nv_bfloat16 g_h_hi[BB*NN*HD];       // h bf16 hi [bn][hd]
__device__ __align__(16) __nv_bfloat16 g_h_lo[BB*NN*HD];
__device__ __align__(16) __nv_bfloat16 g_WoT_hi[CC*HD];        // WoT [c][k] hi
__device__ __align__(16) __nv_bfloat16 g_WoT_lo[CC*HD];

__device__ __forceinline__ uint32_t smem_u32(const void* p) {
    uint32_t a;
    asm("{ .reg .u64 tmp; cvta.to.shared.u64 tmp, %1; cvt.u32.u64 %0, tmp; }"
        : "=r"(a) : "l"(p));
    return a;
}
__device__ __forceinline__ void ldsm_x4(uint32_t* r, uint32_t addr) {
    asm volatile("ldmatrix.sync.aligned.m8n8.x4.shared.b16 {%0,%1,%2,%3}, [%4];"
        : "=r"(r[0]), "=r"(r[1]), "=r"(r[2]), "=r"(r[3]) : "r"(addr));
}
__device__ __forceinline__ void mma16816(float* c, const uint32_t* a, const uint32_t* b) {
    asm volatile(
        "mma.sync.aligned.m16n8k16.row.col.f32.bf16.bf16.f32 "
        "{%0,%1,%2,%3}, {%4,%5,%6,%7}, {%8,%9}, {%0,%1,%2,%3};"
        : "+f"(c[0]), "+f"(c[1]), "+f"(c[2]), "+f"(c[3])
        : "r"(a[0]), "r"(a[1]), "r"(a[2]), "r"(a[3]), "r"(b[0]), "r"(b[1]));
}
#define CP_ASYNC16(dst, src) \
    asm volatile("cp.async.cg.shared.global [%0], [%1], 16;" :: "r"(dst), "l"(src))
#define CP_COMMIT() asm volatile("cp.async.commit_group;" ::: "memory")
#define CP_WAIT(n)  asm volatile("cp.async.wait_group %0;" :: "n"(n) : "memory")

// split a float pair into bf16 hi / lo packed words
__device__ __forceinline__ void split2(float a, float b, uint32_t& hi, uint32_t& lo) {
    __nv_bfloat162 hp = __floats2bfloat162_rn(a, b);
    float2 hf = __bfloat1622float2(hp);
    __nv_bfloat162 lp = __floats2bfloat162_rn(a - hf.x, b - hf.y);
    hi = *reinterpret_cast<uint32_t*>(&hp);
    lo = *reinterpret_cast<uint32_t*>(&lp);
}

// ---------------- KXS: x fp32 -> bf16 hi/lo ----------------
__global__ __launch_bounds__(256) void kxs_split(const float* __restrict__ x) {
    int idx = blockIdx.x*256 + threadIdx.x;      // 0..262143 (x float4s)
    float4 v = reinterpret_cast<const float4*>(x)[idx];
    uint32_t h0, l0, h1, l1;
    split2(v.x, v.y, h0, l0);
    split2(v.z, v.w, h1, l1);
    *reinterpret_cast<uint2*>(g_x_hi + (size_t)idx*4) = make_uint2(h0, h1);
    *reinterpret_cast<uint2*>(g_x_lo + (size_t)idx*4) = make_uint2(l0, l1);
}

// ---------------- KWS: W[h][f][d] -> WcatT[c][f] bf16 hi/lo ----------------
__global__ __launch_bounds__(256) void kws_split(const float* __restrict__ W) {
    int idx = blockIdx.x*256 + threadIdx.x;      // 0..16383 = c*32 + kg
    int c = idx >> 5, kg = idx & 31;
    int h = c >> 6, d = c & 63;
    float v[4];
    #pragma unroll
    for (int q = 0; q < 4; q++)
        v[q] = W[h*(FF*DD) + (kg*4 + q)*DD + d];
    uint32_t h0, l0, h1, l1;
    split2(v[0], v[1], h0, l0);
    split2(v[2], v[3], h1, l1);
    *reinterpret_cast<uint2*>(g_WT_hi + (size_t)c*FF + kg*4) = make_uint2(h0, h1);
    *reinterpret_cast<uint2*>(g_WT_lo + (size_t)c*FF + kg*4) = make_uint2(l0, l1);
}

// ---------------- K4W: Wo[k][c] -> WoT[c][k] bf16 hi/lo ----------------
__global__ __launch_bounds__(256) void k4w_split(const float* __restrict__ Wo) {
    int idx = blockIdx.x*256 + threadIdx.x;      // 0..4095 = c*128 + kg
    int c = idx >> 7, kg = idx & 127;
    float v[4];
    #pragma unroll
    for (int q = 0; q < 4; q++)
        v[q] = Wo[(kg*4 + q)*CC + c];
    uint32_t h0, l0, h1, l1;
    split2(v[0], v[1], h0, l0);
    split2(v[2], v[3], h1, l1);
    *reinterpret_cast<uint2*>(g_WoT_hi + (size_t)c*HD + kg*4) = make_uint2(h0, h1);
    *reinterpret_cast<uint2*>(g_WoT_lo + (size_t)c*HD + kg*4) = make_uint2(l0, l1);
}

// ---------------- K0: adjacency -> transposed bitmask ----------------
__global__ __launch_bounds__(256) void k0_mask(const int* __restrict__ adj) {
    int gw = (blockIdx.x * 256 + threadIdx.x) >> 5;  // 0..8191 = b*2048+row
    int lane = threadIdx.x & 31;
    int b = gw >> 11, row = gw & 2047;
    const int* ar = adj + (size_t)gw * NN;
    #pragma unroll 8
    for (int w = 0; w < 64; w++) {
        unsigned m = __ballot_sync(0xffffffffu, ar[w*32 + lane] > 0);
        if (lane == 0) g_adjbT[((b<<6) + w)*NN + row] = m;
    }
}

// ---------------- K1: Wh = x @ Wcat, HMMA split bf16 ----------------
// smem: Ah @0, Al @18432 (128x72 bf16, 144B pitch); Bh @36864, Bl @46080.
#define K1_SMEM 55296
__global__ __launch_bounds__(256) void k1_hmma() {
    extern __shared__ __align__(16) char smem[];
    uint32_t sb = smem_u32(smem);
    int t = threadIdx.x;
    int warp = t >> 5, lane = t & 31;
    int n0 = blockIdx.x * 64;
    int m0 = blockIdx.y * 128;

    float acc[8][4];
    #pragma unroll
    for (int n=0;n<8;n++){ acc[n][0]=0.f; acc[n][1]=0.f; acc[n][2]=0.f; acc[n][3]=0.f; }

    uint32_t aRow = (uint32_t)(warp*16 + (lane & 15)) * 144u + ((lane & 16) ? 16u : 0u);
    uint32_t bAddr = sb + 36864u + ((lane & 16) ? 9216u : 0u)
                   + (uint32_t)(lane & 7) * 144u + (uint32_t)(lane & 8) * 2u;

    int rA = t >> 1, hA = t & 1;
    int rB = t >> 2, cB = t & 3;

    #pragma unroll
    for (int kt = 0; kt < 2; kt++) {
        if (kt) __syncthreads();
        int k0 = kt * 64;
        {
            const __nv_bfloat16* ph = g_x_hi + (size_t)(m0 + rA)*FF + k0 + hA*32;
            const __nv_bfloat16* pl = g_x_lo + (size_t)(m0 + rA)*FF + k0 + hA*32;
            uint32_t off = (uint32_t)rA*144u + (uint32_t)hA*64u;
            #pragma unroll
            for (int q = 0; q < 4; q++) {
                *reinterpret_cast<uint4*>(smem + off + q*16) =
                    *reinterpret_cast<const uint4*>(ph + q*8);
                *reinterpret_cast<uint4*>(smem + 18432 + off + q*16) =
                    *reinterpret_cast<const uint4*>(pl + q*8);
            }
        }
        {
            const __nv_bfloat16* ph = g_WT_hi + (size_t)(n0 + rB)*FF + k0 + cB*16;
            const __nv_bfloat16* pl = g_WT_lo + (size_t)(n0 + rB)*FF + k0 + cB*16;
            uint32_t off = (uint32_t)rB*144u + (uint32_t)cB*32u;
            #pragma unroll
            for (int q = 0; q < 2; q++) {
                *reinterpret_cast<uint4*>(smem + 36864 + off + q*16) =
                    *reinterpret_cast<const uint4*>(ph + q*8);
                *reinterpret_cast<uint4*>(smem + 46080 + off + q*16) =
                    *reinterpret_cast<const uint4*>(pl + q*8);
            }
        }
        __syncthreads();
        #pragma unroll
        for (int k = 0; k < 4; k++) {
            uint32_t kb = (uint32_t)k * 32u;
            uint32_t ah[4], al[4];
            ldsm_x4(ah, sb + 0     + aRow + kb);
            ldsm_x4(al, sb + 18432 + aRow + kb);
            #pragma unroll
            for (int n = 0; n < 8; n++) {
                uint32_t bf[4];
                ldsm_x4(bf, bAddr + (uint32_t)n*(8u*144u) + kb);
                mma16816(acc[n], ah, bf);
                mma16816(acc[n], ah, bf + 2);
                mma16816(acc[n], al, bf);
            }
        }
    }
    int r0 = warp*16 + (lane >> 2);
    int r1 = r0 + 8;
    int gr0 = m0 + r0, gr1 = m0 + r1;
    int b0 = gr0 >> 11, nd0 = gr0 & 2047;
    int b1 = gr1 >> 11, nd1 = gr1 & 2047;
    #pragma unroll
    for (int n = 0; n < 8; n++) {
        int gc = n0 + n*8 + (lane & 3)*2;
        int h = gc >> 6, d = gc & 63;
        *reinterpret_cast<float2*>(&g_Wh[(size_t)((b0*8+h)*NN + nd0)*DD + d]) =
            make_float2(acc[n][0], acc[n][1]);
        *reinterpret_cast<float2*>(&g_Wh[(size_t)((b1*8+h)*NN + nd1)*DD + d]) =
            make_float2(acc[n][2], acc[n][3]);
    }
}

// ---------------- K2T: transpose Wh -> WhT bf16 hi/lo, + f1/f2 fused ----------------
__global__ __launch_bounds__(256) void k2t_transpose(const float* __restrict__ a1,
                                                     const float* __restrict__ a2) {
    __shared__ float ts[64][129];
    __shared__ float a1s[64], a2s[64];
    int t = threadIdx.x;
    int nblk = blockIdx.x, bh = blockIdx.y;
    int h = bh & 7;
    if (t < 64) { a1s[t] = a1[h*DD + t]; a2s[t] = a2[h*DD + t]; }
    const float* src = g_Wh + ((size_t)bh*NN + nblk*128)*DD;
    #pragma unroll
    for (int q = 0; q < 8; q++) {
        int idx = t + q*256;
        int n = idx >> 4, c4 = idx & 15;
        float4 v = *reinterpret_cast<const float4*>(src + n*DD + c4*4);
        ts[c4*4+0][n] = v.x; ts[c4*4+1][n] = v.y;
        ts[c4*4+2][n] = v.z; ts[c4*4+3][n] = v.w;
    }
    __syncthreads();
    if (t < 128) {
        float f1 = 0.f, f2 = 0.f;
        #pragma unroll
        for (int d = 0; d < 64; d++) {
            float wv = ts[d][t];
            f1 += wv * a1s[d];
            f2 += wv * a2s[d];
        }
        int tid = bh*NN + nblk*128 + t;
        g_F1R[tid] = make_float2(f1, expf(-0.8f*f1));
        g_F2C[tid] = make_float4(f2, expf(f2), expf(0.2f*f2), 0.f);
    }
    #pragma unroll
    for (int q = 0; q < 4; q++) {
        int task = t + q*256;
        int d = task >> 4, nc = task & 15;
        uint32_t hiw[4], low[4];
        #pragma unroll
        for (int p = 0; p < 4; p++)
            split2(ts[d][nc*8 + 2*p], ts[d][nc*8 + 2*p + 1], hiw[p], low[p]);
        size_t off = ((size_t)bh*DD + d)*NN + nblk*128 + nc*8;
        *reinterpret_cast<uint4*>(g_WhT_hi + off) = *reinterpret_cast<uint4*>(hiw);
        *reinterpret_cast<uint4*>(g_WhT_lo + off) = *reinterpret_cast<uint4*>(low);
    }
}

// ---------------- K3: h = elu(softmax(mask(e)) @ Wh), HMMA + cp.async ----------------
// smem: Ah @0, Al @18432; B buf0 hi @36864 lo @46080; buf1 hi @55296 lo @64512;
// zp @73728 (1KB); f2s @74752 (2x64 float4 = 2KB). Total 76800.
#define K3_SMEM 76800
__global__ __launch_bounds__(256) void k3_attn1_mma() {
    extern __shared__ __align__(16) char smem[];
    char* Ahp = smem;
    char* Alp = smem + 18432;
    float* zp = reinterpret_cast<float*>(smem + 73728);
    float4* f2s = reinterpret_cast<float4*>(smem + 74752);
    uint32_t sb = smem_u32(smem);

    int t = threadIdx.x;
    int warp = t >> 5, lane = t & 31;
    int i0 = blockIdx.x * 128;
    int h = blockIdx.y, b = blockIdx.z;
    int bh = (b<<3) + h;

    int i = t & 127, jh = t >> 7;
    float2 f1r = g_F1R[bh*NN + i0 + i];
    float negf1 = -f1r.x, rmul = f1r.y;
    float zacc = 0.f;
    const __nv_bfloat16* bhsrc = g_WhT_hi + (size_t)bh*DD*NN;
    const __nv_bfloat16* blsrc = g_WhT_lo + (size_t)bh*DD*NN;
    const float4* f2g = reinterpret_cast<const float4*>(&g_F2C[bh*NN]);

    float acc[8][4];
    #pragma unroll
    for (int n=0;n<8;n++){ acc[n][0]=0.f; acc[n][1]=0.f; acc[n][2]=0.f; acc[n][3]=0.f; }

    int m0 = warp * 16;
    uint32_t aRow = (uint32_t)(m0 + (lane & 15)) * 144u + ((lane & 16) ? 16u : 0u);
    uint32_t bFrag = ((lane & 16) ? 9216u : 0u)
                   + (uint32_t)(lane & 7) * 144u + (uint32_t)(lane & 8) * 2u;

    // B copy role: d = t>>2 (0..63), chunk c = t&3 (16 j = 32B)
    int dB = t >> 2, cB = t & 3;
    const __nv_bfloat16* pBh = bhsrc + (size_t)dB*NN + cB*16;
    const __nv_bfloat16* pBl = blsrc + (size_t)dB*NN + cB*16;
    uint32_t bStOff = (uint32_t)dB*144u + (uint32_t)cB*32u;

    // prologue: async-load B(0) into buf0; stage f2c(0)
    {
        uint32_t d0 = sb + 36864u + bStOff;
        CP_ASYNC16(d0,          pBh);
        CP_ASYNC16(d0 + 16,     pBh + 8);
        CP_ASYNC16(d0 + 9216u,      pBl);
        CP_ASYNC16(d0 + 9216u + 16, pBl + 8);
        CP_COMMIT();
    }
    if (t < 64) f2s[t] = __ldg(&f2g[t]);
    __syncthreads();

    for (int jt = 0; jt < 32; jt++) {
        int buf = jt & 1;
        if (jt) __syncthreads();       // MMA(jt-1) done: A and B[buf^1] free
        // async-prefetch B(jt+1) into buf^1
        if (jt < 31) {
            uint32_t dN = sb + 36864u + (uint32_t)(buf^1)*18432u + bStOff;
            const __nv_bfloat16* sh = pBh + (jt+1)*64;
            const __nv_bfloat16* sl = pBl + (jt+1)*64;
            CP_ASYNC16(dN,          sh);
            CP_ASYNC16(dN + 16,     sh + 8);
            CP_ASYNC16(dN + 9216u,      sl);
            CP_ASYNC16(dN + 9216u + 16, sl + 8);
            CP_COMMIT();
        }
        // weight phase -> A; f2c read from smem stage (LDS broadcast)
        unsigned bw = g_adjbT[((b<<6) + jt*2 + jh)*NN + i0 + i];
        const float4* f2p = &f2s[(size_t)buf*64 + jh*32];
        #pragma unroll
        for (int oct = 0; oct < 4; oct++) {
            float w[8];
            #pragma unroll
            for (int e = 0; e < 8; e++) {
                float4 fc = f2p[oct*8 + e];
                float w1 = (fc.x > negf1) ? fc.y : rmul*fc.z;
                w[e] = ((bw >> (oct*8 + e)) & 1u) ? w1 : 0.f;
                zacc += w[e];
            }
            uint32_t hiw[4], low[4];
            #pragma unroll
            for (int p = 0; p < 4; p++)
                split2(w[2*p], w[2*p+1], hiw[p], low[p]);
            uint32_t off = (uint32_t)i*144u + (uint32_t)(jh*64 + oct*16);
            *reinterpret_cast<uint4*>(Ahp + off) = *reinterpret_cast<uint4*>(hiw);
            *reinterpret_cast<uint4*>(Alp + off) = *reinterpret_cast<uint4*>(low);
        }
        // stage f2c(jt+1) into the other stage buffer
        if (jt < 31 && t < 64)
            f2s[(size_t)(buf^1)*64 + t] = __ldg(&f2g[(jt+1)*64 + t]);
        if (jt < 31) { CP_WAIT(1); } else { CP_WAIT(0); }
        __syncthreads();               // A + B(jt) + stage(jt) visible
        // ---- MMA(jt) on B[buf] ----
        uint32_t bBase = sb + 36864u + (uint32_t)buf*18432u + bFrag;
        #pragma unroll
        for (int k = 0; k < 4; k++) {
            uint32_t kb = (uint32_t)k * 32u;
            uint32_t ah[4], al[4];
            ldsm_x4(ah, sb + 0     + aRow + kb);
            ldsm_x4(al, sb + 18432 + aRow + kb);
            #pragma unroll
            for (int n = 0; n < 8; n++) {
                uint32_t bf[4];
                ldsm_x4(bf, bBase + (uint32_t)n*(8u*144u) + kb);
                mma16816(acc[n], ah, bf);
                mma16816(acc[n], ah, bf + 2);
                mma16816(acc[n], al, bf);
            }
        }
    }
    zp[jh*128 + i] = zacc;
    __syncthreads();
    // epilogue: normalize + ELU, write h as bf16 hi/lo
    int r0 = m0 + (lane >> 2);
    int r1 = r0 + 8;
    float z0 = zp[r0] + zp[128 + r0];   if (z0 < 1e-30f) z0 = 1.f;
    float z1 = zp[r1] + zp[128 + r1];   if (z1 < 1e-30f) z1 = 1.f;
    float invz0 = 1.f / z0, invz1 = 1.f / z1;
    size_t base0 = (size_t)(b*NN + i0 + r0)*HD + h*DD + (lane & 3)*2;
    size_t base1 = (size_t)(b*NN + i0 + r1)*HD + h*DD + (lane & 3)*2;
    #pragma unroll
    for (int n = 0; n < 8; n++) {
        float v0 = acc[n][0] * invz0, v1 = acc[n][1] * invz0;
        float v2 = acc[n][2] * invz1, v3 = acc[n][3] * invz1;
        v0 = v0 > 0.f ? v0 : expm1f(v0);
        v1 = v1 > 0.f ? v1 : expm1f(v1);
        v2 = v2 > 0.f ? v2 : expm1f(v2);
        v3 = v3 > 0.f ? v3 : expm1f(v3);
        uint32_t h0, l0, h1, l1;
        split2(v0, v1, h0, l0);
        split2(v2, v3, h1, l1);
        *reinterpret_cast<uint32_t*>(g_h_hi + base0 + n*8) = h0;
        *reinterpret_cast<uint32_t*>(g_h_lo + base0 + n*8) = l0;
        *reinterpret_cast<uint32_t*>(g_h_hi + base1 + n*8) = h1;
        *reinterpret_cast<uint32_t*>(g_h_lo + base1 + n*8) = l1;
    }
}

// ---------------- K4: Wh2 = h @ Wo, HMMA split bf16 ----------------
__global__ __launch_bounds__(256) void k4_hmma() {
    __shared__ __align__(16) char Ahp[64*144];
    __shared__ __align__(16) char Alp[64*144];
    __shared__ __align__(16) char Bs[2*32*144];   // hi @0, lo @4608
    uint32_t sbA_h = smem_u32(Ahp), sbA_l = smem_u32(Alp);
    uint32_t sbB = smem_u32(Bs);

    int t = threadIdx.x;
    int warp = t >> 5, lane = t & 31;
    int m0 = blockIdx.x * 64;
    int mt = warp >> 1, nh = warp & 1;

    float acc[2][4];
    acc[0][0]=0.f; acc[0][1]=0.f; acc[0][2]=0.f; acc[0][3]=0.f;
    acc[1][0]=0.f; acc[1][1]=0.f; acc[1][2]=0.f; acc[1][3]=0.f;

    uint32_t aRow = (uint32_t)(mt*16 + (lane & 15)) * 144u + ((lane & 16) ? 16u : 0u);
    uint32_t bAddr = sbB + ((lane & 16) ? 4608u : 0u)
                   + (uint32_t)(lane & 7) * 144u + (uint32_t)(lane & 8) * 2u;

    int rA = t >> 2, cA = t & 3;
    int rB = t >> 3, cB = t & 7;

    #pragma unroll
    for (int kt = 0; kt < 8; kt++) {
        if (kt) __syncthreads();
        int k0 = kt * 64;
        {
            const __nv_bfloat16* ph = g_h_hi + (size_t)(m0 + rA)*HD + k0 + cA*16;
            const __nv_bfloat16* pl = g_h_lo + (size_t)(m0 + rA)*HD + k0 + cA*16;
            uint32_t off = (uint32_t)rA*144u + (uint32_t)cA*32u;
            #pragma unroll
            for (int q = 0; q < 2; q++) {
                *reinterpret_cast<uint4*>(Ahp + off + q*16) =
                    *reinterpret_cast<const uint4*>(ph + q*8);
                *reinterpret_cast<uint4*>(Alp + off + q*16) =
                    *reinterpret_cast<const uint4*>(pl + q*8);
            }
        }
        {
            const __nv_bfloat16* ph = g_WoT_hi + (size_t)rB*HD + k0 + cB*8;
            const __nv_bfloat16* pl = g_WoT_lo + (size_t)rB*HD + k0 + cB*8;
            uint32_t off = (uint32_t)rB*144u + (uint32_t)cB*16u;
            *reinterpret_cast<uint4*>(Bs + off)         = *reinterpret_cast<const uint4*>(ph);
            *reinterpret_cast<uint4*>(Bs + 4608 + off)  = *reinterpret_cast<const uint4*>(pl);
        }
        __syncthreads();
        #pragma unroll
        for (int k = 0; k < 4; k++) {
            uint32_t kb = (uint32_t)k * 32u;
            uint32_t ah[4], al[4];
            ldsm_x4(ah, sbA_h + aRow + kb);
            ldsm_x4(al, sbA_l + aRow + kb);
            #pragma unroll
            for (int n = 0; n < 2; n++) {
                uint32_t bf[4];
                ldsm_x4(bf, bAddr + (uint32_t)(nh*2 + n)*(8u*144u) + kb);
                mma16816(acc[n], ah, bf);
                mma16816(acc[n], ah, bf + 2);
                mma16816(acc[n], al, bf);
            }
        }
    }
    int r0 = mt*16 + (lane >> 2);
    int r1 = r0 + 8;
    #pragma unroll
    for (int n = 0; n < 2; n++) {
        int c0 = nh*16 + n*8 + (lane & 3)*2;
        *reinterpret_cast<float2*>(&g_Wh2[(size_t)(m0 + r0)*CC + c0]) =
            make_float2(acc[n][0], acc[n][1]);
        *reinterpret_cast<float2*>(&g_Wh2[(size_t)(m0 + r1)*CC + c0]) =
            make_float2(acc[n][2], acc[n][3]);
    }
}

// ---------------- K4b: g1,g2 + exp precompute ----------------
__global__ __launch_bounds__(256) void k4b_g(const float* __restrict__ ao1,
                                             const float* __restrict__ ao2) {
    int tid = blockIdx.x*256 + threadIdx.x;  // 0..8191
    const float4* wr = reinterpret_cast<const float4*>(&g_Wh2[tid*CC]);
    const float4* p1 = reinterpret_cast<const float4*>(ao1);
    const float4* p2 = reinterpret_cast<const float4*>(ao2);
    float g1=0.f, g2=0.f;
    #pragma unroll
    for (int i=0;i<8;i++) {
        float4 w = wr[i], v1=p1[i], v2=p2[i];
        g1 += w.x*v1.x + w.y*v1.y + w.z*v1.z + w.w*v1.w;
        g2 += w.x*v2.x + w.y*v2.y + w.z*v2.z + w.w*v2.w;
    }
    g_G1R[tid] = make_float2(g1, expf(-0.8f*g1));
    g_G2C[tid] = make_float4(g2, expf(g2), expf(0.2f*g2), 0.f);
}

// ---------------- K4T: Wh2 fp32 [b][n][c] -> Wh2T bf16 hi/lo [b][c][n] ----------------
__global__ __launch_bounds__(256) void k4t_transpose() {
    __shared__ float ts[32][132];
    int t = threadIdx.x;
    int nblk = blockIdx.x, b = blockIdx.y;
    const float* src = g_Wh2 + ((size_t)(b*NN) + nblk*128)*CC;
    #pragma unroll
    for (int q = 0; q < 4; q++) {
        int idx = t + q*256;
        int n = idx >> 3, c4 = idx & 7;
        float4 v = *reinterpret_cast<const float4*>(src + n*CC + c4*4);
        ts[c4*4+0][n] = v.x; ts[c4*4+1][n] = v.y;
        ts[c4*4+2][n] = v.z; ts[c4*4+3][n] = v.w;
    }
    __syncthreads();
    int c = t >> 3, nc = t & 7;
    uint32_t hiw[8], low[8];
    #pragma unroll
    for (int p = 0; p < 8; p++)
        split2(ts[c][nc*16 + 2*p], ts[c][nc*16 + 2*p + 1], hiw[p], low[p]);
    size_t off = ((size_t)(b*CC) + c)*NN + nblk*128 + nc*16;
    *reinterpret_cast<uint4*>(g_Wh2T_hi + off)     = *reinterpret_cast<uint4*>(&hiw[0]);
    *reinterpret_cast<uint4*>(g_Wh2T_hi + off + 8) = *reinterpret_cast<uint4*>(&hiw[4]);
    *reinterpret_cast<uint4*>(g_Wh2T_lo + off)     = *reinterpret_cast<uint4*>(&low[0]);
    *reinterpret_cast<uint4*>(g_Wh2T_lo + off + 8) = *reinterpret_cast<uint4*>(&low[4]);
}

// ---------------- K5: out = softmax(mask(e2)) @ Wh2, HMMA ----------------
__global__ __launch_bounds__(256) void k5_attn2_mma(float* __restrict__ out) {
    __shared__ __align__(16) char Ahp[64*144];
    __shared__ __align__(16) char Alp[64*144];
    __shared__ __align__(16) char Bs[2*32*144];   // hi @0, lo @4608
    __shared__ float zp[4][64];
    __shared__ __align__(16) float4 g2s[128];     // staged g2c, 2 bufs of 64
    uint32_t sbA_h = smem_u32(Ahp), sbA_l = smem_u32(Alp);
    uint32_t sbB = smem_u32(Bs);

    int t = threadIdx.x;
    int warp = t >> 5, lane = t & 31;
    int i0 = blockIdx.x * 64;
    int b = blockIdx.y;

    int i = t & 63, jq = t >> 6;
    float2 g1r = g_G1R[b*NN + i0 + i];
    float negg = -g1r.x, rmul = g1r.y;
    float zacc = 0.f;
    const __nv_bfloat16* bhsrc = g_Wh2T_hi + (size_t)(b*CC)*NN;
    const __nv_bfloat16* blsrc = g_Wh2T_lo + (size_t)(b*CC)*NN;
    const float4* g2g = reinterpret_cast<const float4*>(&g_G2C[b*NN]);

    int mt = warp >> 1, nh = warp & 1;
    float acc[2][4];
    acc[0][0]=0.f; acc[0][1]=0.f; acc[0][2]=0.f; acc[0][3]=0.f;
    acc[1][0]=0.f; acc[1][1]=0.f; acc[1][2]=0.f; acc[1][3]=0.f;

    uint32_t aRow = (uint32_t)(mt*16 + (lane & 15)) * 144u + ((lane & 16) ? 16u : 0u);
    uint32_t bAddr = sbB + ((lane & 16) ? 4608u : 0u)
                   + (uint32_t)(lane & 7) * 144u + (uint32_t)(lane & 8) * 2u;

    // prologue: stage g2c(0)
    if (t < 64) g2s[t] = __ldg(&g2g[t]);
    __syncthreads();

    for (int jt = 0; jt < 32; jt++) {
        int buf = jt & 1;
        if (jt) __syncthreads();
        int j0 = jt * 64;
        unsigned bwf = g_adjbT[((b<<6) + jt*2 + (jq>>1))*NN + i0 + i];
        unsigned bw = (bwf >> ((jq & 1)*16)) & 0xFFFFu;
        const float4* g2p = &g2s[(size_t)buf*64 + jq*16];
        float w[16];
        #pragma unroll
        for (int e = 0; e < 16; e++) {
            float4 fc = g2p[e];
            float w1 = (fc.x > negg) ? fc.y : rmul*fc.z;
            w[e] = ((bw >> e) & 1u) ? w1 : 0.f;
            zacc += w[e];
        }
        uint32_t hiw[8], low[8];
        #pragma unroll
        for (int p = 0; p < 8; p++)
            split2(w[2*p], w[2*p+1], hiw[p], low[p]);
        uint32_t off = (uint32_t)i*144u + (uint32_t)jq*32u;
        *reinterpret_cast<uint4*>(Ahp + off)      = *reinterpret_cast<uint4*>(&hiw[0]);
        *reinterpret_cast<uint4*>(Ahp + off + 16) = *reinterpret_cast<uint4*>(&hiw[4]);
        *reinterpret_cast<uint4*>(Alp + off)      = *reinterpret_cast<uint4*>(&low[0]);
        *reinterpret_cast<uint4*>(Alp + off + 16) = *reinterpret_cast<uint4*>(&low[4]);
        {
            int c = t >> 3, ch = t & 7;
            uint4 vh = *reinterpret_cast<const uint4*>(bhsrc + (size_t)c*NN + j0 + ch*8);
            uint4 vl = *reinterpret_cast<const uint4*>(blsrc + (size_t)c*NN + j0 + ch*8);
            uint32_t boff = (uint32_t)c*144u + (uint32_t)ch*16u;
            *reinterpret_cast<uint4*>(Bs + boff)        = vh;
            *reinterpret_cast<uint4*>(Bs + 4608 + boff) = vl;
        }
        // stage g2c(jt+1)
        if (jt < 31 && t < 64)
            g2s[(size_t)(buf^1)*64 + t] = __ldg(&g2g[(jt+1)*64 + t]);
        __syncthreads();
        #pragma unroll
        for (int k = 0; k < 4; k++) {
            uint32_t kb = (uint32_t)k * 32u;
            uint32_t ah[4], al[4];
            ldsm_x4(ah, sbA_h + aRow + kb);
            ldsm_x4(al, sbA_l + aRow + kb);
            #pragma unroll
            for (int n = 0; n < 2; n++) {
                uint32_t bf[4];
                ldsm_x4(bf, bAddr + (uint32_t)(nh*2 + n)*(8u*144u) + kb);
                mma16816(acc[n], ah, bf);
                mma16816(acc[n], ah, bf + 2);
                mma16816(acc[n], al, bf);
            }
        }
    }
    zp[jq][i] = zacc;
    __syncthreads();
    int r0 = mt*16 + (lane >> 2);
    int r1 = r0 + 8;
    float z0 = zp[0][r0] + zp[1][r0] + zp[2][r0] + zp[3][r0];
    float z1 = zp[0][r1] + zp[1][r1] + zp[2][r1] + zp[3][r1];
    if (z0 < 1e-30f) z0 = 1.f;
    if (z1 < 1e-30f) z1 = 1.f;
    float invz0 = 1.f / z0, invz1 = 1.f / z1;
    #pragma unroll
    for (int n = 0; n < 2; n++) {
        int c0 = nh*16 + n*8 + (lane & 3)*2;
        float2 o0 = make_float2(acc[n][0]*invz0, acc[n][1]*invz0);
        float2 o1 = make_float2(acc[n][2]*invz1, acc[n][3]*invz1);
        *reinterpret_cast<float2*>(&out[(size_t)(b*NN + i0 + r0)*CC + c0]) = o0;
        *reinterpret_cast<float2*>(&out[(size_t)(b*NN + i0 + r1)*CC + c0]) = o1;
    }
}

extern "C" void kernel_launch(void* const* d_in, const int* in_sizes, int n_in,
                              void* d_out, int out_size) {
    const float* x   = (const float*)d_in[0];
    const int*   adj = (const int*)  d_in[1];
    const float* W   = (const float*)d_in[2];
    const float* a1  = (const float*)d_in[3];
    const float* a2  = (const float*)d_in[4];
    const float* Wo  = (const float*)d_in[5];
    const float* ao1 = (const float*)d_in[6];
    const float* ao2 = (const float*)d_in[7];
    float* out = (float*)d_out;

    cudaFuncSetAttribute(k3_attn1_mma,
                         cudaFuncAttributeMaxDynamicSharedMemorySize, K3_SMEM);
    cudaFuncSetAttribute(k1_hmma,
                         cudaFuncAttributeMaxDynamicSharedMemorySize, K1_SMEM);

    kxs_split<<<1024, 256>>>(x);                      // x -> bf16 hi/lo
    kws_split<<<64, 256>>>(W);                        // W -> WcatT hi/lo
    k4w_split<<<16, 256>>>(Wo);                       // Wo -> WoT hi/lo
    k0_mask<<<1024, 256>>>(adj);                      // adj -> transposed bitmask
    k1_hmma<<<dim3(8, 64), 256, K1_SMEM>>>();         // Wh (HMMA)
    k2t_transpose<<<dim3(16, 32), 256>>>(a1, a2);     // WhT hi/lo + f1/f2
    k3_attn1_mma<<<dim3(16, 8, 4), 256, K3_SMEM>>>(); // layer-1 attn (HMMA+cp.async)
    k4_hmma<<<128, 256>>>();                          // Wh2 = h @ Wo (HMMA)
    k4b_g<<<32, 256>>>(ao1, ao2);                     // g1,g2 + exps
    k4t_transpose<<<dim3(16, 4), 256>>>();            // Wh2T hi/lo
    k5_attn2_mma<<<dim3(32, 4), 256>>>(out);          // layer-2 attn (HMMA)
}

// round 11
// speedup vs baseline: 1.6412x; 1.0497x over previous
#include <cuda_runtime.h>
#include <cuda_bf16.h>
#include <math.h>
#include <stdint.h>

// GAT forward, B=4 N=2048 F=128 H=8 D=64 C=32.
// Softmax trick: exp(lrelu(f1_i+f2_j))/exp(f1_i) = (f1_i+f2_j>0) ? exp(f2_j)
//   : exp(-0.8 f1_i)*exp(0.2 f2_j); exp(f1_i) cancels in softmax.
// R11: k1 fuses x-split + transposed WhT epilogue + f1/f2 (kills kxs,k2t,g_Wh);
// k4 fuses Wh2T transpose + g1/g2 (kills k4b,k4t,g_Wh2); k0 int4+shfl.

#define BB 4
#define NN 2048
#define FF 128
#define DD 64
#define HH 8
#define CC 32
#define HD (HH*DD)

__device__ __align__(16) float2 g_F1R[BB*HH*NN];     // (f1, exp(-0.8 f1))
__device__ __align__(16) float4 g_F2C[BB*HH*NN];     // (f2, exp(f2), exp(0.2 f2), 0)
__device__ __align__(16) float2 g_G1R[BB*NN];
__device__ __align__(16) float4 g_G2C[BB*NN];
__device__ unsigned g_adjbT[BB*64*NN];               // bitmask, TRANSPOSED [b][word][row]
__device__ __align__(16) __nv_bfloat16 g_WhT_hi[BB*HH*DD*NN];  // WhT bf16 hi [bh][d][j]
__device__ __align__(16) __nv_bfloat16 g_WhT_lo[BB*HH*DD*NN];  // WhT bf16 lo
__device__ __align__(16) __nv_bfloat16 g_Wh2T_hi[BB*CC*NN];    // Wh2T bf16 hi [b][c][j]
__device__ __align__(16) __nv_bfloat16 g_Wh2T_lo[BB*CC*NN];    // Wh2T bf16 lo
__device__ __align__(16) __nv_bfloat16 g_WT_hi[HH*DD*FF];      // WcatT [c][f] hi
__device__ __align__(16) __nv_bfloat16 g_WT_lo[HH*DD*FF];
__device__ __align__(16) __nv_bfloat16 g_h_hi[BB*NN*HD];       // h bf16 hi [bn][hd]
__device__ __align__(16) __nv_bfloat16 g_h_lo[BB*NN*HD];
__device__ __align__(16) __nv_bfloat16 g_WoT_hi[CC*HD];        // WoT [c][k] hi
__device__ __align__(16) __nv_bfloat16 g_WoT_lo[CC*HD];

__device__ __forceinline__ uint32_t smem_u32(const void* p) {
    uint32_t a;
    asm("{ .reg .u64 tmp; cvta.to.shared.u64 tmp, %1; cvt.u32.u64 %0, tmp; }"
        : "=r"(a) : "l"(p));
    return a;
}
__device__ __forceinline__ void ldsm_x4(uint32_t* r, uint32_t addr) {
    asm volatile("ldmatrix.sync.aligned.m8n8.x4.shared.b16 {%0,%1,%2,%3}, [%4];"
        : "=r"(r[0]), "=r"(r[1]), "=r"(r[2]), "=r"(r[3]) : "r"(addr));
}
__device__ __forceinline__ void mma16816(float* c, const uint32_t* a, const uint32_t* b) {
    asm volatile(
        "mma.sync.aligned.m16n8k16.row.col.f32.bf16.bf16.f32 "
        "{%0,%1,%2,%3}, {%4,%5,%6,%7}, {%8,%9}, {%0,%1,%2,%3};"
        : "+f"(c[0]), "+f"(c[1]), "+f"(c[2]), "+f"(c[3])
        : "r"(a[0]), "r"(a[1]), "r"(a[2]), "r"(a[3]), "r"(b[0]), "r"(b[1]));
}
#define CP_ASYNC16(dst, src) \
    asm volatile("cp.async.cg.shared.global [%0], [%1], 16;" :: "r"(dst), "l"(src))
#define CP_COMMIT() asm volatile("cp.async.commit_group;" ::: "memory")
#define CP_WAIT(n)  asm volatile("cp.async.wait_group %0;" :: "n"(n) : "memory")

// split a float pair into bf16 hi / lo packed words
__device__ __forceinline__ void split2(float a, float b, uint32_t& hi, uint32_t& lo) {
    __nv_bfloat162 hp = __floats2bfloat162_rn(a, b);
    float2 hf = __bfloat1622float2(hp);
    __nv_bfloat162 lp = __floats2bfloat162_rn(a - hf.x, b - hf.y);
    hi = *reinterpret_cast<uint32_t*>(&hp);
    lo = *reinterpret_cast<uint32_t*>(&lp);
}

// ---------------- KWS: W[h][f][d] -> WcatT[c][f] bf16 hi/lo ----------------
__global__ __launch_bounds__(256) void kws_split(const float* __restrict__ W) {
    int idx = blockIdx.x*256 + threadIdx.x;      // 0..16383 = c*32 + kg
    int c = idx >> 5, kg = idx & 31;
    int h = c >> 6, d = c & 63;
    float v[4];
    #pragma unroll
    for (int q = 0; q < 4; q++)
        v[q] = W[h*(FF*DD) + (kg*4 + q)*DD + d];
    uint32_t h0, l0, h1, l1;
    split2(v[0], v[1], h0, l0);
    split2(v[2], v[3], h1, l1);
    *reinterpret_cast<uint2*>(g_WT_hi + (size_t)c*FF + kg*4) = make_uint2(h0, h1);
    *reinterpret_cast<uint2*>(g_WT_lo + (size_t)c*FF + kg*4) = make_uint2(l0, l1);
}

// ---------------- K4W: Wo[k][c] -> WoT[c][k] bf16 hi/lo ----------------
__global__ __launch_bounds__(256) void k4w_split(const float* __restrict__ Wo) {
    int idx = blockIdx.x*256 + threadIdx.x;      // 0..4095 = c*128 + kg
    int c = idx >> 7, kg = idx & 127;
    float v[4];
    #pragma unroll
    for (int q = 0; q < 4; q++)
        v[q] = Wo[(kg*4 + q)*CC + c];
    uint32_t h0, l0, h1, l1;
    split2(v[0], v[1], h0, l0);
    split2(v[2], v[3], h1, l1);
    *reinterpret_cast<uint2*>(g_WoT_hi + (size_t)c*HD + kg*4) = make_uint2(h0, h1);
    *reinterpret_cast<uint2*>(g_WoT_lo + (size_t)c*HD + kg*4) = make_uint2(l0, l1);
}

// ---------------- K0: adjacency -> transposed bitmask (int4 + shfl-or) ----------------
__global__ __launch_bounds__(256) void k0_mask(const int* __restrict__ adj) {
    int gw = (blockIdx.x * 256 + threadIdx.x) >> 5;  // 0..8191 = b*2048+row
    int lane = threadIdx.x & 31;
    int b = gw >> 11, row = gw & 2047;
    const int4* ar4 = reinterpret_cast<const int4*>(adj + (size_t)gw * NN);
    int lg = lane & 7, wsel = lane >> 3;
    #pragma unroll 4
    for (int it = 0; it < 16; it++) {
        int4 v = ar4[it*32 + lane];
        unsigned nib = (v.x > 0 ? 1u : 0u) | (v.y > 0 ? 2u : 0u)
                     | (v.z > 0 ? 4u : 0u) | (v.w > 0 ? 8u : 0u);
        unsigned part = nib << (lg * 4);
        part |= __shfl_xor_sync(0xffffffffu, part, 1);
        part |= __shfl_xor_sync(0xffffffffu, part, 2);
        part |= __shfl_xor_sync(0xffffffffu, part, 4);
        if (lg == 0)
            g_adjbT[((b<<6) + it*4 + wsel)*NN + row] = part;
    }
}

// ---------------- K1: Wh = x @ Wcat, HMMA; fused WhT-transpose + f1/f2 epilogue ----------------
// Main loop smem: Ah @0, Al @18432 (128x72 bf16); Bh @36864, Bl @46080.
// Epilogue overlays: ts[64][132] fp32 @0 (33792B), a1s @33792, a2s @34048.
#define K1_SMEM 55296
__global__ __launch_bounds__(256) void k1_hmma(const float* __restrict__ x,
                                               const float* __restrict__ a1,
                                               const float* __restrict__ a2) {
    extern __shared__ __align__(16) char smem[];
    uint32_t sb = smem_u32(smem);
    int t = threadIdx.x;
    int warp = t >> 5, lane = t & 31;
    int h = blockIdx.x;             // head; output cols h*64..h*64+63
    int m0 = blockIdx.y * 128;      // global row block
    int b = m0 >> 11, nd0 = m0 & 2047;
    int bh = b*8 + h;

    float acc[8][4];
    #pragma unroll
    for (int n=0;n<8;n++){ acc[n][0]=0.f; acc[n][1]=0.f; acc[n][2]=0.f; acc[n][3]=0.f; }

    uint32_t aRow = (uint32_t)(warp*16 + (lane & 15)) * 144u + ((lane & 16) ? 16u : 0u);
    uint32_t bAddr = sb + 36864u + ((lane & 16) ? 9216u : 0u)
                   + (uint32_t)(lane & 7) * 144u + (uint32_t)(lane & 8) * 2u;

    int rA = t >> 1, hA = t & 1;    // A: 128 rows x 2 halves (32 k)
    int rB = t >> 2, cB = t & 3;    // B: 64 rows x 4 chunks (16 k)

    #pragma unroll
    for (int kt = 0; kt < 2; kt++) {
        if (kt) __syncthreads();
        int k0 = kt * 64;
        {   // A tile: x fp32 -> split inline -> smem hi/lo
            const float4* px = reinterpret_cast<const float4*>(
                x + (size_t)(m0 + rA)*FF + k0 + hA*32);
            uint32_t off = (uint32_t)rA*144u + (uint32_t)hA*64u;
            #pragma unroll
            for (int q = 0; q < 4; q++) {
                float4 v0 = px[q*2], v1 = px[q*2+1];
                uint32_t hw[4], lw[4];
                split2(v0.x, v0.y, hw[0], lw[0]);
                split2(v0.z, v0.w, hw[1], lw[1]);
                split2(v1.x, v1.y, hw[2], lw[2]);
                split2(v1.z, v1.w, hw[3], lw[3]);
                *reinterpret_cast<uint4*>(smem + off + q*16) =
                    *reinterpret_cast<uint4*>(hw);
                *reinterpret_cast<uint4*>(smem + 18432 + off + q*16) =
                    *reinterpret_cast<uint4*>(lw);
            }
        }
        {   // B tile: WcatT hi/lo (pre-split)
            const __nv_bfloat16* ph = g_WT_hi + (size_t)(h*64 + rB)*FF + k0 + cB*16;
            const __nv_bfloat16* pl = g_WT_lo + (size_t)(h*64 + rB)*FF + k0 + cB*16;
            uint32_t off = (uint32_t)rB*144u + (uint32_t)cB*32u;
            #pragma unroll
            for (int q = 0; q < 2; q++) {
                *reinterpret_cast<uint4*>(smem + 36864 + off + q*16) =
                    *reinterpret_cast<const uint4*>(ph + q*8);
                *reinterpret_cast<uint4*>(smem + 46080 + off + q*16) =
                    *reinterpret_cast<const uint4*>(pl + q*8);
            }
        }
        __syncthreads();
        #pragma unroll
        for (int k = 0; k < 4; k++) {
            uint32_t kb = (uint32_t)k * 32u;
            uint32_t ah[4], al[4];
            ldsm_x4(ah, sb + 0     + aRow + kb);
            ldsm_x4(al, sb + 18432 + aRow + kb);
            #pragma unroll
            for (int n = 0; n < 8; n++) {
                uint32_t bf[4];
                ldsm_x4(bf, bAddr + (uint32_t)n*(8u*144u) + kb);
                mma16816(acc[n], ah, bf);
                mma16816(acc[n], ah, bf + 2);
                mma16816(acc[n], al, bf);
            }
        }
    }
    // ---- fused epilogue: stage transposed tile, f1/f2, WhT hi/lo ----
    __syncthreads();                 // smem free for reuse
    float* ts = reinterpret_cast<float*>(smem);          // [64 d][132]
    float* a1s = reinterpret_cast<float*>(smem + 33792); // 64
    float* a2s = reinterpret_cast<float*>(smem + 34048); // 64
    if (t < 64) { a1s[t] = a1[h*DD + t]; a2s[t] = a2[h*DD + t]; }
    int r0 = warp*16 + (lane >> 2);
    int r1 = r0 + 8;
    #pragma unroll
    for (int n = 0; n < 8; n++) {
        int c = n*8 + (lane & 3)*2;
        ts[c*132 + r0]     = acc[n][0];
        ts[(c+1)*132 + r0] = acc[n][1];
        ts[c*132 + r1]     = acc[n][2];
        ts[(c+1)*132 + r1] = acc[n][3];
    }
    __syncthreads();
    if (t < 128) {
        float f1 = 0.f, f2 = 0.f;
        #pragma unroll
        for (int d = 0; d < 64; d++) {
            float wv = ts[d*132 + t];
            f1 += wv * a1s[d];
            f2 += wv * a2s[d];
        }
        int tid = bh*NN + nd0 + t;
        g_F1R[tid] = make_float2(f1, expf(-0.8f*f1));
        g_F2C[tid] = make_float4(f2, expf(f2), expf(0.2f*f2), 0.f);
    }
    #pragma unroll
    for (int q = 0; q < 4; q++) {
        int task = t + q*256;        // 0..1023 = 64 d x 16 chunks(8 n)
        int d = task >> 4, nc = task & 15;
        uint32_t hiw[4], low[4];
        #pragma unroll
        for (int p = 0; p < 4; p++)
            split2(ts[d*132 + nc*8 + 2*p], ts[d*132 + nc*8 + 2*p + 1], hiw[p], low[p]);
        size_t off = ((size_t)bh*DD + d)*NN + nd0 + nc*8;
        *reinterpret_cast<uint4*>(g_WhT_hi + off) = *reinterpret_cast<uint4*>(hiw);
        *reinterpret_cast<uint4*>(g_WhT_lo + off) = *reinterpret_cast<uint4*>(low);
    }
}

// ---------------- K3: h = elu(softmax(mask(e)) @ Wh), HMMA + cp.async ----------------
// smem: Ah @0, Al @18432; B buf0 hi @36864 lo @46080; buf1 hi @55296 lo @64512;
// zp @73728 (1KB); f2s @74752 (2x64 float4 = 2KB). Total 76800.
#define K3_SMEM 76800
__global__ __launch_bounds__(256) void k3_attn1_mma() {
    extern __shared__ __align__(16) char smem[];
    char* Ahp = smem;
    char* Alp = smem + 18432;
    float* zp = reinterpret_cast<float*>(smem + 73728);
    float4* f2s = reinterpret_cast<float4*>(smem + 74752);
    uint32_t sb = smem_u32(smem);

    int t = threadIdx.x;
    int warp = t >> 5, lane = t & 31;
    int i0 = blockIdx.x * 128;
    int h = blockIdx.y, b = blockIdx.z;
    int bh = (b<<3) + h;

    int i = t & 127, jh = t >> 7;
    float2 f1r = g_F1R[bh*NN + i0 + i];
    float negf1 = -f1r.x, rmul = f1r.y;
    float zacc = 0.f;
    const __nv_bfloat16* bhsrc = g_WhT_hi + (size_t)bh*DD*NN;
    const __nv_bfloat16* blsrc = g_WhT_lo + (size_t)bh*DD*NN;
    const float4* f2g = reinterpret_cast<const float4*>(&g_F2C[bh*NN]);

    float acc[8][4];
    #pragma unroll
    for (int n=0;n<8;n++){ acc[n][0]=0.f; acc[n][1]=0.f; acc[n][2]=0.f; acc[n][3]=0.f; }

    int m0 = warp * 16;
    uint32_t aRow = (uint32_t)(m0 + (lane & 15)) * 144u + ((lane & 16) ? 16u : 0u);
    uint32_t bFrag = ((lane & 16) ? 9216u : 0u)
                   + (uint32_t)(lane & 7) * 144u + (uint32_t)(lane & 8) * 2u;

    int dB = t >> 2, cB = t & 3;
    const __nv_bfloat16* pBh = bhsrc + (size_t)dB*NN + cB*16;
    const __nv_bfloat16* pBl = blsrc + (size_t)dB*NN + cB*16;
    uint32_t bStOff = (uint32_t)dB*144u + (uint32_t)cB*32u;

    {
        uint32_t d0 = sb + 36864u + bStOff;
        CP_ASYNC16(d0,          pBh);
        CP_ASYNC16(d0 + 16,     pBh + 8);
        CP_ASYNC16(d0 + 9216u,      pBl);
        CP_ASYNC16(d0 + 9216u + 16, pBl + 8);
        CP_COMMIT();
    }
    if (t < 64) f2s[t] = __ldg(&f2g[t]);
    __syncthreads();

    for (int jt = 0; jt < 32; jt++) {
        int buf = jt & 1;
        if (jt) __syncthreads();
        if (jt < 31) {
            uint32_t dN = sb + 36864u + (uint32_t)(buf^1)*18432u + bStOff;
            const __nv_bfloat16* sh = pBh + (jt+1)*64;
            const __nv_bfloat16* sl = pBl + (jt+1)*64;
            CP_ASYNC16(dN,          sh);
            CP_ASYNC16(dN + 16,     sh + 8);
            CP_ASYNC16(dN + 9216u,      sl);
            CP_ASYNC16(dN + 9216u + 16, sl + 8);
            CP_COMMIT();
        }
        unsigned bw = g_adjbT[((b<<6) + jt*2 + jh)*NN + i0 + i];
        const float4* f2p = &f2s[(size_t)buf*64 + jh*32];
        #pragma unroll
        for (int oct = 0; oct < 4; oct++) {
            float w[8];
            #pragma unroll
            for (int e = 0; e < 8; e++) {
                float4 fc = f2p[oct*8 + e];
                float w1 = (fc.x > negf1) ? fc.y : rmul*fc.z;
                w[e] = ((bw >> (oct*8 + e)) & 1u) ? w1 : 0.f;
                zacc += w[e];
            }
            uint32_t hiw[4], low[4];
            #pragma unroll
            for (int p = 0; p < 4; p++)
                split2(w[2*p], w[2*p+1], hiw[p], low[p]);
            uint32_t off = (uint32_t)i*144u + (uint32_t)(jh*64 + oct*16);
            *reinterpret_cast<uint4*>(Ahp + off) = *reinterpret_cast<uint4*>(hiw);
            *reinterpret_cast<uint4*>(Alp + off) = *reinterpret_cast<uint4*>(low);
        }
        if (jt < 31 && t < 64)
            f2s[(size_t)(buf^1)*64 + t] = __ldg(&f2g[(jt+1)*64 + t]);
        if (jt < 31) { CP_WAIT(1); } else { CP_WAIT(0); }
        __syncthreads();
        uint32_t bBase = sb + 36864u + (uint32_t)buf*18432u + bFrag;
        #pragma unroll
        for (int k = 0; k < 4; k++) {
            uint32_t kb = (uint32_t)k * 32u;
            uint32_t ah[4], al[4];
            ldsm_x4(ah, sb + 0     + aRow + kb);
            ldsm_x4(al, sb + 18432 + aRow + kb);
            #pragma unroll
            for (int n = 0; n < 8; n++) {
                uint32_t bf[4];
                ldsm_x4(bf, bBase + (uint32_t)n*(8u*144u) + kb);
                mma16816(acc[n], ah, bf);
                mma16816(acc[n], ah, bf + 2);
                mma16816(acc[n], al, bf);
            }
        }
    }
    zp[jh*128 + i] = zacc;
    __syncthreads();
    int r0 = m0 + (lane >> 2);
    int r1 = r0 + 8;
    float z0 = zp[r0] + zp[128 + r0];   if (z0 < 1e-30f) z0 = 1.f;
    float z1 = zp[r1] + zp[128 + r1];   if (z1 < 1e-30f) z1 = 1.f;
    float invz0 = 1.f / z0, invz1 = 1.f / z1;
    size_t base0 = (size_t)(b*NN + i0 + r0)*HD + h*DD + (lane & 3)*2;
    size_t base1 = (size_t)(b*NN + i0 + r1)*HD + h*DD + (lane & 3)*2;
    #pragma unroll
    for (int n = 0; n < 8; n++) {
        float v0 = acc[n][0] * invz0, v1 = acc[n][1] * invz0;
        float v2 = acc[n][2] * invz1, v3 = acc[n][3] * invz1;
        v0 = v0 > 0.f ? v0 : expm1f(v0);
        v1 = v1 > 0.f ? v1 : expm1f(v1);
        v2 = v2 > 0.f ? v2 : expm1f(v2);
        v3 = v3 > 0.f ? v3 : expm1f(v3);
        uint32_t h0, l0, h1, l1;
        split2(v0, v1, h0, l0);
        split2(v2, v3, h1, l1);
        *reinterpret_cast<uint32_t*>(g_h_hi + base0 + n*8) = h0;
        *reinterpret_cast<uint32_t*>(g_h_lo + base0 + n*8) = l0;
        *reinterpret_cast<uint32_t*>(g_h_hi + base1 + n*8) = h1;
        *reinterpret_cast<uint32_t*>(g_h_lo + base1 + n*8) = l1;
    }
}

// ---------------- K4: Wh2 = h @ Wo, HMMA; fused Wh2T-transpose + g1/g2 epilogue ----------------
__global__ __launch_bounds__(256) void k4_hmma(const float* __restrict__ ao1,
                                               const float* __restrict__ ao2) {
    __shared__ __align__(16) char Ahp[64*144];
    __shared__ __align__(16) char Alp[64*144];
    __shared__ __align__(16) char Bs[2*32*144];   // hi @0, lo @4608
    uint32_t sbA_h = smem_u32(Ahp), sbA_l = smem_u32(Alp);
    uint32_t sbB = smem_u32(Bs);

    int t = threadIdx.x;
    int warp = t >> 5, lane = t & 31;
    int m0 = blockIdx.x * 64;
    int b = m0 >> 11, nd0 = m0 & 2047;
    int mt = warp >> 1, nh = warp & 1;

    float acc[2][4];
    acc[0][0]=0.f; acc[0][1]=0.f; acc[0][2]=0.f; acc[0][3]=0.f;
    acc[1][0]=0.f; acc[1][1]=0.f; acc[1][2]=0.f; acc[1][3]=0.f;

    uint32_t aRow = (uint32_t)(mt*16 + (lane & 15)) * 144u + ((lane & 16) ? 16u : 0u);
    uint32_t bAddr = sbB + ((lane & 16) ? 4608u : 0u)
                   + (uint32_t)(lane & 7) * 144u + (uint32_t)(lane & 8) * 2u;

    int rA = t >> 2, cA = t & 3;
    int rB = t >> 3, cB = t & 7;

    #pragma unroll
    for (int kt = 0; kt < 8; kt++) {
        if (kt) __syncthreads();
        int k0 = kt * 64;
        {
            const __nv_bfloat16* ph = g_h_hi + (size_t)(m0 + rA)*HD + k0 + cA*16;
            const __nv_bfloat16* pl = g_h_lo + (size_t)(m0 + rA)*HD + k0 + cA*16;
            uint32_t off = (uint32_t)rA*144u + (uint32_t)cA*32u;
            #pragma unroll
            for (int q = 0; q < 2; q++) {
                *reinterpret_cast<uint4*>(Ahp + off + q*16) =
                    *reinterpret_cast<const uint4*>(ph + q*8);
                *reinterpret_cast<uint4*>(Alp + off + q*16) =
                    *reinterpret_cast<const uint4*>(pl + q*8);
            }
        }
        {
            const __nv_bfloat16* ph = g_WoT_hi + (size_t)rB*HD + k0 + cB*8;
            const __nv_bfloat16* pl = g_WoT_lo + (size_t)rB*HD + k0 + cB*8;
            uint32_t off = (uint32_t)rB*144u + (uint32_t)cB*16u;
            *reinterpret_cast<uint4*>(Bs + off)         = *reinterpret_cast<const uint4*>(ph);
            *reinterpret_cast<uint4*>(Bs + 4608 + off)  = *reinterpret_cast<const uint4*>(pl);
        }
        __syncthreads();
        #pragma unroll
        for (int k = 0; k < 4; k++) {
            uint32_t kb = (uint32_t)k * 32u;
            uint32_t ah[4], al[4];
            ldsm_x4(ah, sbA_h + aRow + kb);
            ldsm_x4(al, sbA_l + aRow + kb);
            #pragma unroll
            for (int n = 0; n < 2; n++) {
                uint32_t bf[4];
                ldsm_x4(bf, bAddr + (uint32_t)(nh*2 + n)*(8u*144u) + kb);
                mma16816(acc[n], ah, bf);
                mma16816(acc[n], ah, bf + 2);
                mma16816(acc[n], al, bf);
            }
        }
    }
    // ---- fused epilogue: transpose tile, g1/g2, Wh2T hi/lo ----
    __syncthreads();
    float* ts2 = reinterpret_cast<float*>(Ahp);          // [32 c][68]
    float* ao1s = reinterpret_cast<float*>(Alp);         // 32
    float* ao2s = reinterpret_cast<float*>(Alp + 128);   // 32
    if (t < 32) { ao1s[t] = ao1[t]; ao2s[t] = ao2[t]; }
    int r0 = mt*16 + (lane >> 2);
    int r1 = r0 + 8;
    #pragma unroll
    for (int n = 0; n < 2; n++) {
        int c = nh*16 + n*8 + (lane & 3)*2;
        ts2[c*68 + r0]     = acc[n][0];
        ts2[(c+1)*68 + r0] = acc[n][1];
        ts2[c*68 + r1]     = acc[n][2];
        ts2[(c+1)*68 + r1] = acc[n][3];
    }
    __syncthreads();
    if (t < 64) {
        float g1 = 0.f, g2 = 0.f;
        #pragma unroll
        for (int c = 0; c < 32; c++) {
            float wv = ts2[c*68 + t];
            g1 += wv * ao1s[c];
            g2 += wv * ao2s[c];
        }
        int tid = b*NN + nd0 + t;
        g_G1R[tid] = make_float2(g1, expf(-0.8f*g1));
        g_G2C[tid] = make_float4(g2, expf(g2), expf(0.2f*g2), 0.f);
    }
    {   // Wh2T: 32 c x 8 chunks(8 n) = 256 tasks
        int c = t >> 3, nc = t & 7;
        uint32_t hiw[4], low[4];
        #pragma unroll
        for (int p = 0; p < 4; p++)
            split2(ts2[c*68 + nc*8 + 2*p], ts2[c*68 + nc*8 + 2*p + 1], hiw[p], low[p]);
        size_t off = ((size_t)(b*CC) + c)*NN + nd0 + nc*8;
        *reinterpret_cast<uint4*>(g_Wh2T_hi + off) = *reinterpret_cast<uint4*>(hiw);
        *reinterpret_cast<uint4*>(g_Wh2T_lo + off) = *reinterpret_cast<uint4*>(low);
    }
}

// ---------------- K5: out = softmax(mask(e2)) @ Wh2, HMMA ----------------
__global__ __launch_bounds__(256) void k5_attn2_mma(float* __restrict__ out) {
    __shared__ __align__(16) char Ahp[64*144];
    __shared__ __align__(16) char Alp[64*144];
    __shared__ __align__(16) char Bs[2*32*144];   // hi @0, lo @4608
    __shared__ float zp[4][64];
    __shared__ __align__(16) float4 g2s[128];     // staged g2c, 2 bufs of 64
    uint32_t sbA_h = smem_u32(Ahp), sbA_l = smem_u32(Alp);
    uint32_t sbB = smem_u32(Bs);

    int t = threadIdx.x;
    int warp = t >> 5, lane = t & 31;
    int i0 = blockIdx.x * 64;
    int b = blockIdx.y;

    int i = t & 63, jq = t >> 6;
    float2 g1r = g_G1R[b*NN + i0 + i];
    float negg = -g1r.x, rmul = g1r.y;
    float zacc = 0.f;
    const __nv_bfloat16* bhsrc = g_Wh2T_hi + (size_t)(b*CC)*NN;
    const __nv_bfloat16* blsrc = g_Wh2T_lo + (size_t)(b*CC)*NN;
    const float4* g2g = reinterpret_cast<const float4*>(&g_G2C[b*NN]);

    int mt = warp >> 1, nh = warp & 1;
    float acc[2][4];
    acc[0][0]=0.f; acc[0][1]=0.f; acc[0][2]=0.f; acc[0][3]=0.f;
    acc[1][0]=0.f; acc[1][1]=0.f; acc[1][2]=0.f; acc[1][3]=0.f;

    uint32_t aRow = (uint32_t)(mt*16 + (lane & 15)) * 144u + ((lane & 16) ? 16u : 0u);
    uint32_t bAddr = sbB + ((lane & 16) ? 4608u : 0u)
                   + (uint32_t)(lane & 7) * 144u + (uint32_t)(lane & 8) * 2u;

    if (t < 64) g2s[t] = __ldg(&g2g[t]);
    __syncthreads();

    for (int jt = 0; jt < 32; jt++) {
        int buf = jt & 1;
        if (jt) __syncthreads();
        int j0 = jt * 64;
        unsigned bwf = g_adjbT[((b<<6) + jt*2 + (jq>>1))*NN + i0 + i];
        unsigned bw = (bwf >> ((jq & 1)*16)) & 0xFFFFu;
        const float4* g2p = &g2s[(size_t)buf*64 + jq*16];
        float w[16];
        #pragma unroll
        for (int e = 0; e < 16; e++) {
            float4 fc = g2p[e];
            float w1 = (fc.x > negg) ? fc.y : rmul*fc.z;
            w[e] = ((bw >> e) & 1u) ? w1 : 0.f;
            zacc += w[e];
        }
        uint32_t hiw[8], low[8];
        #pragma unroll
        for (int p = 0; p < 8; p++)
            split2(w[2*p], w[2*p+1], hiw[p], low[p]);
        uint32_t off = (uint32_t)i*144u + (uint32_t)jq*32u;
        *reinterpret_cast<uint4*>(Ahp + off)      = *reinterpret_cast<uint4*>(&hiw[0]);
        *reinterpret_cast<uint4*>(Ahp + off + 16) = *reinterpret_cast<uint4*>(&hiw[4]);
        *reinterpret_cast<uint4*>(Alp + off)      = *reinterpret_cast<uint4*>(&low[0]);
        *reinterpret_cast<uint4*>(Alp + off + 16) = *reinterpret_cast<uint4*>(&low[4]);
        {
            int c = t >> 3, ch = t & 7;
            uint4 vh = *reinterpret_cast<const uint4*>(bhsrc + (size_t)c*NN + j0 + ch*8);
            uint4 vl = *reinterpret_cast<const uint4*>(blsrc + (size_t)c*NN + j0 + ch*8);
            uint32_t boff = (uint32_t)c*144u + (uint32_t)ch*16u;
            *reinterpret_cast<uint4*>(Bs + boff)        = vh;
            *reinterpret_cast<uint4*>(Bs + 4608 + boff) = vl;
        }
        if (jt < 31 && t < 64)
            g2s[(size_t)(buf^1)*64 + t] = __ldg(&g2g[(jt+1)*64 + t]);
        __syncthreads();
        #pragma unroll
        for (int k = 0; k < 4; k++) {
            uint32_t kb = (uint32_t)k * 32u;
            uint32_t ah[4], al[4];
            ldsm_x4(ah, sbA_h + aRow + kb);
            ldsm_x4(al, sbA_l + aRow + kb);
            #pragma unroll
            for (int n = 0; n < 2; n++) {
                uint32_t bf[4];
                ldsm_x4(bf, bAddr + (uint32_t)(nh*2 + n)*(8u*144u) + kb);
                mma16816(acc[n], ah, bf);
                mma16816(acc[n], ah, bf + 2);
                mma16816(acc[n], al, bf);
            }
        }
    }
    zp[jq][i] = zacc;
    __syncthreads();
    int r0 = mt*16 + (lane >> 2);
    int r1 = r0 + 8;
    float z0 = zp[0][r0] + zp[1][r0] + zp[2][r0] + zp[3][r0];
    float z1 = zp[0][r1] + zp[1][r1] + zp[2][r1] + zp[3][r1];
    if (z0 < 1e-30f) z0 = 1.f;
    if (z1 < 1e-30f) z1 = 1.f;
    float invz0 = 1.f / z0, invz1 = 1.f / z1;
    #pragma unroll
    for (int n = 0; n < 2; n++) {
        int c0 = nh*16 + n*8 + (lane & 3)*2;
        float2 o0 = make_float2(acc[n][0]*invz0, acc[n][1]*invz0);
        float2 o1 = make_float2(acc[n][2]*invz1, acc[n][3]*invz1);
        *reinterpret_cast<float2*>(&out[(size_t)(b*NN + i0 + r0)*CC + c0]) = o0;
        *reinterpret_cast<float2*>(&out[(size_t)(b*NN + i0 + r1)*CC + c0]) = o1;
    }
}

extern "C" void kernel_launch(void* const* d_in, const int* in_sizes, int n_in,
                              void* d_out, int out_size) {
    const float* x   = (const float*)d_in[0];
    const int*   adj = (const int*)  d_in[1];
    const float* W   = (const float*)d_in[2];
    const float* a1  = (const float*)d_in[3];
    const float* a2  = (const float*)d_in[4];
    const float* Wo  = (const float*)d_in[5];
    const float* ao1 = (const float*)d_in[6];
    const float* ao2 = (const float*)d_in[7];
    float* out = (float*)d_out;

    cudaFuncSetAttribute(k3_attn1_mma,
                         cudaFuncAttributeMaxDynamicSharedMemorySize, K3_SMEM);
    cudaFuncSetAttribute(k1_hmma,
                         cudaFuncAttributeMaxDynamicSharedMemorySize, K1_SMEM);

    kws_split<<<64, 256>>>(W);                        // W -> WcatT hi/lo
    k4w_split<<<16, 256>>>(Wo);                       // Wo -> WoT hi/lo
    k0_mask<<<1024, 256>>>(adj);                      // adj -> transposed bitmask
    k1_hmma<<<dim3(8, 64), 256, K1_SMEM>>>(x, a1, a2);// Wh + WhT hi/lo + f1/f2
    k3_attn1_mma<<<dim3(16, 8, 4), 256, K3_SMEM>>>(); // layer-1 attn (HMMA+cp.async)
    k4_hmma<<<128, 256>>>(ao1, ao2);                  // Wh2T hi/lo + g1/g2
    k5_attn2_mma<<<dim3(32, 4), 256>>>(out);          // layer-2 attn (HMMA)
}

// round 12
// speedup vs baseline: 1.8927x; 1.1532x over previous
#include <cuda_runtime.h>
#include <cuda_bf16.h>
#include <cuda_fp16.h>
#include <math.h>
#include <stdint.h>

// GAT forward, B=4 N=2048 F=128 H=8 D=64 C=32.
// Softmax trick: exp(lrelu(f1_i+f2_j))/exp(f1_i) = (f1_i+f2_j>0) ? exp(f2_j)
//   : exp(-0.8 f1_i)*exp(0.2 f2_j); exp(f1_i) cancels in softmax.
// R12: k3/k5 switched to fp16 2-product MMA (A = plain fp16 weights (2^-11),
// B = fp16 hi/lo (2^-22)); k1/k4 mainloops stay bf16 3-product, epilogues
// emit fp16 hi/lo for WhT / Wh2T.

#define BB 4
#define NN 2048
#define FF 128
#define DD 64
#define HH 8
#define CC 32
#define HD (HH*DD)

__device__ __align__(16) float2 g_F1R[BB*HH*NN];     // (f1, exp(-0.8 f1))
__device__ __align__(16) float4 g_F2C[BB*HH*NN];     // (f2, exp(f2), exp(0.2 f2), 0)
__device__ __align__(16) float2 g_G1R[BB*NN];
__device__ __align__(16) float4 g_G2C[BB*NN];
__device__ unsigned g_adjbT[BB*64*NN];               // bitmask, TRANSPOSED [b][word][row]
__device__ __align__(16) __half g_WhT_hi[BB*HH*DD*NN];   // WhT fp16 hi [bh][d][j]
__device__ __align__(16) __half g_WhT_lo[BB*HH*DD*NN];   // WhT fp16 lo
__device__ __align__(16) __half g_Wh2T_hi[BB*CC*NN];     // Wh2T fp16 hi [b][c][j]
__device__ __align__(16) __half g_Wh2T_lo[BB*CC*NN];     // Wh2T fp16 lo
__device__ __align__(16) __nv_bfloat16 g_WT_hi[HH*DD*FF];  // WcatT [c][f] bf16 hi
__device__ __align__(16) __nv_bfloat16 g_WT_lo[HH*DD*FF];
__device__ __align__(16) __nv_bfloat16 g_h_hi[BB*NN*HD];   // h bf16 hi [bn][hd]
__device__ __align__(16) __nv_bfloat16 g_h_lo[BB*NN*HD];
__device__ __align__(16) __nv_bfloat16 g_WoT_hi[CC*HD];    // WoT [c][k] bf16 hi
__device__ __align__(16) __nv_bfloat16 g_WoT_lo[CC*HD];

__device__ __forceinline__ uint32_t smem_u32(const void* p) {
    uint32_t a;
    asm("{ .reg .u64 tmp; cvta.to.shared.u64 tmp, %1; cvt.u32.u64 %0, tmp; }"
        : "=r"(a) : "l"(p));
    return a;
}
__device__ __forceinline__ void ldsm_x4(uint32_t* r, uint32_t addr) {
    asm volatile("ldmatrix.sync.aligned.m8n8.x4.shared.b16 {%0,%1,%2,%3}, [%4];"
        : "=r"(r[0]), "=r"(r[1]), "=r"(r[2]), "=r"(r[3]) : "r"(addr));
}
// bf16 mma (k1/k4)
__device__ __forceinline__ void mma16816(float* c, const uint32_t* a, const uint32_t* b) {
    asm volatile(
        "mma.sync.aligned.m16n8k16.row.col.f32.bf16.bf16.f32 "
        "{%0,%1,%2,%3}, {%4,%5,%6,%7}, {%8,%9}, {%0,%1,%2,%3};"
        : "+f"(c[0]), "+f"(c[1]), "+f"(c[2]), "+f"(c[3])
        : "r"(a[0]), "r"(a[1]), "r"(a[2]), "r"(a[3]), "r"(b[0]), "r"(b[1]));
}
// fp16 mma (k3/k5)
__device__ __forceinline__ void mma16816h(float* c, const uint32_t* a, const uint32_t* b) {
    asm volatile(
        "mma.sync.aligned.m16n8k16.row.col.f32.f16.f16.f32 "
        "{%0,%1,%2,%3}, {%4,%5,%6,%7}, {%8,%9}, {%0,%1,%2,%3};"
        : "+f"(c[0]), "+f"(c[1]), "+f"(c[2]), "+f"(c[3])
        : "r"(a[0]), "r"(a[1]), "r"(a[2]), "r"(a[3]), "r"(b[0]), "r"(b[1]));
}
#define CP_ASYNC16(dst, src) \
    asm volatile("cp.async.cg.shared.global [%0], [%1], 16;" :: "r"(dst), "l"(src))
#define CP_COMMIT() asm volatile("cp.async.commit_group;" ::: "memory")
#define CP_WAIT(n)  asm volatile("cp.async.wait_group %0;" :: "n"(n) : "memory")

// split float pair -> bf16 hi/lo packed words
__device__ __forceinline__ void split2(float a, float b, uint32_t& hi, uint32_t& lo) {
    __nv_bfloat162 hp = __floats2bfloat162_rn(a, b);
    float2 hf = __bfloat1622float2(hp);
    __nv_bfloat162 lp = __floats2bfloat162_rn(a - hf.x, b - hf.y);
    hi = *reinterpret_cast<uint32_t*>(&hp);
    lo = *reinterpret_cast<uint32_t*>(&lp);
}
// split float pair -> fp16 hi/lo packed words
__device__ __forceinline__ void split2h(float a, float b, uint32_t& hi, uint32_t& lo) {
    __half2 hp = __floats2half2_rn(a, b);
    float2 hf = __half22float2(hp);
    __half2 lp = __floats2half2_rn(a - hf.x, b - hf.y);
    hi = *reinterpret_cast<uint32_t*>(&hp);
    lo = *reinterpret_cast<uint32_t*>(&lp);
}
__device__ __forceinline__ uint32_t pk_h2(float a, float b) {
    __half2 hp = __floats2half2_rn(a, b);
    return *reinterpret_cast<uint32_t*>(&hp);
}

// ---------------- KWS: W[h][f][d] -> WcatT[c][f] bf16 hi/lo ----------------
__global__ __launch_bounds__(256) void kws_split(const float* __restrict__ W) {
    int idx = blockIdx.x*256 + threadIdx.x;      // 0..16383 = c*32 + kg
    int c = idx >> 5, kg = idx & 31;
    int h = c >> 6, d = c & 63;
    float v[4];
    #pragma unroll
    for (int q = 0; q < 4; q++)
        v[q] = W[h*(FF*DD) + (kg*4 + q)*DD + d];
    uint32_t h0, l0, h1, l1;
    split2(v[0], v[1], h0, l0);
    split2(v[2], v[3], h1, l1);
    *reinterpret_cast<uint2*>(g_WT_hi + (size_t)c*FF + kg*4) = make_uint2(h0, h1);
    *reinterpret_cast<uint2*>(g_WT_lo + (size_t)c*FF + kg*4) = make_uint2(l0, l1);
}

// ---------------- K4W: Wo[k][c] -> WoT[c][k] bf16 hi/lo ----------------
__global__ __launch_bounds__(256) void k4w_split(const float* __restrict__ Wo) {
    int idx = blockIdx.x*256 + threadIdx.x;      // 0..4095 = c*128 + kg
    int c = idx >> 7, kg = idx & 127;
    float v[4];
    #pragma unroll
    for (int q = 0; q < 4; q++)
        v[q] = Wo[(kg*4 + q)*CC + c];
    uint32_t h0, l0, h1, l1;
    split2(v[0], v[1], h0, l0);
    split2(v[2], v[3], h1, l1);
    *reinterpret_cast<uint2*>(g_WoT_hi + (size_t)c*HD + kg*4) = make_uint2(h0, h1);
    *reinterpret_cast<uint2*>(g_WoT_lo + (size_t)c*HD + kg*4) = make_uint2(l0, l1);
}

// ---------------- K0: adjacency -> transposed bitmask (int4 + shfl-or) ----------------
__global__ __launch_bounds__(256) void k0_mask(const int* __restrict__ adj) {
    int gw = (blockIdx.x * 256 + threadIdx.x) >> 5;  // 0..8191 = b*2048+row
    int lane = threadIdx.x & 31;
    int b = gw >> 11, row = gw & 2047;
    const int4* ar4 = reinterpret_cast<const int4*>(adj + (size_t)gw * NN);
    int lg = lane & 7, wsel = lane >> 3;
    #pragma unroll 4
    for (int it = 0; it < 16; it++) {
        int4 v = ar4[it*32 + lane];
        unsigned nib = (v.x > 0 ? 1u : 0u) | (v.y > 0 ? 2u : 0u)
                     | (v.z > 0 ? 4u : 0u) | (v.w > 0 ? 8u : 0u);
        unsigned part = nib << (lg * 4);
        part |= __shfl_xor_sync(0xffffffffu, part, 1);
        part |= __shfl_xor_sync(0xffffffffu, part, 2);
        part |= __shfl_xor_sync(0xffffffffu, part, 4);
        if (lg == 0)
            g_adjbT[((b<<6) + it*4 + wsel)*NN + row] = part;
    }
}

// ---------------- K1: Wh = x @ Wcat (bf16 HMMA); fused WhT(fp16) + f1/f2 ----------------
#define K1_SMEM 55296
__global__ __launch_bounds__(256) void k1_hmma(const float* __restrict__ x,
                                               const float* __restrict__ a1,
                                               const float* __restrict__ a2) {
    extern __shared__ __align__(16) char smem[];
    uint32_t sb = smem_u32(smem);
    int t = threadIdx.x;
    int warp = t >> 5, lane = t & 31;
    int h = blockIdx.x;
    int m0 = blockIdx.y * 128;
    int b = m0 >> 11, nd0 = m0 & 2047;
    int bh = b*8 + h;

    float acc[8][4];
    #pragma unroll
    for (int n=0;n<8;n++){ acc[n][0]=0.f; acc[n][1]=0.f; acc[n][2]=0.f; acc[n][3]=0.f; }

    uint32_t aRow = (uint32_t)(warp*16 + (lane & 15)) * 144u + ((lane & 16) ? 16u : 0u);
    uint32_t bAddr = sb + 36864u + ((lane & 16) ? 9216u : 0u)
                   + (uint32_t)(lane & 7) * 144u + (uint32_t)(lane & 8) * 2u;

    int rA = t >> 1, hA = t & 1;
    int rB = t >> 2, cB = t & 3;

    #pragma unroll
    for (int kt = 0; kt < 2; kt++) {
        if (kt) __syncthreads();
        int k0 = kt * 64;
        {
            const float4* px = reinterpret_cast<const float4*>(
                x + (size_t)(m0 + rA)*FF + k0 + hA*32);
            uint32_t off = (uint32_t)rA*144u + (uint32_t)hA*64u;
            #pragma unroll
            for (int q = 0; q < 4; q++) {
                float4 v0 = px[q*2], v1 = px[q*2+1];
                uint32_t hw[4], lw[4];
                split2(v0.x, v0.y, hw[0], lw[0]);
                split2(v0.z, v0.w, hw[1], lw[1]);
                split2(v1.x, v1.y, hw[2], lw[2]);
                split2(v1.z, v1.w, hw[3], lw[3]);
                *reinterpret_cast<uint4*>(smem + off + q*16) =
                    *reinterpret_cast<uint4*>(hw);
                *reinterpret_cast<uint4*>(smem + 18432 + off + q*16) =
                    *reinterpret_cast<uint4*>(lw);
            }
        }
        {
            const __nv_bfloat16* ph = g_WT_hi + (size_t)(h*64 + rB)*FF + k0 + cB*16;
            const __nv_bfloat16* pl = g_WT_lo + (size_t)(h*64 + rB)*FF + k0 + cB*16;
            uint32_t off = (uint32_t)rB*144u + (uint32_t)cB*32u;
            #pragma unroll
            for (int q = 0; q < 2; q++) {
                *reinterpret_cast<uint4*>(smem + 36864 + off + q*16) =
                    *reinterpret_cast<const uint4*>(ph + q*8);
                *reinterpret_cast<uint4*>(smem + 46080 + off + q*16) =
                    *reinterpret_cast<const uint4*>(pl + q*8);
            }
        }
        __syncthreads();
        #pragma unroll
        for (int k = 0; k < 4; k++) {
            uint32_t kb = (uint32_t)k * 32u;
            uint32_t ah[4], al[4];
            ldsm_x4(ah, sb + 0     + aRow + kb);
            ldsm_x4(al, sb + 18432 + aRow + kb);
            #pragma unroll
            for (int n = 0; n < 8; n++) {
                uint32_t bf[4];
                ldsm_x4(bf, bAddr + (uint32_t)n*(8u*144u) + kb);
                mma16816(acc[n], ah, bf);
                mma16816(acc[n], ah, bf + 2);
                mma16816(acc[n], al, bf);
            }
        }
    }
    // ---- fused epilogue: transpose, f1/f2, WhT fp16 hi/lo ----
    __syncthreads();
    float* ts = reinterpret_cast<float*>(smem);          // [64 d][132]
    float* a1s = reinterpret_cast<float*>(smem + 33792);
    float* a2s = reinterpret_cast<float*>(smem + 34048);
    if (t < 64) { a1s[t] = a1[h*DD + t]; a2s[t] = a2[h*DD + t]; }
    int r0 = warp*16 + (lane >> 2);
    int r1 = r0 + 8;
    #pragma unroll
    for (int n = 0; n < 8; n++) {
        int c = n*8 + (lane & 3)*2;
        ts[c*132 + r0]     = acc[n][0];
        ts[(c+1)*132 + r0] = acc[n][1];
        ts[c*132 + r1]     = acc[n][2];
        ts[(c+1)*132 + r1] = acc[n][3];
    }
    __syncthreads();
    if (t < 128) {
        float f1 = 0.f, f2 = 0.f;
        #pragma unroll
        for (int d = 0; d < 64; d++) {
            float wv = ts[d*132 + t];
            f1 += wv * a1s[d];
            f2 += wv * a2s[d];
        }
        int tid = bh*NN + nd0 + t;
        g_F1R[tid] = make_float2(f1, expf(-0.8f*f1));
        g_F2C[tid] = make_float4(f2, expf(f2), expf(0.2f*f2), 0.f);
    }
    #pragma unroll
    for (int q = 0; q < 4; q++) {
        int task = t + q*256;
        int d = task >> 4, nc = task & 15;
        uint32_t hiw[4], low[4];
        #pragma unroll
        for (int p = 0; p < 4; p++)
            split2h(ts[d*132 + nc*8 + 2*p], ts[d*132 + nc*8 + 2*p + 1], hiw[p], low[p]);
        size_t off = ((size_t)bh*DD + d)*NN + nd0 + nc*8;
        *reinterpret_cast<uint4*>(g_WhT_hi + off) = *reinterpret_cast<uint4*>(hiw);
        *reinterpret_cast<uint4*>(g_WhT_lo + off) = *reinterpret_cast<uint4*>(low);
    }
}

// ---------------- K3: layer-1 attention, fp16 2-product HMMA + cp.async ----------------
// smem: Ah @0 (128x72 fp16, 18432); B buf0 hi @18432 lo @27648;
// buf1 hi @36864 lo @46080; zp @55296 (1KB); f2s @56320 (2KB). Total 58368.
#define K3_SMEM 58368
__global__ __launch_bounds__(256) void k3_attn1_mma() {
    extern __shared__ __align__(16) char smem[];
    char* Ahp = smem;
    float* zp = reinterpret_cast<float*>(smem + 55296);
    float4* f2s = reinterpret_cast<float4*>(smem + 56320);
    uint32_t sb = smem_u32(smem);

    int t = threadIdx.x;
    int warp = t >> 5, lane = t & 31;
    int i0 = blockIdx.x * 128;
    int h = blockIdx.y, b = blockIdx.z;
    int bh = (b<<3) + h;

    int i = t & 127, jh = t >> 7;
    float2 f1r = g_F1R[bh*NN + i0 + i];
    float negf1 = -f1r.x, rmul = f1r.y;
    float zacc = 0.f;
    const __half* bhsrc = g_WhT_hi + (size_t)bh*DD*NN;
    const __half* blsrc = g_WhT_lo + (size_t)bh*DD*NN;
    const float4* f2g = reinterpret_cast<const float4*>(&g_F2C[bh*NN]);

    float acc[8][4];
    #pragma unroll
    for (int n=0;n<8;n++){ acc[n][0]=0.f; acc[n][1]=0.f; acc[n][2]=0.f; acc[n][3]=0.f; }

    int m0 = warp * 16;
    uint32_t aRow = (uint32_t)(m0 + (lane & 15)) * 144u + ((lane & 16) ? 16u : 0u);
    uint32_t bFrag = ((lane & 16) ? 9216u : 0u)
                   + (uint32_t)(lane & 7) * 144u + (uint32_t)(lane & 8) * 2u;

    int dB = t >> 2, cB = t & 3;
    const __half* pBh = bhsrc + (size_t)dB*NN + cB*16;
    const __half* pBl = blsrc + (size_t)dB*NN + cB*16;
    uint32_t bStOff = (uint32_t)dB*144u + (uint32_t)cB*32u;

    {
        uint32_t d0 = sb + 18432u + bStOff;
        CP_ASYNC16(d0,          pBh);
        CP_ASYNC16(d0 + 16,     pBh + 8);
        CP_ASYNC16(d0 + 9216u,      pBl);
        CP_ASYNC16(d0 + 9216u + 16, pBl + 8);
        CP_COMMIT();
    }
    if (t < 64) f2s[t] = __ldg(&f2g[t]);
    __syncthreads();

    for (int jt = 0; jt < 32; jt++) {
        int buf = jt & 1;
        if (jt) __syncthreads();
        if (jt < 31) {
            uint32_t dN = sb + 18432u + (uint32_t)(buf^1)*18432u + bStOff;
            const __half* sh = pBh + (jt+1)*64;
            const __half* sl = pBl + (jt+1)*64;
            CP_ASYNC16(dN,          sh);
            CP_ASYNC16(dN + 16,     sh + 8);
            CP_ASYNC16(dN + 9216u,      sl);
            CP_ASYNC16(dN + 9216u + 16, sl + 8);
            CP_COMMIT();
        }
        // weight phase -> A (plain fp16)
        unsigned bw = g_adjbT[((b<<6) + jt*2 + jh)*NN + i0 + i];
        const float4* f2p = &f2s[(size_t)buf*64 + jh*32];
        #pragma unroll
        for (int oct = 0; oct < 4; oct++) {
            float w[8];
            #pragma unroll
            for (int e = 0; e < 8; e++) {
                float4 fc = f2p[oct*8 + e];
                float w1 = (fc.x > negf1) ? fc.y : rmul*fc.z;
                w[e] = ((bw >> (oct*8 + e)) & 1u) ? w1 : 0.f;
                zacc += w[e];
            }
            uint32_t hw[4];
            #pragma unroll
            for (int p = 0; p < 4; p++)
                hw[p] = pk_h2(w[2*p], w[2*p+1]);
            uint32_t off = (uint32_t)i*144u + (uint32_t)(jh*64 + oct*16);
            *reinterpret_cast<uint4*>(Ahp + off) = *reinterpret_cast<uint4*>(hw);
        }
        if (jt < 31 && t < 64)
            f2s[(size_t)(buf^1)*64 + t] = __ldg(&f2g[(jt+1)*64 + t]);
        if (jt < 31) { CP_WAIT(1); } else { CP_WAIT(0); }
        __syncthreads();
        // ---- MMA(jt): 2 products (Ah*Bh + Ah*Bl) ----
        uint32_t bBase = sb + 18432u + (uint32_t)buf*18432u + bFrag;
        #pragma unroll
        for (int k = 0; k < 4; k++) {
            uint32_t kb = (uint32_t)k * 32u;
            uint32_t ah[4];
            ldsm_x4(ah, sb + aRow + kb);
            #pragma unroll
            for (int n = 0; n < 8; n++) {
                uint32_t bf[4];
                ldsm_x4(bf, bBase + (uint32_t)n*(8u*144u) + kb);
                mma16816h(acc[n], ah, bf);
                mma16816h(acc[n], ah, bf + 2);
            }
        }
    }
    zp[jh*128 + i] = zacc;
    __syncthreads();
    int r0 = m0 + (lane >> 2);
    int r1 = r0 + 8;
    float z0 = zp[r0] + zp[128 + r0];   if (z0 < 1e-30f) z0 = 1.f;
    float z1 = zp[r1] + zp[128 + r1];   if (z1 < 1e-30f) z1 = 1.f;
    float invz0 = 1.f / z0, invz1 = 1.f / z1;
    size_t base0 = (size_t)(b*NN + i0 + r0)*HD + h*DD + (lane & 3)*2;
    size_t base1 = (size_t)(b*NN + i0 + r1)*HD + h*DD + (lane & 3)*2;
    #pragma unroll
    for (int n = 0; n < 8; n++) {
        float v0 = acc[n][0] * invz0, v1 = acc[n][1] * invz0;
        float v2 = acc[n][2] * invz1, v3 = acc[n][3] * invz1;
        v0 = v0 > 0.f ? v0 : expm1f(v0);
        v1 = v1 > 0.f ? v1 : expm1f(v1);
        v2 = v2 > 0.f ? v2 : expm1f(v2);
        v3 = v3 > 0.f ? v3 : expm1f(v3);
        uint32_t h0, l0, h1, l1;
        split2(v0, v1, h0, l0);
        split2(v2, v3, h1, l1);
        *reinterpret_cast<uint32_t*>(g_h_hi + base0 + n*8) = h0;
        *reinterpret_cast<uint32_t*>(g_h_lo + base0 + n*8) = l0;
        *reinterpret_cast<uint32_t*>(g_h_hi + base1 + n*8) = h1;
        *reinterpret_cast<uint32_t*>(g_h_lo + base1 + n*8) = l1;
    }
}

// ---------------- K4: Wh2 = h @ Wo (bf16 HMMA); fused Wh2T(fp16) + g1/g2 ----------------
__global__ __launch_bounds__(256) void k4_hmma(const float* __restrict__ ao1,
                                               const float* __restrict__ ao2) {
    __shared__ __align__(16) char Ahp[64*144];
    __shared__ __align__(16) char Alp[64*144];
    __shared__ __align__(16) char Bs[2*32*144];   // hi @0, lo @4608
    uint32_t sbA_h = smem_u32(Ahp), sbA_l = smem_u32(Alp);
    uint32_t sbB = smem_u32(Bs);

    int t = threadIdx.x;
    int warp = t >> 5, lane = t & 31;
    int m0 = blockIdx.x * 64;
    int b = m0 >> 11, nd0 = m0 & 2047;
    int mt = warp >> 1, nh = warp & 1;

    float acc[2][4];
    acc[0][0]=0.f; acc[0][1]=0.f; acc[0][2]=0.f; acc[0][3]=0.f;
    acc[1][0]=0.f; acc[1][1]=0.f; acc[1][2]=0.f; acc[1][3]=0.f;

    uint32_t aRow = (uint32_t)(mt*16 + (lane & 15)) * 144u + ((lane & 16) ? 16u : 0u);
    uint32_t bAddr = sbB + ((lane & 16) ? 4608u : 0u)
                   + (uint32_t)(lane & 7) * 144u + (uint32_t)(lane & 8) * 2u;

    int rA = t >> 2, cA = t & 3;
    int rB = t >> 3, cB = t & 7;

    #pragma unroll
    for (int kt = 0; kt < 8; kt++) {
        if (kt) __syncthreads();
        int k0 = kt * 64;
        {
            const __nv_bfloat16* ph = g_h_hi + (size_t)(m0 + rA)*HD + k0 + cA*16;
            const __nv_bfloat16* pl = g_h_lo + (size_t)(m0 + rA)*HD + k0 + cA*16;
            uint32_t off = (uint32_t)rA*144u + (uint32_t)cA*32u;
            #pragma unroll
            for (int q = 0; q < 2; q++) {
                *reinterpret_cast<uint4*>(Ahp + off + q*16) =
                    *reinterpret_cast<const uint4*>(ph + q*8);
                *reinterpret_cast<uint4*>(Alp + off + q*16) =
                    *reinterpret_cast<const uint4*>(pl + q*8);
            }
        }
        {
            const __nv_bfloat16* ph = g_WoT_hi + (size_t)rB*HD + k0 + cB*8;
            const __nv_bfloat16* pl = g_WoT_lo + (size_t)rB*HD + k0 + cB*8;
            uint32_t off = (uint32_t)rB*144u + (uint32_t)cB*16u;
            *reinterpret_cast<uint4*>(Bs + off)         = *reinterpret_cast<const uint4*>(ph);
            *reinterpret_cast<uint4*>(Bs + 4608 + off)  = *reinterpret_cast<const uint4*>(pl);
        }
        __syncthreads();
        #pragma unroll
        for (int k = 0; k < 4; k++) {
            uint32_t kb = (uint32_t)k * 32u;
            uint32_t ah[4], al[4];
            ldsm_x4(ah, sbA_h + aRow + kb);
            ldsm_x4(al, sbA_l + aRow + kb);
            #pragma unroll
            for (int n = 0; n < 2; n++) {
                uint32_t bf[4];
                ldsm_x4(bf, bAddr + (uint32_t)(nh*2 + n)*(8u*144u) + kb);
                mma16816(acc[n], ah, bf);
                mma16816(acc[n], ah, bf + 2);
                mma16816(acc[n], al, bf);
            }
        }
    }
    // ---- fused epilogue: transpose tile, g1/g2, Wh2T fp16 hi/lo ----
    __syncthreads();
    float* ts2 = reinterpret_cast<float*>(Ahp);          // [32 c][68]
    float* ao1s = reinterpret_cast<float*>(Alp);         // 32
    float* ao2s = reinterpret_cast<float*>(Alp + 128);   // 32
    if (t < 32) { ao1s[t] = ao1[t]; ao2s[t] = ao2[t]; }
    int r0 = mt*16 + (lane >> 2);
    int r1 = r0 + 8;
    #pragma unroll
    for (int n = 0; n < 2; n++) {
        int c = nh*16 + n*8 + (lane & 3)*2;
        ts2[c*68 + r0]     = acc[n][0];
        ts2[(c+1)*68 + r0] = acc[n][1];
        ts2[c*68 + r1]     = acc[n][2];
        ts2[(c+1)*68 + r1] = acc[n][3];
    }
    __syncthreads();
    if (t < 64) {
        float g1 = 0.f, g2 = 0.f;
        #pragma unroll
        for (int c = 0; c < 32; c++) {
            float wv = ts2[c*68 + t];
            g1 += wv * ao1s[c];
            g2 += wv * ao2s[c];
        }
        int tid = b*NN + nd0 + t;
        g_G1R[tid] = make_float2(g1, expf(-0.8f*g1));
        g_G2C[tid] = make_float4(g2, expf(g2), expf(0.2f*g2), 0.f);
    }
    {
        int c = t >> 3, nc = t & 7;
        uint32_t hiw[4], low[4];
        #pragma unroll
        for (int p = 0; p < 4; p++)
            split2h(ts2[c*68 + nc*8 + 2*p], ts2[c*68 + nc*8 + 2*p + 1], hiw[p], low[p]);
        size_t off = ((size_t)(b*CC) + c)*NN + nd0 + nc*8;
        *reinterpret_cast<uint4*>(g_Wh2T_hi + off) = *reinterpret_cast<uint4*>(hiw);
        *reinterpret_cast<uint4*>(g_Wh2T_lo + off) = *reinterpret_cast<uint4*>(low);
    }
}

// ---------------- K5: layer-2 attention, fp16 2-product HMMA ----------------
__global__ __launch_bounds__(256) void k5_attn2_mma(float* __restrict__ out) {
    __shared__ __align__(16) char Ahp[64*144];    // w fp16 [64][72]
    __shared__ __align__(16) char Bs[2*32*144];   // Wh2T fp16: hi @0, lo @4608
    __shared__ float zp[4][64];
    __shared__ __align__(16) float4 g2s[128];     // staged g2c, 2 bufs of 64
    uint32_t sbA = smem_u32(Ahp);
    uint32_t sbB = smem_u32(Bs);

    int t = threadIdx.x;
    int warp = t >> 5, lane = t & 31;
    int i0 = blockIdx.x * 64;
    int b = blockIdx.y;

    int i = t & 63, jq = t >> 6;
    float2 g1r = g_G1R[b*NN + i0 + i];
    float negg = -g1r.x, rmul = g1r.y;
    float zacc = 0.f;
    const __half* bhsrc = g_Wh2T_hi + (size_t)(b*CC)*NN;
    const __half* blsrc = g_Wh2T_lo + (size_t)(b*CC)*NN;
    const float4* g2g = reinterpret_cast<const float4*>(&g_G2C[b*NN]);

    int mt = warp >> 1, nh = warp & 1;
    float acc[2][4];
    acc[0][0]=0.f; acc[0][1]=0.f; acc[0][2]=0.f; acc[0][3]=0.f;
    acc[1][0]=0.f; acc[1][1]=0.f; acc[1][2]=0.f; acc[1][3]=0.f;

    uint32_t aRow = (uint32_t)(mt*16 + (lane & 15)) * 144u + ((lane & 16) ? 16u : 0u);
    uint32_t bAddr = sbB + ((lane & 16) ? 4608u : 0u)
                   + (uint32_t)(lane & 7) * 144u + (uint32_t)(lane & 8) * 2u;

    if (t < 64) g2s[t] = __ldg(&g2g[t]);
    __syncthreads();

    for (int jt = 0; jt < 32; jt++) {
        int buf = jt & 1;
        if (jt) __syncthreads();
        int j0 = jt * 64;
        unsigned bwf = g_adjbT[((b<<6) + jt*2 + (jq>>1))*NN + i0 + i];
        unsigned bw = (bwf >> ((jq & 1)*16)) & 0xFFFFu;
        const float4* g2p = &g2s[(size_t)buf*64 + jq*16];
        float w[16];
        #pragma unroll
        for (int e = 0; e < 16; e++) {
            float4 fc = g2p[e];
            float w1 = (fc.x > negg) ? fc.y : rmul*fc.z;
            w[e] = ((bw >> e) & 1u) ? w1 : 0.f;
            zacc += w[e];
        }
        uint32_t hw[8];
        #pragma unroll
        for (int p = 0; p < 8; p++)
            hw[p] = pk_h2(w[2*p], w[2*p+1]);
        uint32_t off = (uint32_t)i*144u + (uint32_t)jq*32u;
        *reinterpret_cast<uint4*>(Ahp + off)      = *reinterpret_cast<uint4*>(&hw[0]);
        *reinterpret_cast<uint4*>(Ahp + off + 16) = *reinterpret_cast<uint4*>(&hw[4]);
        {
            int c = t >> 3, ch = t & 7;
            uint4 vh = *reinterpret_cast<const uint4*>(bhsrc + (size_t)c*NN + j0 + ch*8);
            uint4 vl = *reinterpret_cast<const uint4*>(blsrc + (size_t)c*NN + j0 + ch*8);
            uint32_t boff = (uint32_t)c*144u + (uint32_t)ch*16u;
            *reinterpret_cast<uint4*>(Bs + boff)        = vh;
            *reinterpret_cast<uint4*>(Bs + 4608 + boff) = vl;
        }
        if (jt < 31 && t < 64)
            g2s[(size_t)(buf^1)*64 + t] = __ldg(&g2g[(jt+1)*64 + t]);
        __syncthreads();
        #pragma unroll
        for (int k = 0; k < 4; k++) {
            uint32_t kb = (uint32_t)k * 32u;
            uint32_t ah[4];
            ldsm_x4(ah, sbA + aRow + kb);
            #pragma unroll
            for (int n = 0; n < 2; n++) {
                uint32_t bf[4];
                ldsm_x4(bf, bAddr + (uint32_t)(nh*2 + n)*(8u*144u) + kb);
                mma16816h(acc[n], ah, bf);
                mma16816h(acc[n], ah, bf + 2);
            }
        }
    }
    zp[jq][i] = zacc;
    __syncthreads();
    int r0 = mt*16 + (lane >> 2);
    int r1 = r0 + 8;
    float z0 = zp[0][r0] + zp[1][r0] + zp[2][r0] + zp[3][r0];
    float z1 = zp[0][r1] + zp[1][r1] + zp[2][r1] + zp[3][r1];
    if (z0 < 1e-30f) z0 = 1.f;
    if (z1 < 1e-30f) z1 = 1.f;
    float invz0 = 1.f / z0, invz1 = 1.f / z1;
    #pragma unroll
    for (int n = 0; n < 2; n++) {
        int c0 = nh*16 + n*8 + (lane & 3)*2;
        float2 o0 = make_float2(acc[n][0]*invz0, acc[n][1]*invz0);
        float2 o1 = make_float2(acc[n][2]*invz1, acc[n][3]*invz1);
        *reinterpret_cast<float2*>(&out[(size_t)(b*NN + i0 + r0)*CC + c0]) = o0;
        *reinterpret_cast<float2*>(&out[(size_t)(b*NN + i0 + r1)*CC + c0]) = o1;
    }
}

extern "C" void kernel_launch(void* const* d_in, const int* in_sizes, int n_in,
                              void* d_out, int out_size) {
    const float* x   = (const float*)d_in[0];
    const int*   adj = (const int*)  d_in[1];
    const float* W   = (const float*)d_in[2];
    const float* a1  = (const float*)d_in[3];
    const float* a2  = (const float*)d_in[4];
    const float* Wo  = (const float*)d_in[5];
    const float* ao1 = (const float*)d_in[6];
    const float* ao2 = (const float*)d_in[7];
    float* out = (float*)d_out;

    cudaFuncSetAttribute(k3_attn1_mma,
                         cudaFuncAttributeMaxDynamicSharedMemorySize, K3_SMEM);
    cudaFuncSetAttribute(k1_hmma,
                         cudaFuncAttributeMaxDynamicSharedMemorySize, K1_SMEM);

    kws_split<<<64, 256>>>(W);                        // W -> WcatT bf16 hi/lo
    k4w_split<<<16, 256>>>(Wo);                       // Wo -> WoT bf16 hi/lo
    k0_mask<<<1024, 256>>>(adj);                      // adj -> transposed bitmask
    k1_hmma<<<dim3(8, 64), 256, K1_SMEM>>>(x, a1, a2);// Wh + WhT fp16 + f1/f2
    k3_attn1_mma<<<dim3(16, 8, 4), 256, K3_SMEM>>>(); // layer-1 attn (fp16 2-prod)
    k4_hmma<<<128, 256>>>(ao1, ao2);                  // Wh2T fp16 + g1/g2
    k5_attn2_mma<<<dim3(32, 4), 256>>>(out);          // layer-2 attn (fp16 2-prod)
}

// round 13
// speedup vs baseline: 2.5171x; 1.3299x over previous
#include <cuda_runtime.h>
#include <cuda_bf16.h>
#include <cuda_fp16.h>
#include <math.h>
#include <stdint.h>

// GAT forward, B=4 N=2048 F=128 H=8 D=64 C=32.
// Softmax trick: exp(lrelu(f1_i+f2_j))/exp(f1_i) = (f1_i+f2_j>0) ? exp(f2_j)
//   : exp(-0.8 f1_i)*exp(0.2 f2_j); exp(f1_i) cancels in softmax.
// R13: attention layers on single-product plain-fp16 HMMA (A = fp16 weights,
// B = fp16 WhT/Wh2T); per-element rounding RMS-cancels over ~1024 terms
// (measured 6e-5 for the A side in R12). k1/k4 stay bf16 3-product.

#define BB 4
#define NN 2048
#define FF 128
#define DD 64
#define HH 8
#define CC 32
#define HD (HH*DD)

__device__ __align__(16) float2 g_F1R[BB*HH*NN];     // (f1, exp(-0.8 f1))
__device__ __align__(16) float4 g_F2C[BB*HH*NN];     // (f2, exp(f2), exp(0.2 f2), 0)
__device__ __align__(16) float2 g_G1R[BB*NN];
__device__ __align__(16) float4 g_G2C[BB*NN];
__device__ unsigned g_adjbT[BB*64*NN];               // bitmask, TRANSPOSED [b][word][row]
__device__ __align__(16) __half g_WhT[BB*HH*DD*NN];      // WhT fp16 [bh][d][j]
__device__ __align__(16) __half g_Wh2T[BB*CC*NN];        // Wh2T fp16 [b][c][j]
__device__ __align__(16) __nv_bfloat16 g_WT_hi[HH*DD*FF];  // WcatT [c][f] bf16 hi
__device__ __align__(16) __nv_bfloat16 g_WT_lo[HH*DD*FF];
__device__ __align__(16) __nv_bfloat16 g_h_hi[BB*NN*HD];   // h bf16 hi [bn][hd]
__device__ __align__(16) __nv_bfloat16 g_h_lo[BB*NN*HD];
__device__ __align__(16) __nv_bfloat16 g_WoT_hi[CC*HD];    // WoT [c][k] bf16 hi
__device__ __align__(16) __nv_bfloat16 g_WoT_lo[CC*HD];

__device__ __forceinline__ uint32_t smem_u32(const void* p) {
    uint32_t a;
    asm("{ .reg .u64 tmp; cvta.to.shared.u64 tmp, %1; cvt.u32.u64 %0, tmp; }"
        : "=r"(a) : "l"(p));
    return a;
}
__device__ __forceinline__ void ldsm_x4(uint32_t* r, uint32_t addr) {
    asm volatile("ldmatrix.sync.aligned.m8n8.x4.shared.b16 {%0,%1,%2,%3}, [%4];"
        : "=r"(r[0]), "=r"(r[1]), "=r"(r[2]), "=r"(r[3]) : "r"(addr));
}
// bf16 mma (k1/k4)
__device__ __forceinline__ void mma16816(float* c, const uint32_t* a, const uint32_t* b) {
    asm volatile(
        "mma.sync.aligned.m16n8k16.row.col.f32.bf16.bf16.f32 "
        "{%0,%1,%2,%3}, {%4,%5,%6,%7}, {%8,%9}, {%0,%1,%2,%3};"
        : "+f"(c[0]), "+f"(c[1]), "+f"(c[2]), "+f"(c[3])
        : "r"(a[0]), "r"(a[1]), "r"(a[2]), "r"(a[3]), "r"(b[0]), "r"(b[1]));
}
// fp16 mma (k3/k5)
__device__ __forceinline__ void mma16816h(float* c, const uint32_t* a, const uint32_t* b) {
    asm volatile(
        "mma.sync.aligned.m16n8k16.row.col.f32.f16.f16.f32 "
        "{%0,%1,%2,%3}, {%4,%5,%6,%7}, {%8,%9}, {%0,%1,%2,%3};"
        : "+f"(c[0]), "+f"(c[1]), "+f"(c[2]), "+f"(c[3])
        : "r"(a[0]), "r"(a[1]), "r"(a[2]), "r"(a[3]), "r"(b[0]), "r"(b[1]));
}
#define CP_ASYNC16(dst, src) \
    asm volatile("cp.async.cg.shared.global [%0], [%1], 16;" :: "r"(dst), "l"(src))
#define CP_COMMIT() asm volatile("cp.async.commit_group;" ::: "memory")
#define CP_WAIT(n)  asm volatile("cp.async.wait_group %0;" :: "n"(n) : "memory")

// split float pair -> bf16 hi/lo packed words
__device__ __forceinline__ void split2(float a, float b, uint32_t& hi, uint32_t& lo) {
    __nv_bfloat162 hp = __floats2bfloat162_rn(a, b);
    float2 hf = __bfloat1622float2(hp);
    __nv_bfloat162 lp = __floats2bfloat162_rn(a - hf.x, b - hf.y);
    hi = *reinterpret_cast<uint32_t*>(&hp);
    lo = *reinterpret_cast<uint32_t*>(&lp);
}
__device__ __forceinline__ uint32_t pk_h2(float a, float b) {
    __half2 hp = __floats2half2_rn(a, b);
    return *reinterpret_cast<uint32_t*>(&hp);
}

// ---------------- KWS: W[h][f][d] -> WcatT[c][f] bf16 hi/lo ----------------
__global__ __launch_bounds__(256) void kws_split(const float* __restrict__ W) {
    int idx = blockIdx.x*256 + threadIdx.x;      // 0..16383 = c*32 + kg
    int c = idx >> 5, kg = idx & 31;
    int h = c >> 6, d = c & 63;
    float v[4];
    #pragma unroll
    for (int q = 0; q < 4; q++)
        v[q] = W[h*(FF*DD) + (kg*4 + q)*DD + d];
    uint32_t h0, l0, h1, l1;
    split2(v[0], v[1], h0, l0);
    split2(v[2], v[3], h1, l1);
    *reinterpret_cast<uint2*>(g_WT_hi + (size_t)c*FF + kg*4) = make_uint2(h0, h1);
    *reinterpret_cast<uint2*>(g_WT_lo + (size_t)c*FF + kg*4) = make_uint2(l0, l1);
}

// ---------------- K4W: Wo[k][c] -> WoT[c][k] bf16 hi/lo ----------------
__global__ __launch_bounds__(256) void k4w_split(const float* __restrict__ Wo) {
    int idx = blockIdx.x*256 + threadIdx.x;      // 0..4095 = c*128 + kg
    int c = idx >> 7, kg = idx & 127;
    float v[4];
    #pragma unroll
    for (int q = 0; q < 4; q++)
        v[q] = Wo[(kg*4 + q)*CC + c];
    uint32_t h0, l0, h1, l1;
    split2(v[0], v[1], h0, l0);
    split2(v[2], v[3], h1, l1);
    *reinterpret_cast<uint2*>(g_WoT_hi + (size_t)c*HD + kg*4) = make_uint2(h0, h1);
    *reinterpret_cast<uint2*>(g_WoT_lo + (size_t)c*HD + kg*4) = make_uint2(l0, l1);
}

// ---------------- K0: adjacency -> transposed bitmask (int4 + shfl-or) ----------------
__global__ __launch_bounds__(256) void k0_mask(const int* __restrict__ adj) {
    int gw = (blockIdx.x * 256 + threadIdx.x) >> 5;  // 0..8191 = b*2048+row
    int lane = threadIdx.x & 31;
    int b = gw >> 11, row = gw & 2047;
    const int4* ar4 = reinterpret_cast<const int4*>(adj + (size_t)gw * NN);
    int lg = lane & 7, wsel = lane >> 3;
    #pragma unroll 4
    for (int it = 0; it < 16; it++) {
        int4 v = ar4[it*32 + lane];
        unsigned nib = (v.x > 0 ? 1u : 0u) | (v.y > 0 ? 2u : 0u)
                     | (v.z > 0 ? 4u : 0u) | (v.w > 0 ? 8u : 0u);
        unsigned part = nib << (lg * 4);
        part |= __shfl_xor_sync(0xffffffffu, part, 1);
        part |= __shfl_xor_sync(0xffffffffu, part, 2);
        part |= __shfl_xor_sync(0xffffffffu, part, 4);
        if (lg == 0)
            g_adjbT[((b<<6) + it*4 + wsel)*NN + row] = part;
    }
}

// ---------------- K1: Wh = x @ Wcat (bf16 HMMA); fused WhT(fp16) + f1/f2 ----------------
#define K1_SMEM 55296
__global__ __launch_bounds__(256) void k1_hmma(const float* __restrict__ x,
                                               const float* __restrict__ a1,
                                               const float* __restrict__ a2) {
    extern __shared__ __align__(16) char smem[];
    uint32_t sb = smem_u32(smem);
    int t = threadIdx.x;
    int warp = t >> 5, lane = t & 31;
    int h = blockIdx.x;
    int m0 = blockIdx.y * 128;
    int b = m0 >> 11, nd0 = m0 & 2047;
    int bh = b*8 + h;

    float acc[8][4];
    #pragma unroll
    for (int n=0;n<8;n++){ acc[n][0]=0.f; acc[n][1]=0.f; acc[n][2]=0.f; acc[n][3]=0.f; }

    uint32_t aRow = (uint32_t)(warp*16 + (lane & 15)) * 144u + ((lane & 16) ? 16u : 0u);
    uint32_t bAddr = sb + 36864u + ((lane & 16) ? 9216u : 0u)
                   + (uint32_t)(lane & 7) * 144u + (uint32_t)(lane & 8) * 2u;

    int rA = t >> 1, hA = t & 1;
    int rB = t >> 2, cB = t & 3;

    #pragma unroll
    for (int kt = 0; kt < 2; kt++) {
        if (kt) __syncthreads();
        int k0 = kt * 64;
        {
            const float4* px = reinterpret_cast<const float4*>(
                x + (size_t)(m0 + rA)*FF + k0 + hA*32);
            uint32_t off = (uint32_t)rA*144u + (uint32_t)hA*64u;
            #pragma unroll
            for (int q = 0; q < 4; q++) {
                float4 v0 = px[q*2], v1 = px[q*2+1];
                uint32_t hw[4], lw[4];
                split2(v0.x, v0.y, hw[0], lw[0]);
                split2(v0.z, v0.w, hw[1], lw[1]);
                split2(v1.x, v1.y, hw[2], lw[2]);
                split2(v1.z, v1.w, hw[3], lw[3]);
                *reinterpret_cast<uint4*>(smem + off + q*16) =
                    *reinterpret_cast<uint4*>(hw);
                *reinterpret_cast<uint4*>(smem + 18432 + off + q*16) =
                    *reinterpret_cast<uint4*>(lw);
            }
        }
        {
            const __nv_bfloat16* ph = g_WT_hi + (size_t)(h*64 + rB)*FF + k0 + cB*16;
            const __nv_bfloat16* pl = g_WT_lo + (size_t)(h*64 + rB)*FF + k0 + cB*16;
            uint32_t off = (uint32_t)rB*144u + (uint32_t)cB*32u;
            #pragma unroll
            for (int q = 0; q < 2; q++) {
                *reinterpret_cast<uint4*>(smem + 36864 + off + q*16) =
                    *reinterpret_cast<const uint4*>(ph + q*8);
                *reinterpret_cast<uint4*>(smem + 46080 + off + q*16) =
                    *reinterpret_cast<const uint4*>(pl + q*8);
            }
        }
        __syncthreads();
        #pragma unroll
        for (int k = 0; k < 4; k++) {
            uint32_t kb = (uint32_t)k * 32u;
            uint32_t ah[4], al[4];
            ldsm_x4(ah, sb + 0     + aRow + kb);
            ldsm_x4(al, sb + 18432 + aRow + kb);
            #pragma unroll
            for (int n = 0; n < 8; n++) {
                uint32_t bf[4];
                ldsm_x4(bf, bAddr + (uint32_t)n*(8u*144u) + kb);
                mma16816(acc[n], ah, bf);
                mma16816(acc[n], ah, bf + 2);
                mma16816(acc[n], al, bf);
            }
        }
    }
    // ---- fused epilogue: transpose, f1/f2, WhT fp16 ----
    __syncthreads();
    float* ts = reinterpret_cast<float*>(smem);          // [64 d][132]
    float* a1s = reinterpret_cast<float*>(smem + 33792);
    float* a2s = reinterpret_cast<float*>(smem + 34048);
    if (t < 64) { a1s[t] = a1[h*DD + t]; a2s[t] = a2[h*DD + t]; }
    int r0 = warp*16 + (lane >> 2);
    int r1 = r0 + 8;
    #pragma unroll
    for (int n = 0; n < 8; n++) {
        int c = n*8 + (lane & 3)*2;
        ts[c*132 + r0]     = acc[n][0];
        ts[(c+1)*132 + r0] = acc[n][1];
        ts[c*132 + r1]     = acc[n][2];
        ts[(c+1)*132 + r1] = acc[n][3];
    }
    __syncthreads();
    if (t < 128) {
        float f1 = 0.f, f2 = 0.f;
        #pragma unroll
        for (int d = 0; d < 64; d++) {
            float wv = ts[d*132 + t];
            f1 += wv * a1s[d];
            f2 += wv * a2s[d];
        }
        int tid = bh*NN + nd0 + t;
        g_F1R[tid] = make_float2(f1, expf(-0.8f*f1));
        g_F2C[tid] = make_float4(f2, expf(f2), expf(0.2f*f2), 0.f);
    }
    #pragma unroll
    for (int q = 0; q < 4; q++) {
        int task = t + q*256;
        int d = task >> 4, nc = task & 15;
        uint32_t hw[4];
        #pragma unroll
        for (int p = 0; p < 4; p++)
            hw[p] = pk_h2(ts[d*132 + nc*8 + 2*p], ts[d*132 + nc*8 + 2*p + 1]);
        size_t off = ((size_t)bh*DD + d)*NN + nd0 + nc*8;
        *reinterpret_cast<uint4*>(g_WhT + off) = *reinterpret_cast<uint4*>(hw);
    }
}

// ---------------- K3: layer-1 attention, plain-fp16 1-product HMMA + cp.async ----------------
// smem: A @0 (128x72 fp16, 18432); B buf0 @18432 (64x72, 9216); buf1 @27648;
// zp @36864 (1KB); f2s @37888 (2KB). Total 39936.
#define K3_SMEM 39936
__global__ __launch_bounds__(256) void k3_attn1_mma() {
    extern __shared__ __align__(16) char smem[];
    char* Ahp = smem;
    float* zp = reinterpret_cast<float*>(smem + 36864);
    float4* f2s = reinterpret_cast<float4*>(smem + 37888);
    uint32_t sb = smem_u32(smem);

    int t = threadIdx.x;
    int warp = t >> 5, lane = t & 31;
    int i0 = blockIdx.x * 128;
    int h = blockIdx.y, b = blockIdx.z;
    int bh = (b<<3) + h;

    int i = t & 127, jh = t >> 7;
    float2 f1r = g_F1R[bh*NN + i0 + i];
    float negf1 = -f1r.x, rmul = f1r.y;
    float zacc = 0.f;
    const __half* bsrc = g_WhT + (size_t)bh*DD*NN;
    const float4* f2g = reinterpret_cast<const float4*>(&g_F2C[bh*NN]);

    float acc[8][4];
    #pragma unroll
    for (int n=0;n<8;n++){ acc[n][0]=0.f; acc[n][1]=0.f; acc[n][2]=0.f; acc[n][3]=0.f; }

    int m0 = warp * 16;
    uint32_t aRow = (uint32_t)(m0 + (lane & 15)) * 144u + ((lane & 16) ? 16u : 0u);
    // paired-n-tile B fragment: lanes 16-31 fetch rows +8 (next n-tile)
    uint32_t bFrag = (uint32_t)(lane & 7) * 144u + ((lane & 16) ? 1152u : 0u)
                   + (uint32_t)(lane & 8) * 2u;

    // B copy role: d = t>>2 (0..63), chunk c = t&3 (16 half = 32B)
    int dB = t >> 2, cB = t & 3;
    const __half* pB = bsrc + (size_t)dB*NN + cB*16;
    uint32_t bStOff = (uint32_t)dB*144u + (uint32_t)cB*32u;

    {
        uint32_t d0 = sb + 18432u + bStOff;
        CP_ASYNC16(d0,      pB);
        CP_ASYNC16(d0 + 16, pB + 8);
        CP_COMMIT();
    }
    if (t < 64) f2s[t] = __ldg(&f2g[t]);
    __syncthreads();

    for (int jt = 0; jt < 32; jt++) {
        int buf = jt & 1;
        if (jt) __syncthreads();
        if (jt < 31) {
            uint32_t dN = sb + 18432u + (uint32_t)(buf^1)*9216u + bStOff;
            const __half* s = pB + (jt+1)*64;
            CP_ASYNC16(dN,      s);
            CP_ASYNC16(dN + 16, s + 8);
            CP_COMMIT();
        }
        // weight phase -> A (plain fp16)
        unsigned bw = g_adjbT[((b<<6) + jt*2 + jh)*NN + i0 + i];
        const float4* f2p = &f2s[(size_t)buf*64 + jh*32];
        #pragma unroll
        for (int oct = 0; oct < 4; oct++) {
            float w[8];
            #pragma unroll
            for (int e = 0; e < 8; e++) {
                float4 fc = f2p[oct*8 + e];
                float w1 = (fc.x > negf1) ? fc.y : rmul*fc.z;
                w[e] = ((bw >> (oct*8 + e)) & 1u) ? w1 : 0.f;
                zacc += w[e];
            }
            uint32_t hw[4];
            #pragma unroll
            for (int p = 0; p < 4; p++)
                hw[p] = pk_h2(w[2*p], w[2*p+1]);
            uint32_t off = (uint32_t)i*144u + (uint32_t)(jh*64 + oct*16);
            *reinterpret_cast<uint4*>(Ahp + off) = *reinterpret_cast<uint4*>(hw);
        }
        if (jt < 31 && t < 64)
            f2s[(size_t)(buf^1)*64 + t] = __ldg(&f2g[(jt+1)*64 + t]);
        if (jt < 31) { CP_WAIT(1); } else { CP_WAIT(0); }
        __syncthreads();
        // ---- MMA(jt): 1 product, paired-n LDSM ----
        uint32_t bBase = sb + 18432u + (uint32_t)buf*9216u + bFrag;
        #pragma unroll
        for (int k = 0; k < 4; k++) {
            uint32_t kb = (uint32_t)k * 32u;
            uint32_t ah[4];
            ldsm_x4(ah, sb + aRow + kb);
            #pragma unroll
            for (int q = 0; q < 4; q++) {
                uint32_t bf[4];
                ldsm_x4(bf, bBase + (uint32_t)q*2304u + kb);
                mma16816h(acc[2*q],   ah, bf);
                mma16816h(acc[2*q+1], ah, bf + 2);
            }
        }
    }
    zp[jh*128 + i] = zacc;
    __syncthreads();
    int r0 = m0 + (lane >> 2);
    int r1 = r0 + 8;
    float z0 = zp[r0] + zp[128 + r0];   if (z0 < 1e-30f) z0 = 1.f;
    float z1 = zp[r1] + zp[128 + r1];   if (z1 < 1e-30f) z1 = 1.f;
    float invz0 = 1.f / z0, invz1 = 1.f / z1;
    size_t base0 = (size_t)(b*NN + i0 + r0)*HD + h*DD + (lane & 3)*2;
    size_t base1 = (size_t)(b*NN + i0 + r1)*HD + h*DD + (lane & 3)*2;
    #pragma unroll
    for (int n = 0; n < 8; n++) {
        float v0 = acc[n][0] * invz0, v1 = acc[n][1] * invz0;
        float v2 = acc[n][2] * invz1, v3 = acc[n][3] * invz1;
        v0 = v0 > 0.f ? v0 : expm1f(v0);
        v1 = v1 > 0.f ? v1 : expm1f(v1);
        v2 = v2 > 0.f ? v2 : expm1f(v2);
        v3 = v3 > 0.f ? v3 : expm1f(v3);
        uint32_t h0, l0, h1, l1;
        split2(v0, v1, h0, l0);
        split2(v2, v3, h1, l1);
        *reinterpret_cast<uint32_t*>(g_h_hi + base0 + n*8) = h0;
        *reinterpret_cast<uint32_t*>(g_h_lo + base0 + n*8) = l0;
        *reinterpret_cast<uint32_t*>(g_h_hi + base1 + n*8) = h1;
        *reinterpret_cast<uint32_t*>(g_h_lo + base1 + n*8) = l1;
    }
}

// ---------------- K4: Wh2 = h @ Wo (bf16 HMMA); fused Wh2T(fp16) + g1/g2 ----------------
__global__ __launch_bounds__(256) void k4_hmma(const float* __restrict__ ao1,
                                               const float* __restrict__ ao2) {
    __shared__ __align__(16) char Ahp[64*144];
    __shared__ __align__(16) char Alp[64*144];
    __shared__ __align__(16) char Bs[2*32*144];   // hi @0, lo @4608
    uint32_t sbA_h = smem_u32(Ahp), sbA_l = smem_u32(Alp);
    uint32_t sbB = smem_u32(Bs);

    int t = threadIdx.x;
    int warp = t >> 5, lane = t & 31;
    int m0 = blockIdx.x * 64;
    int b = m0 >> 11, nd0 = m0 & 2047;
    int mt = warp >> 1, nh = warp & 1;

    float acc[2][4];
    acc[0][0]=0.f; acc[0][1]=0.f; acc[0][2]=0.f; acc[0][3]=0.f;
    acc[1][0]=0.f; acc[1][1]=0.f; acc[1][2]=0.f; acc[1][3]=0.f;

    uint32_t aRow = (uint32_t)(mt*16 + (lane & 15)) * 144u + ((lane & 16) ? 16u : 0u);
    uint32_t bAddr = sbB + ((lane & 16) ? 4608u : 0u)
                   + (uint32_t)(lane & 7) * 144u + (uint32_t)(lane & 8) * 2u;

    int rA = t >> 2, cA = t & 3;
    int rB = t >> 3, cB = t & 7;

    #pragma unroll
    for (int kt = 0; kt < 8; kt++) {
        if (kt) __syncthreads();
        int k0 = kt * 64;
        {
            const __nv_bfloat16* ph = g_h_hi + (size_t)(m0 + rA)*HD + k0 + cA*16;
            const __nv_bfloat16* pl = g_h_lo + (size_t)(m0 + rA)*HD + k0 + cA*16;
            uint32_t off = (uint32_t)rA*144u + (uint32_t)cA*32u;
            #pragma unroll
            for (int q = 0; q < 2; q++) {
                *reinterpret_cast<uint4*>(Ahp + off + q*16) =
                    *reinterpret_cast<const uint4*>(ph + q*8);
                *reinterpret_cast<uint4*>(Alp + off + q*16) =
                    *reinterpret_cast<const uint4*>(pl + q*8);
            }
        }
        {
            const __nv_bfloat16* ph = g_WoT_hi + (size_t)rB*HD + k0 + cB*8;
            const __nv_bfloat16* pl = g_WoT_lo + (size_t)rB*HD + k0 + cB*8;
            uint32_t off = (uint32_t)rB*144u + (uint32_t)cB*16u;
            *reinterpret_cast<uint4*>(Bs + off)         = *reinterpret_cast<const uint4*>(ph);
            *reinterpret_cast<uint4*>(Bs + 4608 + off)  = *reinterpret_cast<const uint4*>(pl);
        }
        __syncthreads();
        #pragma unroll
        for (int k = 0; k < 4; k++) {
            uint32_t kb = (uint32_t)k * 32u;
            uint32_t ah[4], al[4];
            ldsm_x4(ah, sbA_h + aRow + kb);
            ldsm_x4(al, sbA_l + aRow + kb);
            #pragma unroll
            for (int n = 0; n < 2; n++) {
                uint32_t bf[4];
                ldsm_x4(bf, bAddr + (uint32_t)(nh*2 + n)*(8u*144u) + kb);
                mma16816(acc[n], ah, bf);
                mma16816(acc[n], ah, bf + 2);
                mma16816(acc[n], al, bf);
            }
        }
    }
    // ---- fused epilogue: transpose tile, g1/g2, Wh2T fp16 ----
    __syncthreads();
    float* ts2 = reinterpret_cast<float*>(Ahp);          // [32 c][68]
    float* ao1s = reinterpret_cast<float*>(Alp);         // 32
    float* ao2s = reinterpret_cast<float*>(Alp + 128);   // 32
    if (t < 32) { ao1s[t] = ao1[t]; ao2s[t] = ao2[t]; }
    int r0 = mt*16 + (lane >> 2);
    int r1 = r0 + 8;
    #pragma unroll
    for (int n = 0; n < 2; n++) {
        int c = nh*16 + n*8 + (lane & 3)*2;
        ts2[c*68 + r0]     = acc[n][0];
        ts2[(c+1)*68 + r0] = acc[n][1];
        ts2[c*68 + r1]     = acc[n][2];
        ts2[(c+1)*68 + r1] = acc[n][3];
    }
    __syncthreads();
    if (t < 64) {
        float g1 = 0.f, g2 = 0.f;
        #pragma unroll
        for (int c = 0; c < 32; c++) {
            float wv = ts2[c*68 + t];
            g1 += wv * ao1s[c];
            g2 += wv * ao2s[c];
        }
        int tid = b*NN + nd0 + t;
        g_G1R[tid] = make_float2(g1, expf(-0.8f*g1));
        g_G2C[tid] = make_float4(g2, expf(g2), expf(0.2f*g2), 0.f);
    }
    {
        int c = t >> 3, nc = t & 7;
        uint32_t hw[4];
        #pragma unroll
        for (int p = 0; p < 4; p++)
            hw[p] = pk_h2(ts2[c*68 + nc*8 + 2*p], ts2[c*68 + nc*8 + 2*p + 1]);
        size_t off = ((size_t)(b*CC) + c)*NN + nd0 + nc*8;
        *reinterpret_cast<uint4*>(g_Wh2T + off) = *reinterpret_cast<uint4*>(hw);
    }
}

// ---------------- K5: layer-2 attention, plain-fp16 1-product HMMA ----------------
__global__ __launch_bounds__(256) void k5_attn2_mma(float* __restrict__ out) {
    __shared__ __align__(16) char Ahp[64*144];    // w fp16 [64][72]
    __shared__ __align__(16) char Bs[32*144];     // Wh2T fp16 [32][72]
    __shared__ float zp[4][64];
    __shared__ __align__(16) float4 g2s[128];     // staged g2c, 2 bufs of 64
    uint32_t sbA = smem_u32(Ahp);
    uint32_t sbB = smem_u32(Bs);

    int t = threadIdx.x;
    int warp = t >> 5, lane = t & 31;
    int i0 = blockIdx.x * 64;
    int b = blockIdx.y;

    int i = t & 63, jq = t >> 6;
    float2 g1r = g_G1R[b*NN + i0 + i];
    float negg = -g1r.x, rmul = g1r.y;
    float zacc = 0.f;
    const __half* bsrc = g_Wh2T + (size_t)(b*CC)*NN;
    const float4* g2g = reinterpret_cast<const float4*>(&g_G2C[b*NN]);

    int mt = warp >> 1, nh = warp & 1;
    float acc[2][4];
    acc[0][0]=0.f; acc[0][1]=0.f; acc[0][2]=0.f; acc[0][3]=0.f;
    acc[1][0]=0.f; acc[1][1]=0.f; acc[1][2]=0.f; acc[1][3]=0.f;

    uint32_t aRow = (uint32_t)(mt*16 + (lane & 15)) * 144u + ((lane & 16) ? 16u : 0u);
    // paired-n-tile B fragment: this warp covers n-tiles 2nh, 2nh+1 in one x4
    uint32_t bAddr = sbB + (uint32_t)(lane & 7) * 144u + ((lane & 16) ? 1152u : 0u)
                   + (uint32_t)(lane & 8) * 2u + (uint32_t)nh * 2304u;

    if (t < 64) g2s[t] = __ldg(&g2g[t]);
    __syncthreads();

    for (int jt = 0; jt < 32; jt++) {
        int buf = jt & 1;
        if (jt) __syncthreads();
        int j0 = jt * 64;
        unsigned bwf = g_adjbT[((b<<6) + jt*2 + (jq>>1))*NN + i0 + i];
        unsigned bw = (bwf >> ((jq & 1)*16)) & 0xFFFFu;
        const float4* g2p = &g2s[(size_t)buf*64 + jq*16];
        float w[16];
        #pragma unroll
        for (int e = 0; e < 16; e++) {
            float4 fc = g2p[e];
            float w1 = (fc.x > negg) ? fc.y : rmul*fc.z;
            w[e] = ((bw >> e) & 1u) ? w1 : 0.f;
            zacc += w[e];
        }
        uint32_t hw[8];
        #pragma unroll
        for (int p = 0; p < 8; p++)
            hw[p] = pk_h2(w[2*p], w[2*p+1]);
        uint32_t off = (uint32_t)i*144u + (uint32_t)jq*32u;
        *reinterpret_cast<uint4*>(Ahp + off)      = *reinterpret_cast<uint4*>(&hw[0]);
        *reinterpret_cast<uint4*>(Ahp + off + 16) = *reinterpret_cast<uint4*>(&hw[4]);
        {
            int c = t >> 3, ch = t & 7;
            uint4 v = *reinterpret_cast<const uint4*>(bsrc + (size_t)c*NN + j0 + ch*8);
            *reinterpret_cast<uint4*>(Bs + (uint32_t)c*144u + (uint32_t)ch*16u) = v;
        }
        if (jt < 31 && t < 64)
            g2s[(size_t)(buf^1)*64 + t] = __ldg(&g2g[(jt+1)*64 + t]);
        __syncthreads();
        #pragma unroll
        for (int k = 0; k < 4; k++) {
            uint32_t kb = (uint32_t)k * 32u;
            uint32_t ah[4];
            ldsm_x4(ah, sbA + aRow + kb);
            uint32_t bf[4];
            ldsm_x4(bf, bAddr + kb);
            mma16816h(acc[0], ah, bf);
            mma16816h(acc[1], ah, bf + 2);
        }
    }
    zp[jq][i] = zacc;
    __syncthreads();
    int r0 = mt*16 + (lane >> 2);
    int r1 = r0 + 8;
    float z0 = zp[0][r0] + zp[1][r0] + zp[2][r0] + zp[3][r0];
    float z1 = zp[0][r1] + zp[1][r1] + zp[2][r1] + zp[3][r1];
    if (z0 < 1e-30f) z0 = 1.f;
    if (z1 < 1e-30f) z1 = 1.f;
    float invz0 = 1.f / z0, invz1 = 1.f / z1;
    #pragma unroll
    for (int n = 0; n < 2; n++) {
        int c0 = nh*16 + n*8 + (lane & 3)*2;
        float2 o0 = make_float2(acc[n][0]*invz0, acc[n][1]*invz0);
        float2 o1 = make_float2(acc[n][2]*invz1, acc[n][3]*invz1);
        *reinterpret_cast<float2*>(&out[(size_t)(b*NN + i0 + r0)*CC + c0]) = o0;
        *reinterpret_cast<float2*>(&out[(size_t)(b*NN + i0 + r1)*CC + c0]) = o1;
    }
}

extern "C" void kernel_launch(void* const* d_in, const int* in_sizes, int n_in,
                              void* d_out, int out_size) {
    const float* x   = (const float*)d_in[0];
    const int*   adj = (const int*)  d_in[1];
    const float* W   = (const float*)d_in[2];
    const float* a1  = (const float*)d_in[3];
    const float* a2  = (const float*)d_in[4];
    const float* Wo  = (const float*)d_in[5];
    const float* ao1 = (const float*)d_in[6];
    const float* ao2 = (const float*)d_in[7];
    float* out = (float*)d_out;

    cudaFuncSetAttribute(k3_attn1_mma,
                         cudaFuncAttributeMaxDynamicSharedMemorySize, K3_SMEM);
    cudaFuncSetAttribute(k1_hmma,
                         cudaFuncAttributeMaxDynamicSharedMemorySize, K1_SMEM);

    kws_split<<<64, 256>>>(W);                        // W -> WcatT bf16 hi/lo
    k4w_split<<<16, 256>>>(Wo);                       // Wo -> WoT bf16 hi/lo
    k0_mask<<<1024, 256>>>(adj);                      // adj -> transposed bitmask
    k1_hmma<<<dim3(8, 64), 256, K1_SMEM>>>(x, a1, a2);// Wh + WhT fp16 + f1/f2
    k3_attn1_mma<<<dim3(16, 8, 4), 256, K3_SMEM>>>(); // layer-1 attn (fp16 1-prod)
    k4_hmma<<<128, 256>>>(ao1, ao2);                  // Wh2T fp16 + g1/g2
    k5_attn2_mma<<<dim3(32, 4), 256>>>(out);          // layer-2 attn (fp16 1-prod)
}

// round 14
// speedup vs baseline: 2.6868x; 1.0674x over previous
#include <cuda_runtime.h>
#include <cuda_bf16.h>
#include <cuda_fp16.h>
#include <math.h>
#include <stdint.h>

// GAT forward, B=4 N=2048 F=128 H=8 D=64 C=32.
// Softmax trick: exp(lrelu(f1_i+f2_j))/exp(f1_i) = (f1_i+f2_j>0) ? exp(f2_j)
//   : exp(-0.8 f1_i)*exp(0.2 f2_j); exp(f1_i) cancels in softmax.
// R14: half2 weight phase (packed fp16 triplets per j-pair, hgt2_mask + LOP3
// select) and softmax-z computed by a ones-column MMA (register-constant B
// fragment) -> no zacc adds, no zp smem, no reduction.

#define BB 4
#define NN 2048
#define FF 128
#define DD 64
#define HH 8
#define CC 32
#define HD (HH*DD)

__device__ __align__(16) float2 g_F1R[BB*HH*NN];     // (f1, exp(-0.8 f1))
__device__ __align__(16) uint4  g_F2H[BB*HH*NN/2];   // per j-pair {f2,e,e02} fp16x2
__device__ __align__(16) float2 g_G1R[BB*NN];
__device__ __align__(16) uint4  g_G2H[BB*NN/2];
__device__ unsigned g_adjbT[BB*64*NN];               // bitmask, TRANSPOSED [b][word][row]
__device__ __align__(16) __half g_WhT[BB*HH*DD*NN];      // WhT fp16 [bh][d][j]
__device__ __align__(16) __half g_Wh2T[BB*CC*NN];        // Wh2T fp16 [b][c][j]
__device__ __align__(16) __nv_bfloat16 g_WT_hi[HH*DD*FF];  // WcatT [c][f] bf16 hi
__device__ __align__(16) __nv_bfloat16 g_WT_lo[HH*DD*FF];
__device__ __align__(16) __nv_bfloat16 g_h_hi[BB*NN*HD];   // h bf16 hi [bn][hd]
__device__ __align__(16) __nv_bfloat16 g_h_lo[BB*NN*HD];
__device__ __align__(16) __nv_bfloat16 g_WoT_hi[CC*HD];    // WoT [c][k] bf16 hi
__device__ __align__(16) __nv_bfloat16 g_WoT_lo[CC*HD];

__device__ __forceinline__ uint32_t smem_u32(const void* p) {
    uint32_t a;
    asm("{ .reg .u64 tmp; cvta.to.shared.u64 tmp, %1; cvt.u32.u64 %0, tmp; }"
        : "=r"(a) : "l"(p));
    return a;
}
__device__ __forceinline__ void ldsm_x4(uint32_t* r, uint32_t addr) {
    asm volatile("ldmatrix.sync.aligned.m8n8.x4.shared.b16 {%0,%1,%2,%3}, [%4];"
        : "=r"(r[0]), "=r"(r[1]), "=r"(r[2]), "=r"(r[3]) : "r"(addr));
}
// bf16 mma (k1/k4)
__device__ __forceinline__ void mma16816(float* c, const uint32_t* a, const uint32_t* b) {
    asm volatile(
        "mma.sync.aligned.m16n8k16.row.col.f32.bf16.bf16.f32 "
        "{%0,%1,%2,%3}, {%4,%5,%6,%7}, {%8,%9}, {%0,%1,%2,%3};"
        : "+f"(c[0]), "+f"(c[1]), "+f"(c[2]), "+f"(c[3])
        : "r"(a[0]), "r"(a[1]), "r"(a[2]), "r"(a[3]), "r"(b[0]), "r"(b[1]));
}
// fp16 mma (k3/k5)
__device__ __forceinline__ void mma16816h(float* c, const uint32_t* a, const uint32_t* b) {
    asm volatile(
        "mma.sync.aligned.m16n8k16.row.col.f32.f16.f16.f32 "
        "{%0,%1,%2,%3}, {%4,%5,%6,%7}, {%8,%9}, {%0,%1,%2,%3};"
        : "+f"(c[0]), "+f"(c[1]), "+f"(c[2]), "+f"(c[3])
        : "r"(a[0]), "r"(a[1]), "r"(a[2]), "r"(a[3]), "r"(b[0]), "r"(b[1]));
}
#define CP_ASYNC16(dst, src) \
    asm volatile("cp.async.cg.shared.global [%0], [%1], 16;" :: "r"(dst), "l"(src))
#define CP_COMMIT() asm volatile("cp.async.commit_group;" ::: "memory")
#define CP_WAIT(n)  asm volatile("cp.async.wait_group %0;" :: "n"(n) : "memory")

// split float pair -> bf16 hi/lo packed words
__device__ __forceinline__ void split2(float a, float b, uint32_t& hi, uint32_t& lo) {
    __nv_bfloat162 hp = __floats2bfloat162_rn(a, b);
    float2 hf = __bfloat1622float2(hp);
    __nv_bfloat162 lp = __floats2bfloat162_rn(a - hf.x, b - hf.y);
    hi = *reinterpret_cast<uint32_t*>(&hp);
    lo = *reinterpret_cast<uint32_t*>(&lp);
}
__device__ __forceinline__ uint32_t pk_h2(float a, float b) {
    __half2 hp = __floats2half2_rn(a, b);
    return *reinterpret_cast<uint32_t*>(&hp);
}
__device__ __forceinline__ uint32_t hgt2m(uint32_t a, uint32_t b) {
    return __hgt2_mask(*reinterpret_cast<__half2*>(&a),
                       *reinterpret_cast<__half2*>(&b));
}
__device__ __forceinline__ uint32_t hmul2u(uint32_t a, uint32_t b) {
    __half2 r = __hmul2(*reinterpret_cast<__half2*>(&a),
                        *reinterpret_cast<__half2*>(&b));
    return *reinterpret_cast<uint32_t*>(&r);
}
__device__ __forceinline__ uint32_t f2h2(float v) {
    __half2 r = __float2half2_rn(v);
    return *reinterpret_cast<uint32_t*>(&r);
}

// ---------------- KWS: W[h][f][d] -> WcatT[c][f] bf16 hi/lo ----------------
__global__ __launch_bounds__(256) void kws_split(const float* __restrict__ W) {
    int idx = blockIdx.x*256 + threadIdx.x;      // 0..16383 = c*32 + kg
    int c = idx >> 5, kg = idx & 31;
    int h = c >> 6, d = c & 63;
    float v[4];
    #pragma unroll
    for (int q = 0; q < 4; q++)
        v[q] = W[h*(FF*DD) + (kg*4 + q)*DD + d];
    uint32_t h0, l0, h1, l1;
    split2(v[0], v[1], h0, l0);
    split2(v[2], v[3], h1, l1);
    *reinterpret_cast<uint2*>(g_WT_hi + (size_t)c*FF + kg*4) = make_uint2(h0, h1);
    *reinterpret_cast<uint2*>(g_WT_lo + (size_t)c*FF + kg*4) = make_uint2(l0, l1);
}

// ---------------- K4W: Wo[k][c] -> WoT[c][k] bf16 hi/lo ----------------
__global__ __launch_bounds__(256) void k4w_split(const float* __restrict__ Wo) {
    int idx = blockIdx.x*256 + threadIdx.x;      // 0..4095 = c*128 + kg
    int c = idx >> 7, kg = idx & 127;
    float v[4];
    #pragma unroll
    for (int q = 0; q < 4; q++)
        v[q] = Wo[(kg*4 + q)*CC + c];
    uint32_t h0, l0, h1, l1;
    split2(v[0], v[1], h0, l0);
    split2(v[2], v[3], h1, l1);
    *reinterpret_cast<uint2*>(g_WoT_hi + (size_t)c*HD + kg*4) = make_uint2(h0, h1);
    *reinterpret_cast<uint2*>(g_WoT_lo + (size_t)c*HD + kg*4) = make_uint2(l0, l1);
}

// ---------------- K0: adjacency -> transposed bitmask (int4 + shfl-or) ----------------
__global__ __launch_bounds__(256) void k0_mask(const int* __restrict__ adj) {
    int gw = (blockIdx.x * 256 + threadIdx.x) >> 5;  // 0..8191 = b*2048+row
    int lane = threadIdx.x & 31;
    int b = gw >> 11, row = gw & 2047;
    const int4* ar4 = reinterpret_cast<const int4*>(adj + (size_t)gw * NN);
    int lg = lane & 7, wsel = lane >> 3;
    #pragma unroll 4
    for (int it = 0; it < 16; it++) {
        int4 v = ar4[it*32 + lane];
        unsigned nib = (v.x > 0 ? 1u : 0u) | (v.y > 0 ? 2u : 0u)
                     | (v.z > 0 ? 4u : 0u) | (v.w > 0 ? 8u : 0u);
        unsigned part = nib << (lg * 4);
        part |= __shfl_xor_sync(0xffffffffu, part, 1);
        part |= __shfl_xor_sync(0xffffffffu, part, 2);
        part |= __shfl_xor_sync(0xffffffffu, part, 4);
        if (lg == 0)
            g_adjbT[((b<<6) + it*4 + wsel)*NN + row] = part;
    }
}

// ---------------- K1: Wh = x @ Wcat (bf16 HMMA); fused WhT(fp16) + f1/f2 ----------------
#define K1_SMEM 55296
__global__ __launch_bounds__(256) void k1_hmma(const float* __restrict__ x,
                                               const float* __restrict__ a1,
                                               const float* __restrict__ a2) {
    extern __shared__ __align__(16) char smem[];
    uint32_t sb = smem_u32(smem);
    int t = threadIdx.x;
    int warp = t >> 5, lane = t & 31;
    int h = blockIdx.x;
    int m0 = blockIdx.y * 128;
    int b = m0 >> 11, nd0 = m0 & 2047;
    int bh = b*8 + h;

    float acc[8][4];
    #pragma unroll
    for (int n=0;n<8;n++){ acc[n][0]=0.f; acc[n][1]=0.f; acc[n][2]=0.f; acc[n][3]=0.f; }

    uint32_t aRow = (uint32_t)(warp*16 + (lane & 15)) * 144u + ((lane & 16) ? 16u : 0u);
    uint32_t bAddr = sb + 36864u + ((lane & 16) ? 9216u : 0u)
                   + (uint32_t)(lane & 7) * 144u + (uint32_t)(lane & 8) * 2u;

    int rA = t >> 1, hA = t & 1;
    int rB = t >> 2, cB = t & 3;

    #pragma unroll
    for (int kt = 0; kt < 2; kt++) {
        if (kt) __syncthreads();
        int k0 = kt * 64;
        {
            const float4* px = reinterpret_cast<const float4*>(
                x + (size_t)(m0 + rA)*FF + k0 + hA*32);
            uint32_t off = (uint32_t)rA*144u + (uint32_t)hA*64u;
            #pragma unroll
            for (int q = 0; q < 4; q++) {
                float4 v0 = px[q*2], v1 = px[q*2+1];
                uint32_t hw[4], lw[4];
                split2(v0.x, v0.y, hw[0], lw[0]);
                split2(v0.z, v0.w, hw[1], lw[1]);
                split2(v1.x, v1.y, hw[2], lw[2]);
                split2(v1.z, v1.w, hw[3], lw[3]);
                *reinterpret_cast<uint4*>(smem + off + q*16) =
                    *reinterpret_cast<uint4*>(hw);
                *reinterpret_cast<uint4*>(smem + 18432 + off + q*16) =
                    *reinterpret_cast<uint4*>(lw);
            }
        }
        {
            const __nv_bfloat16* ph = g_WT_hi + (size_t)(h*64 + rB)*FF + k0 + cB*16;
            const __nv_bfloat16* pl = g_WT_lo + (size_t)(h*64 + rB)*FF + k0 + cB*16;
            uint32_t off = (uint32_t)rB*144u + (uint32_t)cB*32u;
            #pragma unroll
            for (int q = 0; q < 2; q++) {
                *reinterpret_cast<uint4*>(smem + 36864 + off + q*16) =
                    *reinterpret_cast<const uint4*>(ph + q*8);
                *reinterpret_cast<uint4*>(smem + 46080 + off + q*16) =
                    *reinterpret_cast<const uint4*>(pl + q*8);
            }
        }
        __syncthreads();
        #pragma unroll
        for (int k = 0; k < 4; k++) {
            uint32_t kb = (uint32_t)k * 32u;
            uint32_t ah[4], al[4];
            ldsm_x4(ah, sb + 0     + aRow + kb);
            ldsm_x4(al, sb + 18432 + aRow + kb);
            #pragma unroll
            for (int n = 0; n < 8; n++) {
                uint32_t bf[4];
                ldsm_x4(bf, bAddr + (uint32_t)n*(8u*144u) + kb);
                mma16816(acc[n], ah, bf);
                mma16816(acc[n], ah, bf + 2);
                mma16816(acc[n], al, bf);
            }
        }
    }
    // ---- fused epilogue: transpose, f1/f2 (+fp16 triplets), WhT fp16 ----
    __syncthreads();
    float* ts = reinterpret_cast<float*>(smem);          // [64 d][132]
    float* a1s = reinterpret_cast<float*>(smem + 33792);
    float* a2s = reinterpret_cast<float*>(smem + 34048);
    float* fse = reinterpret_cast<float*>(smem + 34304); // 3 x 128
    if (t < 64) { a1s[t] = a1[h*DD + t]; a2s[t] = a2[h*DD + t]; }
    int r0 = warp*16 + (lane >> 2);
    int r1 = r0 + 8;
    #pragma unroll
    for (int n = 0; n < 8; n++) {
        int c = n*8 + (lane & 3)*2;
        ts[c*132 + r0]     = acc[n][0];
        ts[(c+1)*132 + r0] = acc[n][1];
        ts[c*132 + r1]     = acc[n][2];
        ts[(c+1)*132 + r1] = acc[n][3];
    }
    __syncthreads();
    if (t < 128) {
        float f1 = 0.f, f2 = 0.f;
        #pragma unroll
        for (int d = 0; d < 64; d++) {
            float wv = ts[d*132 + t];
            f1 += wv * a1s[d];
            f2 += wv * a2s[d];
        }
        int tid = bh*NN + nd0 + t;
        g_F1R[tid] = make_float2(f1, expf(-0.8f*f1));
        fse[t]       = f2;
        fse[128 + t] = expf(f2);
        fse[256 + t] = expf(0.2f*f2);
    }
    #pragma unroll
    for (int q = 0; q < 4; q++) {
        int task = t + q*256;
        int d = task >> 4, nc = task & 15;
        uint32_t hw[4];
        #pragma unroll
        for (int p = 0; p < 4; p++)
            hw[p] = pk_h2(ts[d*132 + nc*8 + 2*p], ts[d*132 + nc*8 + 2*p + 1]);
        size_t off = ((size_t)bh*DD + d)*NN + nd0 + nc*8;
        *reinterpret_cast<uint4*>(g_WhT + off) = *reinterpret_cast<uint4*>(hw);
    }
    __syncthreads();
    if (t < 64) {
        uint4 o;
        o.x = pk_h2(fse[2*t],       fse[2*t + 1]);
        o.y = pk_h2(fse[128 + 2*t], fse[128 + 2*t + 1]);
        o.z = pk_h2(fse[256 + 2*t], fse[256 + 2*t + 1]);
        o.w = 0;
        g_F2H[(size_t)bh*(NN/2) + nd0/2 + t] = o;
    }
}

// ---------------- K3: layer-1 attention, fp16 HMMA, h2 weights, z via ones-MMA ----------------
// smem: A @0 (128x72 fp16, 18432); B buf0 @18432 (9216); buf1 @27648;
// f2s @36864 (uint4[2][32] = 1KB). Total 37888.
#define K3_SMEM 37888
__global__ __launch_bounds__(256) void k3_attn1_mma() {
    extern __shared__ __align__(16) char smem[];
    char* Ahp = smem;
    uint4* f2s = reinterpret_cast<uint4*>(smem + 36864);
    uint32_t sb = smem_u32(smem);

    int t = threadIdx.x;
    int warp = t >> 5, lane = t & 31;
    int i0 = blockIdx.x * 128;
    int h = blockIdx.y, b = blockIdx.z;
    int bh = (b<<3) + h;

    int i = t & 127, jh = t >> 7;
    float2 f1r = g_F1R[bh*NN + i0 + i];
    uint32_t negf1h = f2h2(-f1r.x);
    uint32_t rmulh  = f2h2(f1r.y);
    const __half* bsrc = g_WhT + (size_t)bh*DD*NN;
    const uint4* f2g = g_F2H + (size_t)bh*(NN/2);

    float acc[8][4];
    #pragma unroll
    for (int n=0;n<8;n++){ acc[n][0]=0.f; acc[n][1]=0.f; acc[n][2]=0.f; acc[n][3]=0.f; }
    float accz[4] = {0.f, 0.f, 0.f, 0.f};
    uint32_t bzf[2];
    bzf[0] = (lane < 4) ? 0x3C003C00u : 0u;   // ones column (n=0 of extra tile)
    bzf[1] = bzf[0];

    int m0 = warp * 16;
    uint32_t aRow = (uint32_t)(m0 + (lane & 15)) * 144u + ((lane & 16) ? 16u : 0u);
    uint32_t bFrag = (uint32_t)(lane & 7) * 144u + ((lane & 16) ? 1152u : 0u)
                   + (uint32_t)(lane & 8) * 2u;

    int dB = t >> 2, cB = t & 3;
    const __half* pB = bsrc + (size_t)dB*NN + cB*16;
    uint32_t bStOff = (uint32_t)dB*144u + (uint32_t)cB*32u;

    {
        uint32_t d0 = sb + 18432u + bStOff;
        CP_ASYNC16(d0,      pB);
        CP_ASYNC16(d0 + 16, pB + 8);
        CP_COMMIT();
    }
    if (t < 32) f2s[t] = __ldg(&f2g[t]);
    __syncthreads();

    for (int jt = 0; jt < 32; jt++) {
        int buf = jt & 1;
        if (jt) __syncthreads();
        if (jt < 31) {
            uint32_t dN = sb + 18432u + (uint32_t)(buf^1)*9216u + bStOff;
            const __half* s = pB + (jt+1)*64;
            CP_ASYNC16(dN,      s);
            CP_ASYNC16(dN + 16, s + 8);
            CP_COMMIT();
        }
        // ---- h2 weight phase: 16 j-pairs per thread ----
        unsigned bw = g_adjbT[((b<<6) + jt*2 + jh)*NN + i0 + i];
        const uint4* fp = &f2s[buf*32 + jh*16];
        #pragma unroll
        for (int pq = 0; pq < 4; pq++) {
            uint32_t wv[4];
            #pragma unroll
            for (int p = 0; p < 4; p++) {
                uint4 tr = fp[pq*4 + p];
                uint32_t mgt = hgt2m(tr.x, negf1h);
                uint32_t alt = hmul2u(rmulh, tr.z);
                uint32_t sel = (tr.y & mgt) | (alt & ~mgt);
                uint32_t bits = (bw >> ((pq*4 + p)*2)) & 3u;
                uint32_t am = ((bits & 1u) ? 0xFFFFu : 0u)
                            | ((bits & 2u) ? 0xFFFF0000u : 0u);
                wv[p] = sel & am;
            }
            uint32_t off = (uint32_t)i*144u + (uint32_t)(jh*64 + pq*16);
            *reinterpret_cast<uint4*>(Ahp + off) =
                make_uint4(wv[0], wv[1], wv[2], wv[3]);
        }
        if (jt < 31 && t < 32)
            f2s[(buf^1)*32 + t] = __ldg(&f2g[(jt+1)*32 + t]);
        if (jt < 31) { CP_WAIT(1); } else { CP_WAIT(0); }
        __syncthreads();
        // ---- MMA(jt): 1 product + ones-column z ----
        uint32_t bBase = sb + 18432u + (uint32_t)buf*9216u + bFrag;
        #pragma unroll
        for (int k = 0; k < 4; k++) {
            uint32_t kb = (uint32_t)k * 32u;
            uint32_t ah[4];
            ldsm_x4(ah, sb + aRow + kb);
            mma16816h(accz, ah, bzf);
            #pragma unroll
            for (int q = 0; q < 4; q++) {
                uint32_t bf[4];
                ldsm_x4(bf, bBase + (uint32_t)q*2304u + kb);
                mma16816h(acc[2*q],   ah, bf);
                mma16816h(acc[2*q+1], ah, bf + 2);
            }
        }
    }
    // ---- epilogue: z via shfl (col 0 lives in lanes with lane%4==0) ----
    float z0 = __shfl_sync(0xffffffffu, accz[0], lane & 28);
    float z1 = __shfl_sync(0xffffffffu, accz[2], lane & 28);
    if (z0 < 1e-30f) z0 = 1.f;
    if (z1 < 1e-30f) z1 = 1.f;
    float invz0 = 1.f / z0, invz1 = 1.f / z1;
    int r0 = m0 + (lane >> 2);
    int r1 = r0 + 8;
    size_t base0 = (size_t)(b*NN + i0 + r0)*HD + h*DD + (lane & 3)*2;
    size_t base1 = (size_t)(b*NN + i0 + r1)*HD + h*DD + (lane & 3)*2;
    #pragma unroll
    for (int n = 0; n < 8; n++) {
        float v0 = acc[n][0] * invz0, v1 = acc[n][1] * invz0;
        float v2 = acc[n][2] * invz1, v3 = acc[n][3] * invz1;
        v0 = v0 > 0.f ? v0 : expm1f(v0);
        v1 = v1 > 0.f ? v1 : expm1f(v1);
        v2 = v2 > 0.f ? v2 : expm1f(v2);
        v3 = v3 > 0.f ? v3 : expm1f(v3);
        uint32_t h0, l0, h1, l1;
        split2(v0, v1, h0, l0);
        split2(v2, v3, h1, l1);
        *reinterpret_cast<uint32_t*>(g_h_hi + base0 + n*8) = h0;
        *reinterpret_cast<uint32_t*>(g_h_lo + base0 + n*8) = l0;
        *reinterpret_cast<uint32_t*>(g_h_hi + base1 + n*8) = h1;
        *reinterpret_cast<uint32_t*>(g_h_lo + base1 + n*8) = l1;
    }
}

// ---------------- K4: Wh2 = h @ Wo (bf16 HMMA); fused Wh2T(fp16) + g1/g2 ----------------
__global__ __launch_bounds__(256) void k4_hmma(const float* __restrict__ ao1,
                                               const float* __restrict__ ao2) {
    __shared__ __align__(16) char Ahp[64*144];
    __shared__ __align__(16) char Alp[64*144];
    __shared__ __align__(16) char Bs[2*32*144];   // hi @0, lo @4608
    uint32_t sbA_h = smem_u32(Ahp), sbA_l = smem_u32(Alp);
    uint32_t sbB = smem_u32(Bs);

    int t = threadIdx.x;
    int warp = t >> 5, lane = t & 31;
    int m0 = blockIdx.x * 64;
    int b = m0 >> 11, nd0 = m0 & 2047;
    int mt = warp >> 1, nh = warp & 1;

    float acc[2][4];
    acc[0][0]=0.f; acc[0][1]=0.f; acc[0][2]=0.f; acc[0][3]=0.f;
    acc[1][0]=0.f; acc[1][1]=0.f; acc[1][2]=0.f; acc[1][3]=0.f;

    uint32_t aRow = (uint32_t)(mt*16 + (lane & 15)) * 144u + ((lane & 16) ? 16u : 0u);
    uint32_t bAddr = sbB + ((lane & 16) ? 4608u : 0u)
                   + (uint32_t)(lane & 7) * 144u + (uint32_t)(lane & 8) * 2u;

    int rA = t >> 2, cA = t & 3;
    int rB = t >> 3, cB = t & 7;

    #pragma unroll
    for (int kt = 0; kt < 8; kt++) {
        if (kt) __syncthreads();
        int k0 = kt * 64;
        {
            const __nv_bfloat16* ph = g_h_hi + (size_t)(m0 + rA)*HD + k0 + cA*16;
            const __nv_bfloat16* pl = g_h_lo + (size_t)(m0 + rA)*HD + k0 + cA*16;
            uint32_t off = (uint32_t)rA*144u + (uint32_t)cA*32u;
            #pragma unroll
            for (int q = 0; q < 2; q++) {
                *reinterpret_cast<uint4*>(Ahp + off + q*16) =
                    *reinterpret_cast<const uint4*>(ph + q*8);
                *reinterpret_cast<uint4*>(Alp + off + q*16) =
                    *reinterpret_cast<const uint4*>(pl + q*8);
            }
        }
        {
            const __nv_bfloat16* ph = g_WoT_hi + (size_t)rB*HD + k0 + cB*8;
            const __nv_bfloat16* pl = g_WoT_lo + (size_t)rB*HD + k0 + cB*8;
            uint32_t off = (uint32_t)rB*144u + (uint32_t)cB*16u;
            *reinterpret_cast<uint4*>(Bs + off)         = *reinterpret_cast<const uint4*>(ph);
            *reinterpret_cast<uint4*>(Bs + 4608 + off)  = *reinterpret_cast<const uint4*>(pl);
        }
        __syncthreads();
        #pragma unroll
        for (int k = 0; k < 4; k++) {
            uint32_t kb = (uint32_t)k * 32u;
            uint32_t ah[4], al[4];
            ldsm_x4(ah, sbA_h + aRow + kb);
            ldsm_x4(al, sbA_l + aRow + kb);
            #pragma unroll
            for (int n = 0; n < 2; n++) {
                uint32_t bf[4];
                ldsm_x4(bf, bAddr + (uint32_t)(nh*2 + n)*(8u*144u) + kb);
                mma16816(acc[n], ah, bf);
                mma16816(acc[n], ah, bf + 2);
                mma16816(acc[n], al, bf);
            }
        }
    }
    // ---- fused epilogue: transpose tile, g1/g2 (+fp16 triplets), Wh2T fp16 ----
    __syncthreads();
    float* ts2 = reinterpret_cast<float*>(Ahp);          // [32 c][68]
    float* ao1s = reinterpret_cast<float*>(Alp);         // 32
    float* ao2s = reinterpret_cast<float*>(Alp + 128);   // 32
    float* fse2 = reinterpret_cast<float*>(Alp + 256);   // 3 x 64
    if (t < 32) { ao1s[t] = ao1[t]; ao2s[t] = ao2[t]; }
    int r0 = mt*16 + (lane >> 2);
    int r1 = r0 + 8;
    #pragma unroll
    for (int n = 0; n < 2; n++) {
        int c = nh*16 + n*8 + (lane & 3)*2;
        ts2[c*68 + r0]     = acc[n][0];
        ts2[(c+1)*68 + r0] = acc[n][1];
        ts2[c*68 + r1]     = acc[n][2];
        ts2[(c+1)*68 + r1] = acc[n][3];
    }
    __syncthreads();
    if (t < 64) {
        float g1 = 0.f, g2 = 0.f;
        #pragma unroll
        for (int c = 0; c < 32; c++) {
            float wv = ts2[c*68 + t];
            g1 += wv * ao1s[c];
            g2 += wv * ao2s[c];
        }
        int tid = b*NN + nd0 + t;
        g_G1R[tid] = make_float2(g1, expf(-0.8f*g1));
        fse2[t]       = g2;
        fse2[64 + t]  = expf(g2);
        fse2[128 + t] = expf(0.2f*g2);
    }
    {
        int c = t >> 3, nc = t & 7;
        uint32_t hw[4];
        #pragma unroll
        for (int p = 0; p < 4; p++)
            hw[p] = pk_h2(ts2[c*68 + nc*8 + 2*p], ts2[c*68 + nc*8 + 2*p + 1]);
        size_t off = ((size_t)(b*CC) + c)*NN + nd0 + nc*8;
        *reinterpret_cast<uint4*>(g_Wh2T + off) = *reinterpret_cast<uint4*>(hw);
    }
    __syncthreads();
    if (t < 32) {
        uint4 o;
        o.x = pk_h2(fse2[2*t],       fse2[2*t + 1]);
        o.y = pk_h2(fse2[64 + 2*t],  fse2[64 + 2*t + 1]);
        o.z = pk_h2(fse2[128 + 2*t], fse2[128 + 2*t + 1]);
        o.w = 0;
        g_G2H[(size_t)b*(NN/2) + nd0/2 + t] = o;
    }
}

// ---------------- K5: layer-2 attention, fp16 HMMA, h2 weights, z via ones-MMA ----------------
__global__ __launch_bounds__(256) void k5_attn2_mma(float* __restrict__ out) {
    __shared__ __align__(16) char Ahp[64*144];    // w fp16 [64][72]
    __shared__ __align__(16) char Bs[32*144];     // Wh2T fp16 [32][72]
    __shared__ __align__(16) uint4 g2s[64];       // staged triplets, 2 bufs of 32
    uint32_t sbA = smem_u32(Ahp);
    uint32_t sbB = smem_u32(Bs);

    int t = threadIdx.x;
    int warp = t >> 5, lane = t & 31;
    int i0 = blockIdx.x * 64;
    int b = blockIdx.y;

    int i = t & 63, jq = t >> 6;
    float2 g1r = g_G1R[b*NN + i0 + i];
    uint32_t negg = f2h2(-g1r.x);
    uint32_t rmulh = f2h2(g1r.y);
    const __half* bsrc = g_Wh2T + (size_t)(b*CC)*NN;
    const uint4* g2g = g_G2H + (size_t)b*(NN/2);

    int mt = warp >> 1, nh = warp & 1;
    float acc[2][4];
    acc[0][0]=0.f; acc[0][1]=0.f; acc[0][2]=0.f; acc[0][3]=0.f;
    acc[1][0]=0.f; acc[1][1]=0.f; acc[1][2]=0.f; acc[1][3]=0.f;
    float accz[4] = {0.f, 0.f, 0.f, 0.f};
    uint32_t bzf[2];
    bzf[0] = (lane < 4) ? 0x3C003C00u : 0u;
    bzf[1] = bzf[0];

    uint32_t aRow = (uint32_t)(mt*16 + (lane & 15)) * 144u + ((lane & 16) ? 16u : 0u);
    uint32_t bAddr = sbB + (uint32_t)(lane & 7) * 144u + ((lane & 16) ? 1152u : 0u)
                   + (uint32_t)(lane & 8) * 2u + (uint32_t)nh * 2304u;

    if (t < 32) g2s[t] = __ldg(&g2g[t]);
    __syncthreads();

    for (int jt = 0; jt < 32; jt++) {
        int buf = jt & 1;
        if (jt) __syncthreads();
        int j0 = jt * 64;
        unsigned bwf = g_adjbT[((b<<6) + jt*2 + (jq>>1))*NN + i0 + i];
        unsigned bw = (bwf >> ((jq & 1)*16)) & 0xFFFFu;
        const uint4* gp = &g2s[buf*32 + jq*8];
        #pragma unroll
        for (int pq = 0; pq < 2; pq++) {
            uint32_t wv[4];
            #pragma unroll
            for (int p = 0; p < 4; p++) {
                uint4 tr = gp[pq*4 + p];
                uint32_t mgt = hgt2m(tr.x, negg);
                uint32_t alt = hmul2u(rmulh, tr.z);
                uint32_t sel = (tr.y & mgt) | (alt & ~mgt);
                uint32_t bits = (bw >> ((pq*4 + p)*2)) & 3u;
                uint32_t am = ((bits & 1u) ? 0xFFFFu : 0u)
                            | ((bits & 2u) ? 0xFFFF0000u : 0u);
                wv[p] = sel & am;
            }
            uint32_t off = (uint32_t)i*144u + (uint32_t)(jq*32 + pq*16);
            *reinterpret_cast<uint4*>(Ahp + off) =
                make_uint4(wv[0], wv[1], wv[2], wv[3]);
        }
        {
            int c = t >> 3, ch = t & 7;
            uint4 v = *reinterpret_cast<const uint4*>(bsrc + (size_t)c*NN + j0 + ch*8);
            *reinterpret_cast<uint4*>(Bs + (uint32_t)c*144u + (uint32_t)ch*16u) = v;
        }
        if (jt < 31 && t < 32)
            g2s[(buf^1)*32 + t] = __ldg(&g2g[(jt+1)*32 + t]);
        __syncthreads();
        #pragma unroll
        for (int k = 0; k < 4; k++) {
            uint32_t kb = (uint32_t)k * 32u;
            uint32_t ah[4];
            ldsm_x4(ah, sbA + aRow + kb);
            mma16816h(accz, ah, bzf);
            uint32_t bf[4];
            ldsm_x4(bf, bAddr + kb);
            mma16816h(acc[0], ah, bf);
            mma16816h(acc[1], ah, bf + 2);
        }
    }
    float z0 = __shfl_sync(0xffffffffu, accz[0], lane & 28);
    float z1 = __shfl_sync(0xffffffffu, accz[2], lane & 28);
    if (z0 < 1e-30f) z0 = 1.f;
    if (z1 < 1e-30f) z1 = 1.f;
    float invz0 = 1.f / z0, invz1 = 1.f / z1;
    int r0 = mt*16 + (lane >> 2);
    int r1 = r0 + 8;
    #pragma unroll
    for (int n = 0; n < 2; n++) {
        int c0 = nh*16 + n*8 + (lane & 3)*2;
        float2 o0 = make_float2(acc[n][0]*invz0, acc[n][1]*invz0);
        float2 o1 = make_float2(acc[n][2]*invz1, acc[n][3]*invz1);
        *reinterpret_cast<float2*>(&out[(size_t)(b*NN + i0 + r0)*CC + c0]) = o0;
        *reinterpret_cast<float2*>(&out[(size_t)(b*NN + i0 + r1)*CC + c0]) = o1;
    }
}

extern "C" void kernel_launch(void* const* d_in, const int* in_sizes, int n_in,
                              void* d_out, int out_size) {
    const float* x   = (const float*)d_in[0];
    const int*   adj = (const int*)  d_in[1];
    const float* W   = (const float*)d_in[2];
    const float* a1  = (const float*)d_in[3];
    const float* a2  = (const float*)d_in[4];
    const float* Wo  = (const float*)d_in[5];
    const float* ao1 = (const float*)d_in[6];
    const float* ao2 = (const float*)d_in[7];
    float* out = (float*)d_out;

    cudaFuncSetAttribute(k3_attn1_mma,
                         cudaFuncAttributeMaxDynamicSharedMemorySize, K3_SMEM);
    cudaFuncSetAttribute(k1_hmma,
                         cudaFuncAttributeMaxDynamicSharedMemorySize, K1_SMEM);

    kws_split<<<64, 256>>>(W);                        // W -> WcatT bf16 hi/lo
    k4w_split<<<16, 256>>>(Wo);                       // Wo -> WoT bf16 hi/lo
    k0_mask<<<1024, 256>>>(adj);                      // adj -> transposed bitmask
    k1_hmma<<<dim3(8, 64), 256, K1_SMEM>>>(x, a1, a2);// Wh + WhT fp16 + f-triplets
    k3_attn1_mma<<<dim3(16, 8, 4), 256, K3_SMEM>>>(); // layer-1 attn (h2 + z-MMA)
    k4_hmma<<<128, 256>>>(ao1, ao2);                  // Wh2T fp16 + g-triplets
    k5_attn2_mma<<<dim3(32, 4), 256>>>(out);          // layer-2 attn (h2 + z-MMA)
}